// round 1
// baseline (speedup 1.0000x reference)
#include <cuda_runtime.h>
#include <cuda_bf16.h>
#include <cstddef>

// Problem constants
// B=2, S=2048, E=1024, H=16, D=64, GROUPS=16, GROUP_SIZE=64
// tokens M = B*S = 4096

#define BM 128
#define BN 128
#define BK 16

// ---------------- device scratch (no allocations allowed) ----------------
__device__ float g_w[4][1024 * 1024];          // dequantized q/k/v/o weights [O,I]
__device__ float g_q[2 * 16 * 2048 * 64];      // [B,H,S,D]
__device__ float g_k[2 * 16 * 2048 * 64];
__device__ float g_v[2 * 16 * 2048 * 64];
__device__ float g_ao[2 * 2048 * 1024];        // attn output in [B,S,E]

// ---------------- dequant ----------------
__global__ __launch_bounds__(256) void dequant_kernel(
    const int* __restrict__ qw, const float* __restrict__ sc,
    const float* __restrict__ zr, float* __restrict__ w)
{
    int idx = blockIdx.x * 256 + threadIdx.x;     // 0 .. 1M-1
    int o = idx >> 10;
    int i = idx & 1023;
    int g = i >> 6;
    float s = sc[o * 16 + g];
    float z = zr[o * 16 + g];
    w[idx] = ((float)qw[idx] - z) * s;
}

// ---------------- projection GEMM: Y[s,o] = sum_e X[s,e] W[o,e] + bias[o] ----------------
// M=4096, N=1024, K=1024.  head_split: write [B,H,S,D] layout, else [B,S,E].
__global__ __launch_bounds__(256) void proj_kernel(
    const float* __restrict__ X, const float* __restrict__ W,
    const float* __restrict__ bias, float* __restrict__ Y, int head_split)
{
    const int K = 1024;
    __shared__ float As[BK][BM + 4];
    __shared__ float Bs[BK][BN + 4];
    int bn0 = blockIdx.x * BN;
    int bm0 = blockIdx.y * BM;
    int tid = threadIdx.x;
    int tx = tid & 15, ty = tid >> 4;

    float acc[8][8];
#pragma unroll
    for (int i = 0; i < 8; i++)
#pragma unroll
        for (int j = 0; j < 8; j++) acc[i][j] = 0.f;

    for (int k0 = 0; k0 < K; k0 += BK) {
#pragma unroll
        for (int l = 0; l < 2; l++) {
            int v = tid + l * 256;
            int r = v >> 2;
            int c4 = (v & 3) * 4;
            float4 a = *(const float4*)&X[(size_t)(bm0 + r) * K + k0 + c4];
            As[c4 + 0][r] = a.x; As[c4 + 1][r] = a.y;
            As[c4 + 2][r] = a.z; As[c4 + 3][r] = a.w;
            float4 b = *(const float4*)&W[(size_t)(bn0 + r) * K + k0 + c4];
            Bs[c4 + 0][r] = b.x; Bs[c4 + 1][r] = b.y;
            Bs[c4 + 2][r] = b.z; Bs[c4 + 3][r] = b.w;
        }
        __syncthreads();
#pragma unroll
        for (int kk = 0; kk < BK; kk++) {
            float ar[8], br[8];
#pragma unroll
            for (int i = 0; i < 8; i++) ar[i] = As[kk][ty * 8 + i];
#pragma unroll
            for (int j = 0; j < 8; j++) br[j] = Bs[kk][tx * 8 + j];
#pragma unroll
            for (int i = 0; i < 8; i++)
#pragma unroll
                for (int j = 0; j < 8; j++)
                    acc[i][j] = fmaf(ar[i], br[j], acc[i][j]);
        }
        __syncthreads();
    }

#pragma unroll
    for (int i = 0; i < 8; i++) {
        int s = bm0 + ty * 8 + i;
#pragma unroll
        for (int j = 0; j < 8; j++) {
            int o = bn0 + tx * 8 + j;
            float val = acc[i][j] + bias[o];
            if (head_split) {
                int b = s >> 11, si = s & 2047;
                int h = o >> 6, d = o & 63;
                Y[((size_t)(b * 16 + h) * 2048 + si) * 64 + d] = val;
            } else {
                Y[(size_t)s * 1024 + o] = val;
            }
        }
    }
}

// ---------------- scores: S[bh, s, t] = (1/8) * sum_d Q[bh,s,d] K[bh,t,d] ----------------
__global__ __launch_bounds__(256) void scores_kernel(
    const float* __restrict__ Q, const float* __restrict__ Kb, float* __restrict__ S)
{
    const int K = 64;
    int bh = blockIdx.z;
    const float* Qp = Q + (size_t)bh * 2048 * 64;
    const float* Kp = Kb + (size_t)bh * 2048 * 64;
    float* Sp = S + (size_t)bh * 2048 * 2048;

    __shared__ float As[BK][BM + 4];
    __shared__ float Bs[BK][BN + 4];
    int bn0 = blockIdx.x * BN;
    int bm0 = blockIdx.y * BM;
    int tid = threadIdx.x;
    int tx = tid & 15, ty = tid >> 4;

    float acc[8][8];
#pragma unroll
    for (int i = 0; i < 8; i++)
#pragma unroll
        for (int j = 0; j < 8; j++) acc[i][j] = 0.f;

    for (int k0 = 0; k0 < K; k0 += BK) {
#pragma unroll
        for (int l = 0; l < 2; l++) {
            int v = tid + l * 256;
            int r = v >> 2;
            int c4 = (v & 3) * 4;
            float4 a = *(const float4*)&Qp[(size_t)(bm0 + r) * K + k0 + c4];
            As[c4 + 0][r] = a.x; As[c4 + 1][r] = a.y;
            As[c4 + 2][r] = a.z; As[c4 + 3][r] = a.w;
            float4 b = *(const float4*)&Kp[(size_t)(bn0 + r) * K + k0 + c4];
            Bs[c4 + 0][r] = b.x; Bs[c4 + 1][r] = b.y;
            Bs[c4 + 2][r] = b.z; Bs[c4 + 3][r] = b.w;
        }
        __syncthreads();
#pragma unroll
        for (int kk = 0; kk < BK; kk++) {
            float ar[8], br[8];
#pragma unroll
            for (int i = 0; i < 8; i++) ar[i] = As[kk][ty * 8 + i];
#pragma unroll
            for (int j = 0; j < 8; j++) br[j] = Bs[kk][tx * 8 + j];
#pragma unroll
            for (int i = 0; i < 8; i++)
#pragma unroll
                for (int j = 0; j < 8; j++)
                    acc[i][j] = fmaf(ar[i], br[j], acc[i][j]);
        }
        __syncthreads();
    }

#pragma unroll
    for (int i = 0; i < 8; i++) {
        int s = bm0 + ty * 8 + i;
#pragma unroll
        for (int j = 0; j < 8; j++) {
            int t = bn0 + tx * 8 + j;
            Sp[(size_t)s * 2048 + t] = acc[i][j] * 0.125f;
        }
    }
}

// ---------------- softmax: in place over last dim (2048) ----------------
__global__ __launch_bounds__(256) void softmax_kernel(float* __restrict__ S)
{
    size_t row = blockIdx.x;
    float* p = S + row * 2048;
    int t = threadIdx.x;
    float v[8];
#pragma unroll
    for (int i = 0; i < 8; i++) v[i] = p[t + i * 256];
    float m = v[0];
#pragma unroll
    for (int i = 1; i < 8; i++) m = fmaxf(m, v[i]);
#pragma unroll
    for (int o = 16; o > 0; o >>= 1) m = fmaxf(m, __shfl_xor_sync(0xffffffffu, m, o));
    __shared__ float sred[8];
    __shared__ float sbc;
    if ((t & 31) == 0) sred[t >> 5] = m;
    __syncthreads();
    if (t == 0) {
        float x = sred[0];
#pragma unroll
        for (int i = 1; i < 8; i++) x = fmaxf(x, sred[i]);
        sbc = x;
    }
    __syncthreads();
    m = sbc;
    float sum = 0.f;
#pragma unroll
    for (int i = 0; i < 8; i++) { v[i] = __expf(v[i] - m); sum += v[i]; }
#pragma unroll
    for (int o = 16; o > 0; o >>= 1) sum += __shfl_xor_sync(0xffffffffu, sum, o);
    __syncthreads();  // everyone has read sbc before reuse
    if ((t & 31) == 0) sred[t >> 5] = sum;
    __syncthreads();
    if (t == 0) {
        float x = 0.f;
#pragma unroll
        for (int i = 0; i < 8; i++) x += sred[i];
        sbc = 1.0f / x;
    }
    __syncthreads();
    float inv = sbc;
#pragma unroll
    for (int i = 0; i < 8; i++) p[t + i * 256] = v[i] * inv;
}

// ---------------- PV: Y[b,s, h*64+d] = sum_t P[bh,s,t] V[bh,t,d] ----------------
__global__ __launch_bounds__(256) void pv_kernel(
    const float* __restrict__ P, const float* __restrict__ V, float* __restrict__ Y)
{
    int bh = blockIdx.z;
    int b = bh >> 4, h = bh & 15;
    const float* Pp = P + (size_t)bh * 2048 * 2048;
    const float* Vp = V + (size_t)bh * 2048 * 64;

    __shared__ float As[BK][BM + 4];
    __shared__ float Bs[BK][68];
    int bm0 = blockIdx.y * BM;
    int tid = threadIdx.x;
    int tx = tid & 15, ty = tid >> 4;

    float acc[8][4];
#pragma unroll
    for (int i = 0; i < 8; i++)
#pragma unroll
        for (int j = 0; j < 4; j++) acc[i][j] = 0.f;

    for (int k0 = 0; k0 < 2048; k0 += BK) {
#pragma unroll
        for (int l = 0; l < 2; l++) {
            int v = tid + l * 256;
            int r = v >> 2;
            int c4 = (v & 3) * 4;
            float4 a = *(const float4*)&Pp[(size_t)(bm0 + r) * 2048 + k0 + c4];
            As[c4 + 0][r] = a.x; As[c4 + 1][r] = a.y;
            As[c4 + 2][r] = a.z; As[c4 + 3][r] = a.w;
        }
        {
            int r = tid >> 4;          // 0..15 (k within tile)
            int c4 = (tid & 15) * 4;   // 0..60
            float4 bv = *(const float4*)&Vp[(size_t)(k0 + r) * 64 + c4];
            Bs[r][c4 + 0] = bv.x; Bs[r][c4 + 1] = bv.y;
            Bs[r][c4 + 2] = bv.z; Bs[r][c4 + 3] = bv.w;
        }
        __syncthreads();
#pragma unroll
        for (int kk = 0; kk < BK; kk++) {
            float ar[8], br[4];
#pragma unroll
            for (int i = 0; i < 8; i++) ar[i] = As[kk][ty * 8 + i];
#pragma unroll
            for (int j = 0; j < 4; j++) br[j] = Bs[kk][tx * 4 + j];
#pragma unroll
            for (int i = 0; i < 8; i++)
#pragma unroll
                for (int j = 0; j < 4; j++)
                    acc[i][j] = fmaf(ar[i], br[j], acc[i][j]);
        }
        __syncthreads();
    }

#pragma unroll
    for (int i = 0; i < 8; i++) {
        int s = bm0 + ty * 8 + i;
#pragma unroll
        for (int j = 0; j < 4; j++) {
            int d = tx * 4 + j;
            Y[((size_t)(b * 2048 + s)) * 1024 + h * 64 + d] = acc[i][j];
        }
    }
}

// ---------------- launch ----------------
extern "C" void kernel_launch(void* const* d_in, const int* in_sizes, int n_in,
                              void* d_out, int out_size)
{
    const float* x = (const float*)d_in[0];
    const int* qw[4];
    const float *sc[4], *zr[4], *bs[4];
    for (int p = 0; p < 4; p++) {
        qw[p] = (const int*)d_in[1 + 4 * p];
        sc[p] = (const float*)d_in[2 + 4 * p];
        zr[p] = (const float*)d_in[3 + 4 * p];
        bs[p] = (const float*)d_in[4 + 4 * p];
    }

    float* wbase; cudaGetSymbolAddress((void**)&wbase, g_w);
    float* q;     cudaGetSymbolAddress((void**)&q, g_q);
    float* k;     cudaGetSymbolAddress((void**)&k, g_k);
    float* v;     cudaGetSymbolAddress((void**)&v, g_v);
    float* ao;    cudaGetSymbolAddress((void**)&ao, g_ao);

    float* out = (float*)d_out;                 // [B,S,E] = 4,194,304 floats
    float* attn = out + (size_t)4194304;        // [B,H,S,S] = 134,217,728 floats

    for (int p = 0; p < 4; p++)
        dequant_kernel<<<4096, 256>>>(qw[p], sc[p], zr[p], wbase + (size_t)p * 1024 * 1024);

    // QKV projections -> [B,H,S,D]
    proj_kernel<<<dim3(8, 32), 256>>>(x, wbase + 0 * 1048576, bs[0], q, 1);
    proj_kernel<<<dim3(8, 32), 256>>>(x, wbase + 1 * 1048576, bs[1], k, 1);
    proj_kernel<<<dim3(8, 32), 256>>>(x, wbase + 2 * 1048576, bs[2], v, 1);

    // raw scores into the attn_weights region of d_out
    scores_kernel<<<dim3(16, 16, 32), 256>>>(q, k, attn);

    // in-place softmax over rows of 2048
    softmax_kernel<<<65536, 256>>>(attn);

    // PV -> attn output [B,S,E]
    pv_kernel<<<dim3(1, 16, 32), 256>>>(attn, v, ao);

    // output projection -> d_out[0 : 4M]
    proj_kernel<<<dim3(8, 32), 256>>>(ao, wbase + 3 * 1048576, bs[3], out, 0);
}

// round 4
// speedup vs baseline: 1.7107x; 1.7107x over previous
#include <cuda_runtime.h>
#include <cstdint>
#include <cstddef>

#define DEV __device__ __forceinline__

#define S_LEN 2048
#define EMB   1024
#define PAD   20          // float2 stride per SMEM row (16 + 4 pad) -> conflict-free lds.64

// ---------------- scratch ----------------
__device__ float g_w[4][1024 * 1024];     // dequantized weights [O,I] fp32
__device__ float g_q[32 * 2048 * 64];     // [bh][s][d]
__device__ float g_k[32 * 2048 * 64];
__device__ float g_vt[32 * 64 * 2048];    // [bh][d][s]  (V transposed)
__device__ float g_ao[4096 * 1024];       // attn out [token][e]

DEV uint32_t f2u(float f) { return __float_as_uint(f); }

DEV void mma_tf32(float* c, const uint32_t* a, const uint32_t* b) {
    asm volatile(
        "mma.sync.aligned.m16n8k8.row.col.f32.tf32.tf32.f32 "
        "{%0,%1,%2,%3}, {%4,%5,%6,%7}, {%8,%9}, {%0,%1,%2,%3};"
        : "+f"(c[0]), "+f"(c[1]), "+f"(c[2]), "+f"(c[3])
        : "r"(a[0]), "r"(a[1]), "r"(a[2]), "r"(a[3]), "r"(b[0]), "r"(b[1]));
}

// split fp32 -> (tf32 hi, tf32 lo) stored interleaved
DEV void split_store(float2* s, float v) {
    uint32_t hb; asm("cvt.rna.tf32.f32 %0, %1;" : "=r"(hb) : "f"(v));
    float hf = __uint_as_float(hb);
    float lo = v - hf;
    uint32_t lb; asm("cvt.rna.tf32.f32 %0, %1;" : "=r"(lb) : "f"(lo));
    s->x = hf; s->y = __uint_as_float(lb);
}

// ---------------- generic 3xTF32 GEMM mainloop ----------------
// C[BM,BN] += A[BM,K] * B[BN,K]^T, both K-major fp32.  256 threads, WM x WN warps.
// acc layout: acc[(mi*NT+ni)*4 + cj]
template<int BM, int BN, int WM, int WN, int MT, int NT>
DEV void gemm_main(const float* __restrict__ A, size_t lda,
                   const float* __restrict__ B, size_t ldb,
                   int K, char* smem, float* acc)
{
    const int tid = threadIdx.x;
    const int lane = tid & 31, wid = tid >> 5;
    const int g = lane >> 2, tq = lane & 3;
    const int wm0 = (wid / WN) * (BM / WM);
    const int wn0 = (wid % WN) * (BN / WN);

    float2* As = (float2*)smem;                                   // [2][BM][PAD]
    float2* Bs = (float2*)(smem + 2 * BM * PAD * sizeof(float2)); // [2][BN][PAD]

    constexpr int ARE = BM / 64;   // float4 gmem regs per thread
    constexpr int BRE = BN / 64;
    float4 ra[ARE], rb[BRE];

    auto load_regs = [&](int c) {
        int k0 = c * 16;
#pragma unroll
        for (int i = 0; i < ARE; i++) {
            int idx = tid + i * 256; int r = idx >> 2; int c4 = (idx & 3) * 4;
            ra[i] = *(const float4*)(A + (size_t)r * lda + k0 + c4);
        }
#pragma unroll
        for (int i = 0; i < BRE; i++) {
            int idx = tid + i * 256; int r = idx >> 2; int c4 = (idx & 3) * 4;
            rb[i] = *(const float4*)(B + (size_t)r * ldb + k0 + c4);
        }
    };
    auto store_smem = [&](int buf) {
#pragma unroll
        for (int i = 0; i < ARE; i++) {
            int idx = tid + i * 256; int r = idx >> 2; int c4 = (idx & 3) * 4;
            float2* base = As + buf * BM * PAD + r * PAD + c4;
            split_store(base + 0, ra[i].x); split_store(base + 1, ra[i].y);
            split_store(base + 2, ra[i].z); split_store(base + 3, ra[i].w);
        }
#pragma unroll
        for (int i = 0; i < BRE; i++) {
            int idx = tid + i * 256; int r = idx >> 2; int c4 = (idx & 3) * 4;
            float2* base = Bs + buf * BN * PAD + r * PAD + c4;
            split_store(base + 0, rb[i].x); split_store(base + 1, rb[i].y);
            split_store(base + 2, rb[i].z); split_store(base + 3, rb[i].w);
        }
    };
    auto compute = [&](int buf) {
        const float2* Ab = As + buf * BM * PAD;
        const float2* Bb = Bs + buf * BN * PAD;
#pragma unroll
        for (int ks = 0; ks < 2; ks++) {
            int kb = ks * 8;
            uint32_t ah[MT][4], al[MT][4], bhg[NT][2], blg[NT][2];
#pragma unroll
            for (int mi = 0; mi < MT; mi++) {
                int r0 = wm0 + mi * 16 + g;
                float2 v0 = Ab[r0 * PAD + kb + tq];
                float2 v1 = Ab[(r0 + 8) * PAD + kb + tq];
                float2 v2 = Ab[r0 * PAD + kb + tq + 4];
                float2 v3 = Ab[(r0 + 8) * PAD + kb + tq + 4];
                ah[mi][0] = f2u(v0.x); al[mi][0] = f2u(v0.y);
                ah[mi][1] = f2u(v1.x); al[mi][1] = f2u(v1.y);
                ah[mi][2] = f2u(v2.x); al[mi][2] = f2u(v2.y);
                ah[mi][3] = f2u(v3.x); al[mi][3] = f2u(v3.y);
            }
#pragma unroll
            for (int ni = 0; ni < NT; ni++) {
                int n0 = wn0 + ni * 8 + g;
                float2 w0 = Bb[n0 * PAD + kb + tq];
                float2 w1 = Bb[n0 * PAD + kb + tq + 4];
                bhg[ni][0] = f2u(w0.x); blg[ni][0] = f2u(w0.y);
                bhg[ni][1] = f2u(w1.x); blg[ni][1] = f2u(w1.y);
            }
#pragma unroll
            for (int mi = 0; mi < MT; mi++)
#pragma unroll
                for (int ni = 0; ni < NT; ni++) {
                    float* c = acc + (mi * NT + ni) * 4;
                    mma_tf32(c, ah[mi], bhg[ni]);
                    mma_tf32(c, ah[mi], blg[ni]);
                    mma_tf32(c, al[mi], bhg[ni]);
                }
        }
    };

    int nc = K >> 4;
    load_regs(0);
    store_smem(0);
    __syncthreads();
    for (int c = 0; c < nc; c++) {
        int buf = c & 1;
        if (c + 1 < nc) load_regs(c + 1);     // gmem latency hidden behind compute
        compute(buf);
        __syncthreads();
        if (c + 1 < nc) { store_smem(buf ^ 1); __syncthreads(); }
    }
}

// epilogue iteration: calls fn(row, col, val) for each accumulator element
template<int BM, int BN, int WM, int WN, int MT, int NT, typename F>
DEV void epilogue(const float* acc, F fn)
{
    int lane = threadIdx.x & 31, wid = threadIdx.x >> 5;
    int g = lane >> 2, tq = lane & 3;
    int wm0 = (wid / WN) * (BM / WM);
    int wn0 = (wid % WN) * (BN / WN);
#pragma unroll
    for (int mi = 0; mi < MT; mi++)
#pragma unroll
        for (int ni = 0; ni < NT; ni++)
#pragma unroll
            for (int cj = 0; cj < 4; cj++) {
                int row = wm0 + mi * 16 + g + ((cj >= 2) ? 8 : 0);
                int col = wn0 + ni * 8 + 2 * tq + (cj & 1);
                fn(row, col, acc[(mi * NT + ni) * 4 + cj]);
            }
}

// ---------------- dequant ----------------
__global__ __launch_bounds__(256) void dequant_kernel(
    const int* __restrict__ qw, const float* __restrict__ sc,
    const float* __restrict__ zr, float* __restrict__ w)
{
    int idx = blockIdx.x * 256 + threadIdx.x;
    int o = idx >> 10, i = idx & 1023, grp = i >> 6;
    w[idx] = ((float)qw[idx] - zr[o * 16 + grp]) * sc[o * 16 + grp];
}

// ---------------- QKV projection ----------------
#define QKV_SMEM (2 * (128 + 128) * PAD * 8)
__global__ __launch_bounds__(256) void proj_qkv_kernel(
    const float* __restrict__ x, const float* __restrict__ bq,
    const float* __restrict__ bk, const float* __restrict__ bv)
{
    extern __shared__ char smem[];
    int mode = blockIdx.z;
    int n0 = blockIdx.x * 128, m0 = blockIdx.y * 128;
    const float* B = g_w[mode];
    const float* bias = mode == 0 ? bq : (mode == 1 ? bk : bv);

    float acc[64];
#pragma unroll
    for (int i = 0; i < 64; i++) acc[i] = 0.f;

    gemm_main<128, 128, 2, 4, 4, 4>(x + (size_t)m0 * EMB, EMB,
                                    B + (size_t)n0 * EMB, EMB, EMB, smem, acc);

    if (mode < 2) {
        float* dst = mode == 0 ? g_q : g_k;
        epilogue<128, 128, 2, 4, 4, 4>(acc, [&](int row, int col, float val) {
            int token = m0 + row, o = n0 + col;
            int b = token >> 11, si = token & 2047;
            int h = o >> 6, d = o & 63;
            dst[((size_t)(b * 16 + h) * S_LEN + si) * 64 + d] = val + bias[o];
        });
    } else {
        // transpose through smem so g_vt stores are coalesced
        __syncthreads();
        float* T = (float*)smem;   // [128][132]
        epilogue<128, 128, 2, 4, 4, 4>(acc, [&](int row, int col, float val) {
            T[col * 132 + row] = val + bias[n0 + col];
        });
        __syncthreads();
        for (int i = threadIdx.x; i < 128 * 128; i += 256) {
            int cl = i >> 7, rw = i & 127;
            int o = n0 + cl; int h = o >> 6, d = o & 63;
            int token = m0 + rw; int b = token >> 11, si = token & 2047;
            g_vt[((size_t)(b * 16 + h) * 64 + d) * S_LEN + si] = T[cl * 132 + rw];
        }
    }
}

// ---------------- scores ----------------
__global__ __launch_bounds__(256) void scores_kernel(float* __restrict__ attn)
{
    extern __shared__ char smem[];
    int bh = blockIdx.z;
    int n0 = blockIdx.x * 128, m0 = blockIdx.y * 128;
    size_t base = (size_t)bh * S_LEN * 64;

    float acc[64];
#pragma unroll
    for (int i = 0; i < 64; i++) acc[i] = 0.f;

    gemm_main<128, 128, 2, 4, 4, 4>(g_q + base + (size_t)m0 * 64, 64,
                                    g_k + base + (size_t)n0 * 64, 64, 64, smem, acc);

    float* out = attn + (size_t)bh * S_LEN * S_LEN;
    epilogue<128, 128, 2, 4, 4, 4>(acc, [&](int row, int col, float val) {
        out[(size_t)(m0 + row) * S_LEN + n0 + col] = val * 0.125f;
    });
}

// ---------------- softmax (in place) ----------------
__global__ __launch_bounds__(256) void softmax_kernel(float* __restrict__ S)
{
    size_t row = blockIdx.x;
    float* p = S + row * S_LEN;
    int t = threadIdx.x;
    float v[8];
#pragma unroll
    for (int i = 0; i < 8; i++) v[i] = p[t + i * 256];
    float m = v[0];
#pragma unroll
    for (int i = 1; i < 8; i++) m = fmaxf(m, v[i]);
#pragma unroll
    for (int o = 16; o > 0; o >>= 1) m = fmaxf(m, __shfl_xor_sync(0xffffffffu, m, o));
    __shared__ float sred[8]; __shared__ float sbc;
    if ((t & 31) == 0) sred[t >> 5] = m;
    __syncthreads();
    if (t == 0) {
        float x = sred[0];
#pragma unroll
        for (int i = 1; i < 8; i++) x = fmaxf(x, sred[i]);
        sbc = x;
    }
    __syncthreads();
    m = sbc;
    float sum = 0.f;
#pragma unroll
    for (int i = 0; i < 8; i++) { v[i] = __expf(v[i] - m); sum += v[i]; }
#pragma unroll
    for (int o = 16; o > 0; o >>= 1) sum += __shfl_xor_sync(0xffffffffu, sum, o);
    __syncthreads();
    if ((t & 31) == 0) sred[t >> 5] = sum;
    __syncthreads();
    if (t == 0) {
        float x = 0.f;
#pragma unroll
        for (int i = 0; i < 8; i++) x += sred[i];
        sbc = 1.0f / x;
    }
    __syncthreads();
    float inv = sbc;
#pragma unroll
    for (int i = 0; i < 8; i++) p[t + i * 256] = v[i] * inv;
}

// ---------------- PV ----------------
#define PV_SMEM (2 * (128 + 64) * PAD * 8)
__global__ __launch_bounds__(256) void pv_kernel(const float* __restrict__ attn)
{
    extern __shared__ char smem[];
    int bh = blockIdx.z;
    int m0 = blockIdx.y * 128;

    float acc[32];
#pragma unroll
    for (int i = 0; i < 32; i++) acc[i] = 0.f;

    gemm_main<128, 64, 4, 2, 2, 4>(attn + (size_t)bh * S_LEN * S_LEN + (size_t)m0 * S_LEN, S_LEN,
                                   g_vt + (size_t)bh * 64 * S_LEN, S_LEN, S_LEN, smem, acc);

    int b = bh >> 4, h = bh & 15;
    epilogue<128, 64, 4, 2, 2, 4>(acc, [&](int row, int col, float val) {
        size_t token = (size_t)b * S_LEN + m0 + row;
        g_ao[token * EMB + h * 64 + col] = val;
    });
}

// ---------------- O projection ----------------
__global__ __launch_bounds__(256) void oproj_kernel(
    const float* __restrict__ bias, float* __restrict__ out)
{
    extern __shared__ char smem[];
    int n0 = blockIdx.x * 128, m0 = blockIdx.y * 128;

    float acc[64];
#pragma unroll
    for (int i = 0; i < 64; i++) acc[i] = 0.f;

    gemm_main<128, 128, 2, 4, 4, 4>(g_ao + (size_t)m0 * EMB, EMB,
                                    g_w[3] + (size_t)n0 * EMB, EMB, EMB, smem, acc);

    epilogue<128, 128, 2, 4, 4, 4>(acc, [&](int row, int col, float val) {
        int token = m0 + row, o = n0 + col;
        out[(size_t)token * EMB + o] = val + bias[o];
    });
}

// ---------------- launch ----------------
extern "C" void kernel_launch(void* const* d_in, const int* in_sizes, int n_in,
                              void* d_out, int out_size)
{
    const float* x = (const float*)d_in[0];
    const int* qw[4];
    const float *sc[4], *zr[4], *bs[4];
    for (int p = 0; p < 4; p++) {
        qw[p] = (const int*)d_in[1 + 4 * p];
        sc[p] = (const float*)d_in[2 + 4 * p];
        zr[p] = (const float*)d_in[3 + 4 * p];
        bs[p] = (const float*)d_in[4 + 4 * p];
    }
    float* out = (float*)d_out;                 // [B,S,E]
    float* attn = out + (size_t)4194304;        // [B,H,S,S]

    float* wbase; cudaGetSymbolAddress((void**)&wbase, g_w);

    cudaFuncSetAttribute(proj_qkv_kernel, cudaFuncAttributeMaxDynamicSharedMemorySize, QKV_SMEM);
    cudaFuncSetAttribute(scores_kernel,   cudaFuncAttributeMaxDynamicSharedMemorySize, QKV_SMEM);
    cudaFuncSetAttribute(pv_kernel,       cudaFuncAttributeMaxDynamicSharedMemorySize, PV_SMEM);
    cudaFuncSetAttribute(oproj_kernel,    cudaFuncAttributeMaxDynamicSharedMemorySize, QKV_SMEM);

    for (int p = 0; p < 4; p++)
        dequant_kernel<<<4096, 256>>>(qw[p], sc[p], zr[p], wbase + (size_t)p * 1024 * 1024);

    proj_qkv_kernel<<<dim3(8, 32, 3), 256, QKV_SMEM>>>(x, bs[0], bs[1], bs[2]);
    scores_kernel<<<dim3(16, 16, 32), 256, QKV_SMEM>>>(attn);
    softmax_kernel<<<65536, 256>>>(attn);
    pv_kernel<<<dim3(1, 16, 32), 256, PV_SMEM>>>(attn);
    oproj_kernel<<<dim3(8, 32), 256, QKV_SMEM>>>(bs[3], out);
}

// round 5
// speedup vs baseline: 2.3067x; 1.3484x over previous
#include <cuda_runtime.h>
#include <cuda_bf16.h>
#include <cstdint>
#include <cstddef>

#define DEV __device__ __forceinline__

#define S_LEN 2048
#define EMB   1024
#define PAD   20          // float2 per SMEM row (16 data + 4 pad)
#define PADB  10          // uint2 per SMEM row for bf16 path (8 data + 2 pad)

// ---------------- scratch ----------------
__device__ float g_w[4][1024 * 1024];     // dequantized weights [O,I] fp32
__device__ float g_q[32 * 2048 * 64];     // [bh][s][d]
__device__ float g_k[32 * 2048 * 64];
__device__ float g_vt[32 * 64 * 2048];    // [bh][d][s]  (V transposed)
__device__ float g_ao[4096 * 1024];       // attn out [token][e]

DEV uint32_t f2u(float f) { return __float_as_uint(f); }

DEV void mma_tf32(float* c, const uint32_t* a, const uint32_t* b) {
    asm volatile(
        "mma.sync.aligned.m16n8k8.row.col.f32.tf32.tf32.f32 "
        "{%0,%1,%2,%3}, {%4,%5,%6,%7}, {%8,%9}, {%0,%1,%2,%3};"
        : "+f"(c[0]), "+f"(c[1]), "+f"(c[2]), "+f"(c[3])
        : "r"(a[0]), "r"(a[1]), "r"(a[2]), "r"(a[3]), "r"(b[0]), "r"(b[1]));
}

DEV void mma_bf16(float* c, const uint32_t* a, const uint32_t* b) {
    asm volatile(
        "mma.sync.aligned.m16n8k16.row.col.f32.bf16.bf16.f32 "
        "{%0,%1,%2,%3}, {%4,%5,%6,%7}, {%8,%9}, {%0,%1,%2,%3};"
        : "+f"(c[0]), "+f"(c[1]), "+f"(c[2]), "+f"(c[3])
        : "r"(a[0]), "r"(a[1]), "r"(a[2]), "r"(a[3]), "r"(b[0]), "r"(b[1]));
}

// split fp32 -> (tf32 hi, tf32 lo) stored interleaved
DEV void split_store(float2* s, float v) {
    uint32_t hb; asm("cvt.rna.tf32.f32 %0, %1;" : "=r"(hb) : "f"(v));
    float hf = __uint_as_float(hb);
    float lo = v - hf;
    uint32_t lb; asm("cvt.rna.tf32.f32 %0, %1;" : "=r"(lb) : "f"(lo));
    s->x = hf; s->y = __uint_as_float(lb);
}

// pack two floats as bf16x2: low half = a (element k), high half = b (element k+1)
DEV uint32_t pack_bf16(float a, float b) {
    uint32_t r;
    asm("cvt.rn.bf16x2.f32 %0, %1, %2;" : "=r"(r) : "f"(b), "f"(a));
    return r;
}
DEV void split_bf(float v, float& hi, float& lo) {
    hi = __bfloat162float(__float2bfloat16(v));
    lo = v - hi;
}
// store 4 consecutive k-values as (hi-pair, lo-pair) uint2 x2
DEV void bf_store4(uint2* base, float4 v) {
    float hx, lx, hy, ly, hz, lz, hw, lw;
    split_bf(v.x, hx, lx); split_bf(v.y, hy, ly);
    split_bf(v.z, hz, lz); split_bf(v.w, hw, lw);
    base[0] = make_uint2(pack_bf16(hx, hy), pack_bf16(lx, ly));
    base[1] = make_uint2(pack_bf16(hz, hw), pack_bf16(lz, lw));
}

// ---------------- 3xTF32 GEMM mainloop (single smem buffer) ----------------
// C[BM,BN] += A[BM,K] * B[BN,K]^T, both K-major fp32.  256 threads.
template<int BM, int BN, int WM, int WN, int MT, int NT>
DEV void gemm_main(const float* __restrict__ A, size_t lda,
                   const float* __restrict__ B, size_t ldb,
                   int K, char* smem, float* acc)
{
    const int tid = threadIdx.x;
    const int lane = tid & 31, wid = tid >> 5;
    const int g = lane >> 2, tq = lane & 3;
    const int wm0 = (wid / WN) * (BM / WM);
    const int wn0 = (wid % WN) * (BN / WN);

    float2* As = (float2*)smem;                    // [BM][PAD]
    float2* Bs = As + BM * PAD;                    // [BN][PAD]

    constexpr int ARE = BM / 64;
    constexpr int BRE = BN / 64;
    float4 ra[ARE], rb[BRE];

    auto load_regs = [&](int c) {
        int k0 = c * 16;
#pragma unroll
        for (int i = 0; i < ARE; i++) {
            int idx = tid + i * 256; int r = idx >> 2; int c4 = (idx & 3) * 4;
            ra[i] = *(const float4*)(A + (size_t)r * lda + k0 + c4);
        }
#pragma unroll
        for (int i = 0; i < BRE; i++) {
            int idx = tid + i * 256; int r = idx >> 2; int c4 = (idx & 3) * 4;
            rb[i] = *(const float4*)(B + (size_t)r * ldb + k0 + c4);
        }
    };
    auto store_smem = [&]() {
#pragma unroll
        for (int i = 0; i < ARE; i++) {
            int idx = tid + i * 256; int r = idx >> 2; int c4 = (idx & 3) * 4;
            float2* base = As + r * PAD + c4;
            split_store(base + 0, ra[i].x); split_store(base + 1, ra[i].y);
            split_store(base + 2, ra[i].z); split_store(base + 3, ra[i].w);
        }
#pragma unroll
        for (int i = 0; i < BRE; i++) {
            int idx = tid + i * 256; int r = idx >> 2; int c4 = (idx & 3) * 4;
            float2* base = Bs + r * PAD + c4;
            split_store(base + 0, rb[i].x); split_store(base + 1, rb[i].y);
            split_store(base + 2, rb[i].z); split_store(base + 3, rb[i].w);
        }
    };
    auto compute = [&]() {
#pragma unroll
        for (int ks = 0; ks < 2; ks++) {
            int kb = ks * 8;
            uint32_t bh[NT][2], bl[NT][2];
#pragma unroll
            for (int ni = 0; ni < NT; ni++) {
                int n0 = wn0 + ni * 8 + g;
                float2 w0 = Bs[n0 * PAD + kb + tq];
                float2 w1 = Bs[n0 * PAD + kb + tq + 4];
                bh[ni][0] = f2u(w0.x); bl[ni][0] = f2u(w0.y);
                bh[ni][1] = f2u(w1.x); bl[ni][1] = f2u(w1.y);
            }
#pragma unroll
            for (int mi = 0; mi < MT; mi++) {
                int r0 = wm0 + mi * 16 + g;
                float2 v0 = As[r0 * PAD + kb + tq];
                float2 v1 = As[(r0 + 8) * PAD + kb + tq];
                float2 v2 = As[r0 * PAD + kb + tq + 4];
                float2 v3 = As[(r0 + 8) * PAD + kb + tq + 4];
                uint32_t ah[4] = { f2u(v0.x), f2u(v1.x), f2u(v2.x), f2u(v3.x) };
                uint32_t al[4] = { f2u(v0.y), f2u(v1.y), f2u(v2.y), f2u(v3.y) };
#pragma unroll
                for (int ni = 0; ni < NT; ni++) {
                    float* c = acc + (mi * NT + ni) * 4;
                    mma_tf32(c, ah, bh[ni]);
                    mma_tf32(c, ah, bl[ni]);
                    mma_tf32(c, al, bh[ni]);
                }
            }
        }
    };

    int nc = K >> 4;
    load_regs(0);
    for (int c = 0; c < nc; c++) {
        store_smem();
        __syncthreads();
        if (c + 1 < nc) load_regs(c + 1);       // gmem prefetch overlaps compute
        compute();
        __syncthreads();
    }
}

// ---------------- 2-limb bf16 x3 GEMM mainloop (single smem buffer) ----------------
template<int BM, int BN, int WM, int WN, int MT, int NT>
DEV void gemm_bf16(const float* __restrict__ A, size_t lda,
                   const float* __restrict__ B, size_t ldb,
                   int K, char* smem, float* acc)
{
    const int tid = threadIdx.x;
    const int lane = tid & 31, wid = tid >> 5;
    const int g = lane >> 2, tq = lane & 3;
    const int wm0 = (wid / WN) * (BM / WM);
    const int wn0 = (wid % WN) * (BN / WN);

    uint2* As = (uint2*)smem;                      // [BM][PADB]
    uint2* Bs = As + BM * PADB;                    // [BN][PADB]

    constexpr int ARE = BM / 64;
    constexpr int BRE = BN / 64;
    float4 ra[ARE], rb[BRE];

    auto load_regs = [&](int c) {
        int k0 = c * 16;
#pragma unroll
        for (int i = 0; i < ARE; i++) {
            int idx = tid + i * 256; int r = idx >> 2; int c4 = (idx & 3) * 4;
            ra[i] = *(const float4*)(A + (size_t)r * lda + k0 + c4);
        }
#pragma unroll
        for (int i = 0; i < BRE; i++) {
            int idx = tid + i * 256; int r = idx >> 2; int c4 = (idx & 3) * 4;
            rb[i] = *(const float4*)(B + (size_t)r * ldb + k0 + c4);
        }
    };
    auto store_smem = [&]() {
#pragma unroll
        for (int i = 0; i < ARE; i++) {
            int idx = tid + i * 256; int r = idx >> 2; int c4 = (idx & 3) * 4;
            bf_store4(As + r * PADB + (c4 >> 1), ra[i]);
        }
#pragma unroll
        for (int i = 0; i < BRE; i++) {
            int idx = tid + i * 256; int r = idx >> 2; int c4 = (idx & 3) * 4;
            bf_store4(Bs + r * PADB + (c4 >> 1), rb[i]);
        }
    };
    auto compute = [&]() {
        uint32_t bh[NT][2], bl[NT][2];
#pragma unroll
        for (int ni = 0; ni < NT; ni++) {
            int n0 = wn0 + ni * 8 + g;
            uint2 w0 = Bs[n0 * PADB + tq];
            uint2 w1 = Bs[n0 * PADB + tq + 4];
            bh[ni][0] = w0.x; bl[ni][0] = w0.y;
            bh[ni][1] = w1.x; bl[ni][1] = w1.y;
        }
#pragma unroll
        for (int mi = 0; mi < MT; mi++) {
            int r0 = wm0 + mi * 16 + g;
            uint2 v0 = As[r0 * PADB + tq];
            uint2 v1 = As[(r0 + 8) * PADB + tq];
            uint2 v2 = As[r0 * PADB + tq + 4];
            uint2 v3 = As[(r0 + 8) * PADB + tq + 4];
            uint32_t ah[4] = { v0.x, v1.x, v2.x, v3.x };
            uint32_t al[4] = { v0.y, v1.y, v2.y, v3.y };
#pragma unroll
            for (int ni = 0; ni < NT; ni++) {
                float* c = acc + (mi * NT + ni) * 4;
                mma_bf16(c, ah, bh[ni]);
                mma_bf16(c, ah, bl[ni]);
                mma_bf16(c, al, bh[ni]);
            }
        }
    };

    int nc = K >> 4;
    load_regs(0);
    for (int c = 0; c < nc; c++) {
        store_smem();
        __syncthreads();
        if (c + 1 < nc) load_regs(c + 1);
        compute();
        __syncthreads();
    }
}

// epilogue iteration: calls fn(row, col, val) for each accumulator element
template<int BM, int BN, int WM, int WN, int MT, int NT, typename F>
DEV void epilogue(const float* acc, F fn)
{
    int lane = threadIdx.x & 31, wid = threadIdx.x >> 5;
    int g = lane >> 2, tq = lane & 3;
    int wm0 = (wid / WN) * (BM / WM);
    int wn0 = (wid % WN) * (BN / WN);
#pragma unroll
    for (int mi = 0; mi < MT; mi++)
#pragma unroll
        for (int ni = 0; ni < NT; ni++)
#pragma unroll
            for (int cj = 0; cj < 4; cj++) {
                int row = wm0 + mi * 16 + g + ((cj >= 2) ? 8 : 0);
                int col = wn0 + ni * 8 + 2 * tq + (cj & 1);
                fn(row, col, acc[(mi * NT + ni) * 4 + cj]);
            }
}

// ---------------- dequant ----------------
__global__ __launch_bounds__(256) void dequant_kernel(
    const int* __restrict__ qw, const float* __restrict__ sc,
    const float* __restrict__ zr, float* __restrict__ w)
{
    int idx = blockIdx.x * 256 + threadIdx.x;
    int o = idx >> 10, i = idx & 1023, grp = i >> 6;
    w[idx] = ((float)qw[idx] - zr[o * 16 + grp]) * sc[o * 16 + grp];
}

// ---------------- QKV projection ----------------
#define QKV_SMEM ((128 + 128) * PAD * 8)                 // 40960 B
__global__ __launch_bounds__(256, 2) void proj_qkv_kernel(
    const float* __restrict__ x, const float* __restrict__ bq,
    const float* __restrict__ bk, const float* __restrict__ bv)
{
    extern __shared__ char smem[];
    int mode = blockIdx.z;
    int n0 = blockIdx.x * 128, m0 = blockIdx.y * 128;
    const float* B = g_w[mode];
    const float* bias = mode == 0 ? bq : (mode == 1 ? bk : bv);

    float acc[64];
#pragma unroll
    for (int i = 0; i < 64; i++) acc[i] = 0.f;

    gemm_main<128, 128, 2, 4, 4, 4>(x + (size_t)m0 * EMB, EMB,
                                    B + (size_t)n0 * EMB, EMB, EMB, smem, acc);

    if (mode < 2) {
        float* dst = mode == 0 ? g_q : g_k;
        epilogue<128, 128, 2, 4, 4, 4>(acc, [&](int row, int col, float val) {
            int token = m0 + row, o = n0 + col;
            int b = token >> 11, si = token & 2047;
            int h = o >> 6, d = o & 63;
            dst[((size_t)(b * 16 + h) * S_LEN + si) * 64 + d] = val + bias[o];
        });
    } else {
        // transpose through smem in two 64-col halves (fits 40KB buffer)
        float* T = (float*)smem;   // [64][132]
        for (int half = 0; half < 2; half++) {
            int c0 = half * 64;
            __syncthreads();
            epilogue<128, 128, 2, 4, 4, 4>(acc, [&](int row, int col, float val) {
                if (col >= c0 && col < c0 + 64)
                    T[(col - c0) * 132 + row] = val + bias[n0 + col];
            });
            __syncthreads();
            for (int i = threadIdx.x; i < 64 * 128; i += 256) {
                int cl = i >> 7, rw = i & 127;
                int o = n0 + c0 + cl; int h = o >> 6, d = o & 63;
                int token = m0 + rw; int b = token >> 11, si = token & 2047;
                g_vt[((size_t)(b * 16 + h) * 64 + d) * S_LEN + si] = T[cl * 132 + rw];
            }
        }
    }
}

// ---------------- scores ----------------
__global__ __launch_bounds__(256, 2) void scores_kernel(float* __restrict__ attn)
{
    extern __shared__ char smem[];
    int bh = blockIdx.z;
    int n0 = blockIdx.x * 128, m0 = blockIdx.y * 128;
    size_t base = (size_t)bh * S_LEN * 64;

    float acc[64];
#pragma unroll
    for (int i = 0; i < 64; i++) acc[i] = 0.f;

    gemm_main<128, 128, 2, 4, 4, 4>(g_q + base + (size_t)m0 * 64, 64,
                                    g_k + base + (size_t)n0 * 64, 64, 64, smem, acc);

    float* out = attn + (size_t)bh * S_LEN * S_LEN;
    epilogue<128, 128, 2, 4, 4, 4>(acc, [&](int row, int col, float val) {
        out[(size_t)(m0 + row) * S_LEN + n0 + col] = val * 0.125f;
    });
}

// ---------------- softmax (in place) ----------------
__global__ __launch_bounds__(256) void softmax_kernel(float* __restrict__ S)
{
    size_t row = blockIdx.x;
    float* p = S + row * S_LEN;
    int t = threadIdx.x;
    float v[8];
#pragma unroll
    for (int i = 0; i < 8; i++) v[i] = p[t + i * 256];
    float m = v[0];
#pragma unroll
    for (int i = 1; i < 8; i++) m = fmaxf(m, v[i]);
#pragma unroll
    for (int o = 16; o > 0; o >>= 1) m = fmaxf(m, __shfl_xor_sync(0xffffffffu, m, o));
    __shared__ float sred[8]; __shared__ float sbc;
    if ((t & 31) == 0) sred[t >> 5] = m;
    __syncthreads();
    if (t == 0) {
        float x = sred[0];
#pragma unroll
        for (int i = 1; i < 8; i++) x = fmaxf(x, sred[i]);
        sbc = x;
    }
    __syncthreads();
    m = sbc;
    float sum = 0.f;
#pragma unroll
    for (int i = 0; i < 8; i++) { v[i] = __expf(v[i] - m); sum += v[i]; }
#pragma unroll
    for (int o = 16; o > 0; o >>= 1) sum += __shfl_xor_sync(0xffffffffu, sum, o);
    __syncthreads();
    if ((t & 31) == 0) sred[t >> 5] = sum;
    __syncthreads();
    if (t == 0) {
        float x = 0.f;
#pragma unroll
        for (int i = 0; i < 8; i++) x += sred[i];
        sbc = 1.0f / x;
    }
    __syncthreads();
    float inv = sbc;
#pragma unroll
    for (int i = 0; i < 8; i++) p[t + i * 256] = v[i] * inv;
}

// ---------------- PV (2-limb bf16) ----------------
#define PV_SMEM ((128 + 64) * PADB * 8)                  // 15360 B
__global__ __launch_bounds__(256, 2) void pv_kernel(const float* __restrict__ attn)
{
    extern __shared__ char smem[];
    int bh = blockIdx.z;
    int m0 = blockIdx.y * 128;

    float acc[32];
#pragma unroll
    for (int i = 0; i < 32; i++) acc[i] = 0.f;

    gemm_bf16<128, 64, 4, 2, 2, 4>(attn + (size_t)bh * S_LEN * S_LEN + (size_t)m0 * S_LEN, S_LEN,
                                   g_vt + (size_t)bh * 64 * S_LEN, S_LEN, S_LEN, smem, acc);

    int b = bh >> 4, h = bh & 15;
    epilogue<128, 64, 4, 2, 2, 4>(acc, [&](int row, int col, float val) {
        size_t token = (size_t)b * S_LEN + m0 + row;
        g_ao[token * EMB + h * 64 + col] = val;
    });
}

// ---------------- O projection (2-limb bf16) ----------------
#define OP_SMEM ((128 + 128) * PADB * 8)                 // 20480 B
__global__ __launch_bounds__(256, 2) void oproj_kernel(
    const float* __restrict__ bias, float* __restrict__ out)
{
    extern __shared__ char smem[];
    int n0 = blockIdx.x * 128, m0 = blockIdx.y * 128;

    float acc[64];
#pragma unroll
    for (int i = 0; i < 64; i++) acc[i] = 0.f;

    gemm_bf16<128, 128, 2, 4, 4, 4>(g_ao + (size_t)m0 * EMB, EMB,
                                    g_w[3] + (size_t)n0 * EMB, EMB, EMB, smem, acc);

    epilogue<128, 128, 2, 4, 4, 4>(acc, [&](int row, int col, float val) {
        int token = m0 + row, o = n0 + col;
        out[(size_t)token * EMB + o] = val + bias[o];
    });
}

// ---------------- launch ----------------
extern "C" void kernel_launch(void* const* d_in, const int* in_sizes, int n_in,
                              void* d_out, int out_size)
{
    const float* x = (const float*)d_in[0];
    const int* qw[4];
    const float *sc[4], *zr[4], *bs[4];
    for (int p = 0; p < 4; p++) {
        qw[p] = (const int*)d_in[1 + 4 * p];
        sc[p] = (const float*)d_in[2 + 4 * p];
        zr[p] = (const float*)d_in[3 + 4 * p];
        bs[p] = (const float*)d_in[4 + 4 * p];
    }
    float* out = (float*)d_out;                 // [B,S,E]
    float* attn = out + (size_t)4194304;        // [B,H,S,S]

    float* wbase; cudaGetSymbolAddress((void**)&wbase, g_w);

    cudaFuncSetAttribute(proj_qkv_kernel, cudaFuncAttributeMaxDynamicSharedMemorySize, QKV_SMEM);
    cudaFuncSetAttribute(scores_kernel,   cudaFuncAttributeMaxDynamicSharedMemorySize, QKV_SMEM);
    cudaFuncSetAttribute(pv_kernel,       cudaFuncAttributeMaxDynamicSharedMemorySize, PV_SMEM);
    cudaFuncSetAttribute(oproj_kernel,    cudaFuncAttributeMaxDynamicSharedMemorySize, OP_SMEM);

    for (int p = 0; p < 4; p++)
        dequant_kernel<<<4096, 256>>>(qw[p], sc[p], zr[p], wbase + (size_t)p * 1024 * 1024);

    proj_qkv_kernel<<<dim3(8, 32, 3), 256, QKV_SMEM>>>(x, bs[0], bs[1], bs[2]);
    scores_kernel<<<dim3(16, 16, 32), 256, QKV_SMEM>>>(attn);
    softmax_kernel<<<65536, 256>>>(attn);
    pv_kernel<<<dim3(1, 16, 32), 256, PV_SMEM>>>(attn);
    oproj_kernel<<<dim3(8, 32), 256, OP_SMEM>>>(bs[3], out);
}

// round 6
// speedup vs baseline: 2.3635x; 1.0246x over previous
#include <cuda_runtime.h>
#include <cuda_bf16.h>
#include <cstdint>
#include <cstddef>

#define DEV __device__ __forceinline__

#define S_LEN 2048
#define EMB   1024
#define PAD   20          // float2 per SMEM row (16 data + 4 pad) = 160 B
#define PADB  10          // uint2 per SMEM row (8 data + 2 pad)   = 80 B

// ---------------- scratch (16B-aligned via float4/uint4) ----------------
__device__ float4 g_xs4[4096 * 1024 / 2];            // x  tf32 (hi,lo) pairs
__device__ float4 g_ws4[3][1024 * 1024 / 2];         // q/k/v weights tf32 pairs
__device__ uint4  g_wo4[1024 * 1024 / 4];            // o weights bf16 limb pairs
__device__ float4 g_qs4[32 * 2048 * 64 / 2];         // q tf32 pairs [bh][s][d]
__device__ float4 g_ks4[32 * 2048 * 64 / 2];
__device__ uint4  g_vts4[32 * 64 * 2048 / 4];        // v^T bf16 limbs [bh][d][s/2]
__device__ uint4  g_pps4[(size_t)32 * 2048 * 2048 / 4];  // P bf16 limbs [bh*s][t/2]
__device__ uint4  g_aos4[4096 * 1024 / 4];           // attn-out bf16 limbs [tok][e/2]

DEV uint32_t f2u(float f) { return __float_as_uint(f); }

DEV uint32_t smem_u32(const void* p) {
    uint32_t a;
    asm("{ .reg .u64 t; cvta.to.shared.u64 t, %1; cvt.u32.u64 %0, t; }" : "=r"(a) : "l"(p));
    return a;
}
DEV void cp16(uint32_t dst, const void* src) {
    asm volatile("cp.async.cg.shared.global [%0], [%1], 16;" :: "r"(dst), "l"(src));
}
DEV void cp_commit() { asm volatile("cp.async.commit_group;" ::: "memory"); }
template<int N> DEV void cp_wait() { asm volatile("cp.async.wait_group %0;" :: "n"(N) : "memory"); }

DEV void mma_tf32(float* c, const uint32_t* a, const uint32_t* b) {
    asm volatile(
        "mma.sync.aligned.m16n8k8.row.col.f32.tf32.tf32.f32 "
        "{%0,%1,%2,%3}, {%4,%5,%6,%7}, {%8,%9}, {%0,%1,%2,%3};"
        : "+f"(c[0]), "+f"(c[1]), "+f"(c[2]), "+f"(c[3])
        : "r"(a[0]), "r"(a[1]), "r"(a[2]), "r"(a[3]), "r"(b[0]), "r"(b[1]));
}
DEV void mma_bf16(float* c, const uint32_t* a, const uint32_t* b) {
    asm volatile(
        "mma.sync.aligned.m16n8k16.row.col.f32.bf16.bf16.f32 "
        "{%0,%1,%2,%3}, {%4,%5,%6,%7}, {%8,%9}, {%0,%1,%2,%3};"
        : "+f"(c[0]), "+f"(c[1]), "+f"(c[2]), "+f"(c[3])
        : "r"(a[0]), "r"(a[1]), "r"(a[2]), "r"(a[3]), "r"(b[0]), "r"(b[1]));
}

// fp32 -> interleaved (tf32 hi, tf32 lo)
DEV void split_store(float2* s, float v) {
    uint32_t hb; asm("cvt.rna.tf32.f32 %0, %1;" : "=r"(hb) : "f"(v));
    float hf = __uint_as_float(hb);
    float lo = v - hf;
    uint32_t lb; asm("cvt.rna.tf32.f32 %0, %1;" : "=r"(lb) : "f"(lo));
    s->x = hf; s->y = __uint_as_float(lb);
}
DEV uint32_t pack_bf16(float a, float b) {
    uint32_t r;
    asm("cvt.rn.bf16x2.f32 %0, %1, %2;" : "=r"(r) : "f"(b), "f"(a));
    return r;
}
DEV void split_bf(float v, float& hi, float& lo) {
    hi = __bfloat162float(__float2bfloat16(v));
    lo = v - hi;
}
// two fp32 values -> uint2(hi-pair, lo-pair)
DEV uint2 limb2(float a, float b) {
    float ha, la, hb, lb;
    split_bf(a, ha, la); split_bf(b, hb, lb);
    return make_uint2(pack_bf16(ha, hb), pack_bf16(la, lb));
}

// ---------------- async 3xTF32 GEMM (2-stage, 1 sync/chunk) ----------------
// A,B: pre-split float2 pairs, K-major, lda/ldb in PAIRS.
template<int BM, int BN, int WM, int WN, int MT, int NT>
DEV void gemm_async_tf32(const float2* __restrict__ A, int lda,
                         const float2* __restrict__ B, int ldb,
                         int K, char* smem, uint32_t su, float* acc)
{
    const int tid = threadIdx.x;
    const int lane = tid & 31, wid = tid >> 5;
    const int g = lane >> 2, tq = lane & 3;
    const int wm0 = (wid / WN) * (BM / WM);
    const int wn0 = (wid % WN) * (BN / WN);

    constexpr int SA = BM * PAD * 8;           // bytes per A stage
    constexpr int STAGE = SA + BN * PAD * 8;

    auto copy_chunk = [&](int c, int s) {
        uint32_t base = su + s * STAGE;
#pragma unroll
        for (int t = 0; t < BM * 8 / 256; t++) {
            int idx = tid + t * 256; int r = idx >> 3, j = idx & 7;
            cp16(base + r * 160 + j * 16, A + (size_t)r * lda + c * 16 + j * 2);
        }
#pragma unroll
        for (int t = 0; t < BN * 8 / 256; t++) {
            int idx = tid + t * 256; int r = idx >> 3, j = idx & 7;
            cp16(base + SA + r * 160 + j * 16, B + (size_t)r * ldb + c * 16 + j * 2);
        }
        cp_commit();
    };
    auto compute = [&](int s) {
        const float2* Ab = (const float2*)(smem + s * STAGE);
        const float2* Bb = (const float2*)(smem + s * STAGE + SA);
#pragma unroll
        for (int ks = 0; ks < 2; ks++) {
            int kb = ks * 8;
            uint32_t bh[NT][2], bl[NT][2];
#pragma unroll
            for (int ni = 0; ni < NT; ni++) {
                int n0 = wn0 + ni * 8 + g;
                float2 w0 = Bb[n0 * PAD + kb + tq];
                float2 w1 = Bb[n0 * PAD + kb + tq + 4];
                bh[ni][0] = f2u(w0.x); bl[ni][0] = f2u(w0.y);
                bh[ni][1] = f2u(w1.x); bl[ni][1] = f2u(w1.y);
            }
#pragma unroll
            for (int mi = 0; mi < MT; mi++) {
                int r0 = wm0 + mi * 16 + g;
                float2 v0 = Ab[r0 * PAD + kb + tq];
                float2 v1 = Ab[(r0 + 8) * PAD + kb + tq];
                float2 v2 = Ab[r0 * PAD + kb + tq + 4];
                float2 v3 = Ab[(r0 + 8) * PAD + kb + tq + 4];
                uint32_t ah[4] = { f2u(v0.x), f2u(v1.x), f2u(v2.x), f2u(v3.x) };
                uint32_t al[4] = { f2u(v0.y), f2u(v1.y), f2u(v2.y), f2u(v3.y) };
#pragma unroll
                for (int ni = 0; ni < NT; ni++) {
                    float* c = acc + (mi * NT + ni) * 4;
                    mma_tf32(c, ah, bh[ni]);
                    mma_tf32(c, ah, bl[ni]);
                    mma_tf32(c, al, bh[ni]);
                }
            }
        }
    };

    int nc = K >> 4;
    copy_chunk(0, 0);
    for (int c = 0; c < nc; c++) {
        cp_wait<0>();
        __syncthreads();
        if (c + 1 < nc) copy_chunk(c + 1, (c + 1) & 1);
        compute(c & 1);
    }
}

// ---------------- async 2-limb bf16 x3 GEMM (2-stage, 1 sync/chunk) ----------------
// A,B: bf16 limb-pair uint2 ([row][elem/2]), lda/ldb in uint2 units.
template<int BM, int BN, int WM, int WN, int MT, int NT>
DEV void gemm_async_bf16(const uint2* __restrict__ A, int lda,
                         const uint2* __restrict__ B, int ldb,
                         int K, char* smem, uint32_t su, float* acc)
{
    const int tid = threadIdx.x;
    const int lane = tid & 31, wid = tid >> 5;
    const int g = lane >> 2, tq = lane & 3;
    const int wm0 = (wid / WN) * (BM / WM);
    const int wn0 = (wid % WN) * (BN / WN);

    constexpr int SA = BM * PADB * 8;
    constexpr int STAGE = SA + BN * PADB * 8;

    auto copy_chunk = [&](int c, int s) {
        uint32_t base = su + s * STAGE;
#pragma unroll
        for (int t = 0; t < BM * 4 / 256; t++) {
            int idx = tid + t * 256; int r = idx >> 2, j = idx & 3;
            cp16(base + r * 80 + j * 16, A + (size_t)r * lda + c * 8 + j * 2);
        }
#pragma unroll
        for (int t = 0; t < (BN * 4 + 255) / 256; t++) {
            int idx = tid + t * 256;
            if (BN * 4 % 256 == 0 || idx < BN * 4) {
                int r = idx >> 2, j = idx & 3;
                cp16(base + SA + r * 80 + j * 16, B + (size_t)r * ldb + c * 8 + j * 2);
            }
        }
        cp_commit();
    };
    auto compute = [&](int s) {
        const uint2* Ab = (const uint2*)(smem + s * STAGE);
        const uint2* Bb = (const uint2*)(smem + s * STAGE + SA);
        uint32_t bh[NT][2], bl[NT][2];
#pragma unroll
        for (int ni = 0; ni < NT; ni++) {
            int n0 = wn0 + ni * 8 + g;
            uint2 w0 = Bb[n0 * PADB + tq];
            uint2 w1 = Bb[n0 * PADB + tq + 4];
            bh[ni][0] = w0.x; bl[ni][0] = w0.y;
            bh[ni][1] = w1.x; bl[ni][1] = w1.y;
        }
#pragma unroll
        for (int mi = 0; mi < MT; mi++) {
            int r0 = wm0 + mi * 16 + g;
            uint2 v0 = Ab[r0 * PADB + tq];
            uint2 v1 = Ab[(r0 + 8) * PADB + tq];
            uint2 v2 = Ab[r0 * PADB + tq + 4];
            uint2 v3 = Ab[(r0 + 8) * PADB + tq + 4];
            uint32_t ah[4] = { v0.x, v1.x, v2.x, v3.x };
            uint32_t al[4] = { v0.y, v1.y, v2.y, v3.y };
#pragma unroll
            for (int ni = 0; ni < NT; ni++) {
                float* c = acc + (mi * NT + ni) * 4;
                mma_bf16(c, ah, bh[ni]);
                mma_bf16(c, ah, bl[ni]);
                mma_bf16(c, al, bh[ni]);
            }
        }
    };

    int nc = K >> 4;
    copy_chunk(0, 0);
    for (int c = 0; c < nc; c++) {
        cp_wait<0>();
        __syncthreads();
        if (c + 1 < nc) copy_chunk(c + 1, (c + 1) & 1);
        compute(c & 1);
    }
}

// epilogue iteration: calls fn(row, col, val)
template<int BM, int BN, int WM, int WN, int MT, int NT, typename F>
DEV void epilogue(const float* acc, F fn)
{
    int lane = threadIdx.x & 31, wid = threadIdx.x >> 5;
    int g = lane >> 2, tq = lane & 3;
    int wm0 = (wid / WN) * (BM / WM);
    int wn0 = (wid % WN) * (BN / WN);
#pragma unroll
    for (int mi = 0; mi < MT; mi++)
#pragma unroll
        for (int ni = 0; ni < NT; ni++)
#pragma unroll
            for (int cj = 0; cj < 4; cj++) {
                int row = wm0 + mi * 16 + g + ((cj >= 2) ? 8 : 0);
                int col = wn0 + ni * 8 + 2 * tq + (cj & 1);
                fn(row, col, acc[(mi * NT + ni) * 4 + cj]);
            }
}

// ---------------- prep kernels ----------------
__global__ __launch_bounds__(256) void x_split_kernel(const float* __restrict__ x)
{
    int idx = blockIdx.x * 256 + threadIdx.x;
    split_store((float2*)g_xs4 + idx, x[idx]);
}

__global__ __launch_bounds__(256) void dequant_qkv_kernel(
    const int* __restrict__ qw, const float* __restrict__ sc,
    const float* __restrict__ zr, int mode)
{
    int idx = blockIdx.x * 256 + threadIdx.x;
    int o = idx >> 10, i = idx & 1023, grp = i >> 6;
    float v = ((float)qw[idx] - zr[o * 16 + grp]) * sc[o * 16 + grp];
    split_store((float2*)g_ws4[mode] + idx, v);
}

__global__ __launch_bounds__(256) void dequant_o_kernel(
    const int* __restrict__ qw, const float* __restrict__ sc,
    const float* __restrict__ zr)
{
    int idx4 = (blockIdx.x * 256 + threadIdx.x) * 4;
    int o = idx4 >> 10, i = idx4 & 1023, grp = i >> 6;
    float s = sc[o * 16 + grp], z = zr[o * 16 + grp];
    uint2* dst = (uint2*)g_wo4 + (idx4 >> 1);
    dst[0] = limb2(((float)qw[idx4 + 0] - z) * s, ((float)qw[idx4 + 1] - z) * s);
    dst[1] = limb2(((float)qw[idx4 + 2] - z) * s, ((float)qw[idx4 + 3] - z) * s);
}

// ---------------- QKV projection ----------------
#define QKV_SMEM (2 * (128 + 128) * PAD * 8)            // 81920 B
__global__ __launch_bounds__(256, 2) void proj_qkv_kernel(
    const float* __restrict__ bq, const float* __restrict__ bk,
    const float* __restrict__ bv)
{
    extern __shared__ char smem[];
    uint32_t su = smem_u32(smem);
    int mode = blockIdx.z;
    int n0 = blockIdx.x * 128, m0 = blockIdx.y * 128;
    const float* bias = mode == 0 ? bq : (mode == 1 ? bk : bv);

    float acc[64];
#pragma unroll
    for (int i = 0; i < 64; i++) acc[i] = 0.f;

    gemm_async_tf32<128, 128, 2, 4, 4, 4>(
        (const float2*)g_xs4 + (size_t)m0 * EMB, EMB,
        (const float2*)g_ws4[mode] + (size_t)n0 * EMB, EMB, EMB, smem, su, acc);

    if (mode < 2) {
        float2* dst = mode == 0 ? (float2*)g_qs4 : (float2*)g_ks4;
        epilogue<128, 128, 2, 4, 4, 4>(acc, [&](int row, int col, float val) {
            int token = m0 + row, o = n0 + col;
            int b = token >> 11, si = token & 2047;
            int h = o >> 6, d = o & 63;
            split_store(dst + ((size_t)(b * 16 + h) * S_LEN + si) * 64 + d, val + bias[o]);
        });
    } else {
        // transpose through smem in two 64-col halves, write bf16 limb pairs
        float* T = (float*)smem;   // [64][132]
        int b = m0 >> 11, si0 = m0 & 2047;
        for (int half = 0; half < 2; half++) {
            int c0 = half * 64;
            __syncthreads();
            epilogue<128, 128, 2, 4, 4, 4>(acc, [&](int row, int col, float val) {
                if (col >= c0 && col < c0 + 64)
                    T[(col - c0) * 132 + row] = val + bias[n0 + col];
            });
            __syncthreads();
            for (int i = threadIdx.x; i < 64 * 64; i += 256) {
                int cl = i >> 6, sp = i & 63;
                int o = n0 + c0 + cl; int h = o >> 6, d = o & 63;
                uint2 v = limb2(T[cl * 132 + 2 * sp], T[cl * 132 + 2 * sp + 1]);
                ((uint2*)g_vts4)[((size_t)(b * 16 + h) * 64 + d) * 1024 + ((si0 + 2 * sp) >> 1)] = v;
            }
        }
    }
}

// ---------------- scores ----------------
__global__ __launch_bounds__(256, 2) void scores_kernel(float* __restrict__ attn)
{
    extern __shared__ char smem[];
    uint32_t su = smem_u32(smem);
    int bh = blockIdx.z;
    int n0 = blockIdx.x * 128, m0 = blockIdx.y * 128;
    size_t base = (size_t)bh * S_LEN * 64;

    float acc[64];
#pragma unroll
    for (int i = 0; i < 64; i++) acc[i] = 0.f;

    gemm_async_tf32<128, 128, 2, 4, 4, 4>(
        (const float2*)g_qs4 + base + (size_t)m0 * 64, 64,
        (const float2*)g_ks4 + base + (size_t)n0 * 64, 64, 64, smem, su, acc);

    float* out = attn + (size_t)bh * S_LEN * S_LEN;
    epilogue<128, 128, 2, 4, 4, 4>(acc, [&](int row, int col, float val) {
        out[(size_t)(m0 + row) * S_LEN + n0 + col] = val * 0.125f;
    });
}

// ---------------- softmax (in place) + write bf16 limb P ----------------
__global__ __launch_bounds__(256) void softmax_kernel(float* __restrict__ S)
{
    size_t row = blockIdx.x;
    float4* p4 = (float4*)(S + row * S_LEN);
    int t = threadIdx.x;
    float4 u0 = p4[2 * t], u1 = p4[2 * t + 1];
    float v[8] = { u0.x, u0.y, u0.z, u0.w, u1.x, u1.y, u1.z, u1.w };
    float m = v[0];
#pragma unroll
    for (int i = 1; i < 8; i++) m = fmaxf(m, v[i]);
#pragma unroll
    for (int o = 16; o > 0; o >>= 1) m = fmaxf(m, __shfl_xor_sync(0xffffffffu, m, o));
    __shared__ float sred[8]; __shared__ float sbc;
    if ((t & 31) == 0) sred[t >> 5] = m;
    __syncthreads();
    if (t == 0) {
        float x = sred[0];
#pragma unroll
        for (int i = 1; i < 8; i++) x = fmaxf(x, sred[i]);
        sbc = x;
    }
    __syncthreads();
    m = sbc;
    float sum = 0.f;
#pragma unroll
    for (int i = 0; i < 8; i++) { v[i] = __expf(v[i] - m); sum += v[i]; }
#pragma unroll
    for (int o = 16; o > 0; o >>= 1) sum += __shfl_xor_sync(0xffffffffu, sum, o);
    __syncthreads();
    if ((t & 31) == 0) sred[t >> 5] = sum;
    __syncthreads();
    if (t == 0) {
        float x = 0.f;
#pragma unroll
        for (int i = 0; i < 8; i++) x += sred[i];
        sbc = 1.0f / x;
    }
    __syncthreads();
    float inv = sbc;
    float w[8];
#pragma unroll
    for (int i = 0; i < 8; i++) w[i] = v[i] * inv;
    p4[2 * t]     = make_float4(w[0], w[1], w[2], w[3]);
    p4[2 * t + 1] = make_float4(w[4], w[5], w[6], w[7]);
    uint2* lp = (uint2*)g_pps4 + row * 1024 + t * 4;
    lp[0] = limb2(w[0], w[1]); lp[1] = limb2(w[2], w[3]);
    lp[2] = limb2(w[4], w[5]); lp[3] = limb2(w[6], w[7]);
}

// ---------------- PV ----------------
#define PV_SMEM (2 * (128 + 64) * PADB * 8)             // 30720 B
__global__ __launch_bounds__(256, 2) void pv_kernel()
{
    extern __shared__ char smem[];
    uint32_t su = smem_u32(smem);
    int bh = blockIdx.z;
    int m0 = blockIdx.y * 128;

    float acc[32];
#pragma unroll
    for (int i = 0; i < 32; i++) acc[i] = 0.f;

    gemm_async_bf16<128, 64, 4, 2, 2, 4>(
        (const uint2*)g_pps4 + ((size_t)bh * S_LEN + m0) * 1024, 1024,
        (const uint2*)g_vts4 + (size_t)bh * 64 * 1024, 1024, S_LEN, smem, su, acc);

    int b = bh >> 4, h = bh & 15;
    {
        int lane = threadIdx.x & 31, wid = threadIdx.x >> 5;
        int g = lane >> 2, tq = lane & 3;
        int wm0 = (wid / 2) * 32;
        int wn0 = (wid % 2) * 32;
#pragma unroll
        for (int mi = 0; mi < 2; mi++)
#pragma unroll
            for (int ni = 0; ni < 4; ni++) {
                const float* c = acc + (mi * 4 + ni) * 4;
                int col0 = wn0 + ni * 8 + 2 * tq;
                int r0 = wm0 + mi * 16 + g;
                size_t tok0 = (size_t)b * S_LEN + m0 + r0;
                ((uint2*)g_aos4)[tok0 * 512 + (h * 64 + col0) / 2] = limb2(c[0], c[1]);
                ((uint2*)g_aos4)[(tok0 + 8) * 512 + (h * 64 + col0) / 2] = limb2(c[2], c[3]);
            }
    }
}

// ---------------- O projection ----------------
#define OP_SMEM (2 * (128 + 128) * PADB * 8)            // 40960 B
__global__ __launch_bounds__(256, 2) void oproj_kernel(
    const float* __restrict__ bias, float* __restrict__ out)
{
    extern __shared__ char smem[];
    uint32_t su = smem_u32(smem);
    int n0 = blockIdx.x * 128, m0 = blockIdx.y * 128;

    float acc[64];
#pragma unroll
    for (int i = 0; i < 64; i++) acc[i] = 0.f;

    gemm_async_bf16<128, 128, 2, 4, 4, 4>(
        (const uint2*)g_aos4 + (size_t)m0 * 512, 512,
        (const uint2*)g_wo4 + (size_t)n0 * 512, 512, EMB, smem, su, acc);

    epilogue<128, 128, 2, 4, 4, 4>(acc, [&](int row, int col, float val) {
        int token = m0 + row, o = n0 + col;
        out[(size_t)token * EMB + o] = val + bias[o];
    });
}

// ---------------- launch ----------------
extern "C" void kernel_launch(void* const* d_in, const int* in_sizes, int n_in,
                              void* d_out, int out_size)
{
    const float* x = (const float*)d_in[0];
    const int* qw[4];
    const float *sc[4], *zr[4], *bs[4];
    for (int p = 0; p < 4; p++) {
        qw[p] = (const int*)d_in[1 + 4 * p];
        sc[p] = (const float*)d_in[2 + 4 * p];
        zr[p] = (const float*)d_in[3 + 4 * p];
        bs[p] = (const float*)d_in[4 + 4 * p];
    }
    float* out = (float*)d_out;                 // [B,S,E]
    float* attn = out + (size_t)4194304;        // [B,H,S,S]

    cudaFuncSetAttribute(proj_qkv_kernel, cudaFuncAttributeMaxDynamicSharedMemorySize, QKV_SMEM);
    cudaFuncSetAttribute(scores_kernel,   cudaFuncAttributeMaxDynamicSharedMemorySize, QKV_SMEM);
    cudaFuncSetAttribute(pv_kernel,       cudaFuncAttributeMaxDynamicSharedMemorySize, PV_SMEM);
    cudaFuncSetAttribute(oproj_kernel,    cudaFuncAttributeMaxDynamicSharedMemorySize, OP_SMEM);

    x_split_kernel<<<16384, 256>>>(x);
    for (int p = 0; p < 3; p++)
        dequant_qkv_kernel<<<4096, 256>>>(qw[p], sc[p], zr[p], p);
    dequant_o_kernel<<<1024, 256>>>(qw[3], sc[3], zr[3]);

    proj_qkv_kernel<<<dim3(8, 32, 3), 256, QKV_SMEM>>>(bs[0], bs[1], bs[2]);
    scores_kernel<<<dim3(16, 16, 32), 256, QKV_SMEM>>>(attn);
    softmax_kernel<<<65536, 256>>>(attn);
    pv_kernel<<<dim3(1, 16, 32), 256, PV_SMEM>>>();
    oproj_kernel<<<dim3(8, 32), 256, OP_SMEM>>>(bs[3], out);
}

// round 11
// speedup vs baseline: 2.6651x; 1.1276x over previous
#include <cuda_runtime.h>
#include <cuda_bf16.h>
#include <cstdint>
#include <cstddef>

#define DEV __device__ __forceinline__

#define S_LEN 2048
#define EMB   1024
#define PAD   20          // float2 per SMEM row (16 data + 4 pad) = 160 B
#define PADB  10          // uint2 per SMEM row (8 data + 2 pad)   = 80 B

// ---------------- scratch (16B-aligned) ----------------
__device__ uint4  g_xbf4[4096 * 1024 / 4];           // x bf16 limb pairs [t][e/2]  (4B/elem!)
__device__ __align__(16) float g_xg[4096 * 16];      // group sums of x [t][g]
__device__ uint4  g_wqkvl4[3][1024 * 1024 / 4];      // qw as (bf16 pair, 0) limb uint2 [o][e/2]
__device__ __align__(16) float g_s[3][1024 * 16];    // scales [o][g]
__device__ __align__(16) float g_sz[3][1024 * 16];   // scale*zero [o][g]
__device__ uint4  g_wo4[1024 * 1024 / 4];            // o weights bf16 limb pairs
__device__ float4 g_qs4[32 * 2048 * 64 / 2];         // q tf32 pairs [bh][s][d]
__device__ float4 g_ks4[32 * 2048 * 64 / 2];
__device__ uint4  g_vts4[32 * 64 * 2048 / 4];        // v^T bf16 limbs [bh][d][s/2]
__device__ uint4  g_pps4[(size_t)32 * 2048 * 2048 / 4];  // P bf16 limbs [bh*s][t/2]
__device__ uint4  g_aos4[4096 * 1024 / 4];           // attn-out bf16 limbs [tok][e/2]

DEV uint32_t f2u(float f) { return __float_as_uint(f); }

DEV uint32_t smem_u32(const void* p) {
    uint32_t a;
    asm("{ .reg .u64 t; cvta.to.shared.u64 t, %1; cvt.u32.u64 %0, t; }" : "=r"(a) : "l"(p));
    return a;
}
DEV void cp16(uint32_t dst, const void* src) {
    asm volatile("cp.async.cg.shared.global [%0], [%1], 16;" :: "r"(dst), "l"(src));
}
DEV void cp_commit() { asm volatile("cp.async.commit_group;" ::: "memory"); }
template<int N> DEV void cp_wait() { asm volatile("cp.async.wait_group %0;" :: "n"(N) : "memory"); }

DEV void mma_tf32(float* c, const uint32_t* a, const uint32_t* b) {
    asm volatile(
        "mma.sync.aligned.m16n8k8.row.col.f32.tf32.tf32.f32 "
        "{%0,%1,%2,%3}, {%4,%5,%6,%7}, {%8,%9}, {%0,%1,%2,%3};"
        : "+f"(c[0]), "+f"(c[1]), "+f"(c[2]), "+f"(c[3])
        : "r"(a[0]), "r"(a[1]), "r"(a[2]), "r"(a[3]), "r"(b[0]), "r"(b[1]));
}
DEV void mma_bf16(float* c, const uint32_t* a, const uint32_t* b) {
    asm volatile(
        "mma.sync.aligned.m16n8k16.row.col.f32.bf16.bf16.f32 "
        "{%0,%1,%2,%3}, {%4,%5,%6,%7}, {%8,%9}, {%0,%1,%2,%3};"
        : "+f"(c[0]), "+f"(c[1]), "+f"(c[2]), "+f"(c[3])
        : "r"(a[0]), "r"(a[1]), "r"(a[2]), "r"(a[3]), "r"(b[0]), "r"(b[1]));
}

DEV void split_store(float2* s, float v) {
    uint32_t hb; asm("cvt.rna.tf32.f32 %0, %1;" : "=r"(hb) : "f"(v));
    float hf = __uint_as_float(hb);
    float lo = v - hf;
    uint32_t lb; asm("cvt.rna.tf32.f32 %0, %1;" : "=r"(lb) : "f"(lo));
    s->x = hf; s->y = __uint_as_float(lb);
}
DEV uint32_t pack_bf16(float a, float b) {
    uint32_t r;
    asm("cvt.rn.bf16x2.f32 %0, %1, %2;" : "=r"(r) : "f"(b), "f"(a));
    return r;
}
DEV void split_bf(float v, float& hi, float& lo) {
    hi = __bfloat162float(__float2bfloat16(v));
    lo = v - hi;
}
DEV uint2 limb2(float a, float b) {
    float ha, la, hb, lb;
    split_bf(a, ha, la); split_bf(b, hb, lb);
    return make_uint2(pack_bf16(ha, hb), pack_bf16(la, lb));
}

// ---------------- async 3xTF32 GEMM (2-stage, 1 sync/chunk) ----------------
template<int BM, int BN, int WM, int WN, int MT, int NT>
DEV void gemm_async_tf32(const float2* __restrict__ A, int lda,
                         const float2* __restrict__ B, int ldb,
                         int K, char* smem, uint32_t su, float* acc)
{
    const int tid = threadIdx.x;
    const int lane = tid & 31, wid = tid >> 5;
    const int g = lane >> 2, tq = lane & 3;
    const int wm0 = (wid / WN) * (BM / WM);
    const int wn0 = (wid % WN) * (BN / WN);

    constexpr int SA = BM * PAD * 8;
    constexpr int STAGE = SA + BN * PAD * 8;

    auto copy_chunk = [&](int c, int s) {
        uint32_t base = su + s * STAGE;
#pragma unroll
        for (int t = 0; t < BM * 8 / 256; t++) {
            int idx = tid + t * 256; int r = idx >> 3, j = idx & 7;
            cp16(base + r * 160 + j * 16, A + (size_t)r * lda + c * 16 + j * 2);
        }
#pragma unroll
        for (int t = 0; t < BN * 8 / 256; t++) {
            int idx = tid + t * 256; int r = idx >> 3, j = idx & 7;
            cp16(base + SA + r * 160 + j * 16, B + (size_t)r * ldb + c * 16 + j * 2);
        }
        cp_commit();
    };
    auto compute = [&](int s) {
        const float2* Ab = (const float2*)(smem + s * STAGE);
        const float2* Bb = (const float2*)(smem + s * STAGE + SA);
#pragma unroll
        for (int ks = 0; ks < 2; ks++) {
            int kb = ks * 8;
            uint32_t bh[NT][2], bl[NT][2];
#pragma unroll
            for (int ni = 0; ni < NT; ni++) {
                int n0 = wn0 + ni * 8 + g;
                float2 w0 = Bb[n0 * PAD + kb + tq];
                float2 w1 = Bb[n0 * PAD + kb + tq + 4];
                bh[ni][0] = f2u(w0.x); bl[ni][0] = f2u(w0.y);
                bh[ni][1] = f2u(w1.x); bl[ni][1] = f2u(w1.y);
            }
#pragma unroll
            for (int mi = 0; mi < MT; mi++) {
                int r0 = wm0 + mi * 16 + g;
                float2 v0 = Ab[r0 * PAD + kb + tq];
                float2 v1 = Ab[(r0 + 8) * PAD + kb + tq];
                float2 v2 = Ab[r0 * PAD + kb + tq + 4];
                float2 v3 = Ab[(r0 + 8) * PAD + kb + tq + 4];
                uint32_t ah[4] = { f2u(v0.x), f2u(v1.x), f2u(v2.x), f2u(v3.x) };
                uint32_t al[4] = { f2u(v0.y), f2u(v1.y), f2u(v2.y), f2u(v3.y) };
#pragma unroll
                for (int ni = 0; ni < NT; ni++) {
                    float* c = acc + (mi * NT + ni) * 4;
                    mma_tf32(c, ah, bh[ni]);
                    mma_tf32(c, ah, bl[ni]);
                    mma_tf32(c, al, bh[ni]);
                }
            }
        }
    };

    int nc = K >> 4;
    copy_chunk(0, 0);
    for (int c = 0; c < nc; c++) {
        cp_wait<0>();
        __syncthreads();
        if (c + 1 < nc) copy_chunk(c + 1, (c + 1) & 1);
        compute(c & 1);
    }
}

// ---------------- async 2-limb bf16 x3 GEMM (proven) ----------------
template<int BM, int BN, int WM, int WN, int MT, int NT>
DEV void gemm_async_bf16(const uint2* __restrict__ A, int lda,
                         const uint2* __restrict__ B, int ldb,
                         int K, char* smem, uint32_t su, float* acc)
{
    const int tid = threadIdx.x;
    const int lane = tid & 31, wid = tid >> 5;
    const int g = lane >> 2, tq = lane & 3;
    const int wm0 = (wid / WN) * (BM / WM);
    const int wn0 = (wid % WN) * (BN / WN);

    constexpr int SA = BM * PADB * 8;
    constexpr int STAGE = SA + BN * PADB * 8;

    auto copy_chunk = [&](int c, int s) {
        uint32_t base = su + s * STAGE;
#pragma unroll
        for (int t = 0; t < BM * 4 / 256; t++) {
            int idx = tid + t * 256; int r = idx >> 2, j = idx & 3;
            cp16(base + r * 80 + j * 16, A + (size_t)r * lda + c * 8 + j * 2);
        }
#pragma unroll
        for (int t = 0; t < (BN * 4 + 255) / 256; t++) {
            int idx = tid + t * 256;
            if (BN * 4 % 256 == 0 || idx < BN * 4) {
                int r = idx >> 2, j = idx & 3;
                cp16(base + SA + r * 80 + j * 16, B + (size_t)r * ldb + c * 8 + j * 2);
            }
        }
        cp_commit();
    };
    auto compute = [&](int s) {
        const uint2* Ab = (const uint2*)(smem + s * STAGE);
        const uint2* Bb = (const uint2*)(smem + s * STAGE + SA);
        uint32_t bh[NT][2], bl[NT][2];
#pragma unroll
        for (int ni = 0; ni < NT; ni++) {
            int n0 = wn0 + ni * 8 + g;
            uint2 w0 = Bb[n0 * PADB + tq];
            uint2 w1 = Bb[n0 * PADB + tq + 4];
            bh[ni][0] = w0.x; bl[ni][0] = w0.y;
            bh[ni][1] = w1.x; bl[ni][1] = w1.y;
        }
#pragma unroll
        for (int mi = 0; mi < MT; mi++) {
            int r0 = wm0 + mi * 16 + g;
            uint2 v0 = Ab[r0 * PADB + tq];
            uint2 v1 = Ab[(r0 + 8) * PADB + tq];
            uint2 v2 = Ab[r0 * PADB + tq + 4];
            uint2 v3 = Ab[(r0 + 8) * PADB + tq + 4];
            uint32_t ah[4] = { v0.x, v1.x, v2.x, v3.x };
            uint32_t al[4] = { v0.y, v1.y, v2.y, v3.y };
#pragma unroll
            for (int ni = 0; ni < NT; ni++) {
                float* c = acc + (mi * NT + ni) * 4;
                mma_bf16(c, ah, bh[ni]);
                mma_bf16(c, ah, bl[ni]);
                mma_bf16(c, al, bh[ni]);
            }
        }
    };

    int nc = K >> 4;
    copy_chunk(0, 0);
    for (int c = 0; c < nc; c++) {
        cp_wait<0>();
        __syncthreads();
        if (c + 1 < nc) copy_chunk(c + 1, (c + 1) & 1);
        compute(c & 1);
    }
}

// epilogue iteration
template<int BM, int BN, int WM, int WN, int MT, int NT, typename F>
DEV void epilogue(const float* acc, F fn)
{
    int lane = threadIdx.x & 31, wid = threadIdx.x >> 5;
    int g = lane >> 2, tq = lane & 3;
    int wm0 = (wid / WN) * (BM / WM);
    int wn0 = (wid % WN) * (BN / WN);
#pragma unroll
    for (int mi = 0; mi < MT; mi++)
#pragma unroll
        for (int ni = 0; ni < NT; ni++)
#pragma unroll
            for (int cj = 0; cj < 4; cj++) {
                int row = wm0 + mi * 16 + g + ((cj >= 2) ? 8 : 0);
                int col = wn0 + ni * 8 + 2 * tq + (cj & 1);
                fn(row, col, acc[(mi * NT + ni) * 4 + cj]);
            }
}

// ---------------- prep kernels ----------------
__global__ __launch_bounds__(256) void x_split_kernel(const float* __restrict__ x)
{
    int idx = blockIdx.x * 256 + threadIdx.x;       // pair index, 2M total
    ((uint2*)g_xbf4)[idx] = limb2(x[2 * idx], x[2 * idx + 1]);
}

// per-token group sums: xg[t][g] = sum of 64 x values
__global__ __launch_bounds__(256) void xg_kernel(const float* __restrict__ x)
{
    int t = blockIdx.x;
    int tid = threadIdx.x;
    float4 v = ((const float4*)(x + (size_t)t * EMB))[tid];
    float p = v.x + v.y + v.z + v.w;
#pragma unroll
    for (int o = 8; o > 0; o >>= 1) p += __shfl_down_sync(0xffffffffu, p, o, 16);
    if ((tid & 15) == 0) g_xg[t * 16 + (tid >> 4)] = p;
}

// pack qw to (exact bf16 pair, zero lo-limb) uint2
__global__ __launch_bounds__(256) void pack_qwl_kernel(const int* __restrict__ qw, int mode)
{
    int idx = blockIdx.x * 256 + threadIdx.x;       // pair index, 512K total
    ((uint2*)g_wqkvl4[mode])[idx] =
        make_uint2(pack_bf16((float)qw[2 * idx], (float)qw[2 * idx + 1]), 0u);
}
__global__ __launch_bounds__(256) void pack_scale_kernel(
    const float* __restrict__ sc, const float* __restrict__ zr, int mode)
{
    int idx = blockIdx.x * 256 + threadIdx.x;       // 16384
    float s = sc[idx];
    g_s[mode][idx] = s;
    g_sz[mode][idx] = s * zr[idx];
}

__global__ __launch_bounds__(256) void dequant_o_kernel(
    const int* __restrict__ qw, const float* __restrict__ sc,
    const float* __restrict__ zr)
{
    int idx4 = (blockIdx.x * 256 + threadIdx.x) * 4;
    int o = idx4 >> 10, i = idx4 & 1023, grp = i >> 6;
    float s = sc[o * 16 + grp], z = zr[o * 16 + grp];
    uint2* dst = (uint2*)g_wo4 + (idx4 >> 1);
    dst[0] = limb2(((float)qw[idx4 + 0] - z) * s, ((float)qw[idx4 + 1] - z) * s);
    dst[1] = limb2(((float)qw[idx4 + 2] - z) * s, ((float)qw[idx4 + 3] - z) * s);
}

// ---------------- QKV projection: exact-integer via PROVEN bf16 GEMM ----------------
#define QKV_SMEM 33792
__global__ __launch_bounds__(256, 2) void proj_qkv_kernel(
    const float* __restrict__ bq, const float* __restrict__ bk,
    const float* __restrict__ bv)
{
    extern __shared__ char smem[];
    uint32_t su = smem_u32(smem);
    const int lane = threadIdx.x & 31, wid = threadIdx.x >> 5;
    const int g = lane >> 2, tq = lane & 3;
    const int wm0 = (wid / 2) * 32;             // WM=4
    const int wn0 = (wid % 2) * 32;             // WN=2

    int mode = blockIdx.z;
    int n0 = blockIdx.x * 64, m0 = blockIdx.y * 128;
    const float* bias = mode == 0 ? bq : (mode == 1 ? bk : bv);

    const uint2* A = (const uint2*)g_xbf4 + (size_t)m0 * 512;
    const uint2* B = (const uint2*)g_wqkvl4[mode] + (size_t)n0 * 512;
    const float* sarr = g_s[mode];
    const float* szarr = g_sz[mode];

    float master[32];
#pragma unroll
    for (int i = 0; i < 32; i++) master[i] = 0.f;

    for (int grp = 0; grp < 16; grp++) {
        float tmp[32];
#pragma unroll
        for (int i = 0; i < 32; i++) tmp[i] = 0.f;

        gemm_async_bf16<128, 64, 4, 2, 2, 4>(A + grp * 32, 512,
                                             B + grp * 32, 512, 64, smem, su, tmp);

        // fold: master += s[col][grp] * tmp
#pragma unroll
        for (int ni = 0; ni < 4; ni++) {
            int c0 = n0 + wn0 + ni * 8 + 2 * tq;
            float s0 = __ldg(&sarr[c0 * 16 + grp]);
            float s1 = __ldg(&sarr[(c0 + 1) * 16 + grp]);
#pragma unroll
            for (int mi = 0; mi < 2; mi++) {
                float* mm = master + (mi * 4 + ni) * 4;
                const float* tt = tmp + (mi * 4 + ni) * 4;
                mm[0] = fmaf(s0, tt[0], mm[0]);
                mm[1] = fmaf(s1, tt[1], mm[1]);
                mm[2] = fmaf(s0, tt[2], mm[2]);
                mm[3] = fmaf(s1, tt[3], mm[3]);
            }
        }
    }

    // zero correction: master[row,col] -= sum_g sz[col][g] * xg[row][g]
    for (int grp = 0; grp < 16; grp++) {
        float xr[2][2];
#pragma unroll
        for (int mi = 0; mi < 2; mi++) {
            int r0 = m0 + wm0 + mi * 16 + g;
            xr[mi][0] = __ldg(&g_xg[r0 * 16 + grp]);
            xr[mi][1] = __ldg(&g_xg[(r0 + 8) * 16 + grp]);
        }
#pragma unroll
        for (int ni = 0; ni < 4; ni++) {
            int c0 = n0 + wn0 + ni * 8 + 2 * tq;
            float z0 = __ldg(&szarr[c0 * 16 + grp]);
            float z1 = __ldg(&szarr[(c0 + 1) * 16 + grp]);
#pragma unroll
            for (int mi = 0; mi < 2; mi++) {
                float* mm = master + (mi * 4 + ni) * 4;
                mm[0] = fmaf(-z0, xr[mi][0], mm[0]);
                mm[1] = fmaf(-z1, xr[mi][0], mm[1]);
                mm[2] = fmaf(-z0, xr[mi][1], mm[2]);
                mm[3] = fmaf(-z1, xr[mi][1], mm[3]);
            }
        }
    }

    if (mode < 2) {
        float2* dst = mode == 0 ? (float2*)g_qs4 : (float2*)g_ks4;
        epilogue<128, 64, 4, 2, 2, 4>(master, [&](int row, int col, float val) {
            int token = m0 + row, o = n0 + col;
            int b = token >> 11, si = token & 2047;
            int h = o >> 6, d = o & 63;
            split_store(dst + ((size_t)(b * 16 + h) * S_LEN + si) * 64 + d, val + bias[o]);
        });
    } else {
        __syncthreads();                        // gemm stage buffers dead; reuse smem
        float* T = (float*)smem;                // [64 cols][132]
        int b = m0 >> 11, si0 = m0 & 2047;
        epilogue<128, 64, 4, 2, 2, 4>(master, [&](int row, int col, float val) {
            T[col * 132 + row] = val + bias[n0 + col];
        });
        __syncthreads();
        for (int i = threadIdx.x; i < 64 * 64; i += 256) {
            int cl = i >> 6, sp = i & 63;
            int o = n0 + cl; int h = o >> 6, d = o & 63;
            uint2 v = limb2(T[cl * 132 + 2 * sp], T[cl * 132 + 2 * sp + 1]);
            ((uint2*)g_vts4)[((size_t)(b * 16 + h) * 64 + d) * 1024 + ((si0 + 2 * sp) >> 1)] = v;
        }
    }
}

// ---------------- scores (3xTF32, proven) ----------------
#define SC_SMEM (2 * (128 + 128) * PAD * 8)
__global__ __launch_bounds__(256, 2) void scores_kernel(float* __restrict__ attn)
{
    extern __shared__ char smem[];
    uint32_t su = smem_u32(smem);
    int bh = blockIdx.z;
    int n0 = blockIdx.x * 128, m0 = blockIdx.y * 128;
    size_t base = (size_t)bh * S_LEN * 64;

    float acc[64];
#pragma unroll
    for (int i = 0; i < 64; i++) acc[i] = 0.f;

    gemm_async_tf32<128, 128, 2, 4, 4, 4>(
        (const float2*)g_qs4 + base + (size_t)m0 * 64, 64,
        (const float2*)g_ks4 + base + (size_t)n0 * 64, 64, 64, smem, su, acc);

    float* out = attn + (size_t)bh * S_LEN * S_LEN;
    epilogue<128, 128, 2, 4, 4, 4>(acc, [&](int row, int col, float val) {
        out[(size_t)(m0 + row) * S_LEN + n0 + col] = val * 0.125f;
    });
}

// ---------------- softmax (in place) + write bf16 limb P (proven) ----------------
__global__ __launch_bounds__(256) void softmax_kernel(float* __restrict__ S)
{
    size_t row = blockIdx.x;
    float4* p4 = (float4*)(S + row * S_LEN);
    int t = threadIdx.x;
    float4 u0 = p4[2 * t], u1 = p4[2 * t + 1];
    float v[8] = { u0.x, u0.y, u0.z, u0.w, u1.x, u1.y, u1.z, u1.w };
    float m = v[0];
#pragma unroll
    for (int i = 1; i < 8; i++) m = fmaxf(m, v[i]);
#pragma unroll
    for (int o = 16; o > 0; o >>= 1) m = fmaxf(m, __shfl_xor_sync(0xffffffffu, m, o));
    __shared__ float sred[8]; __shared__ float sbc;
    if ((t & 31) == 0) sred[t >> 5] = m;
    __syncthreads();
    if (t == 0) {
        float x = sred[0];
#pragma unroll
        for (int i = 1; i < 8; i++) x = fmaxf(x, sred[i]);
        sbc = x;
    }
    __syncthreads();
    m = sbc;
    float sum = 0.f;
#pragma unroll
    for (int i = 0; i < 8; i++) { v[i] = __expf(v[i] - m); sum += v[i]; }
#pragma unroll
    for (int o = 16; o > 0; o >>= 1) sum += __shfl_xor_sync(0xffffffffu, sum, o);
    __syncthreads();
    if ((t & 31) == 0) sred[t >> 5] = sum;
    __syncthreads();
    if (t == 0) {
        float x = 0.f;
#pragma unroll
        for (int i = 0; i < 8; i++) x += sred[i];
        sbc = 1.0f / x;
    }
    __syncthreads();
    float inv = sbc;
    float w[8];
#pragma unroll
    for (int i = 0; i < 8; i++) w[i] = v[i] * inv;
    p4[2 * t]     = make_float4(w[0], w[1], w[2], w[3]);
    p4[2 * t + 1] = make_float4(w[4], w[5], w[6], w[7]);
    uint2* lp = (uint2*)g_pps4 + row * 1024 + t * 4;
    lp[0] = limb2(w[0], w[1]); lp[1] = limb2(w[2], w[3]);
    lp[2] = limb2(w[4], w[5]); lp[3] = limb2(w[6], w[7]);
}

// ---------------- PV (proven) ----------------
#define PV_SMEM (2 * (128 + 64) * PADB * 8)
__global__ __launch_bounds__(256, 2) void pv_kernel()
{
    extern __shared__ char smem[];
    uint32_t su = smem_u32(smem);
    int bh = blockIdx.z;
    int m0 = blockIdx.y * 128;

    float acc[32];
#pragma unroll
    for (int i = 0; i < 32; i++) acc[i] = 0.f;

    gemm_async_bf16<128, 64, 4, 2, 2, 4>(
        (const uint2*)g_pps4 + ((size_t)bh * S_LEN + m0) * 1024, 1024,
        (const uint2*)g_vts4 + (size_t)bh * 64 * 1024, 1024, S_LEN, smem, su, acc);

    int b = bh >> 4, h = bh & 15;
    {
        int lane = threadIdx.x & 31, wid = threadIdx.x >> 5;
        int g = lane >> 2, tq = lane & 3;
        int wm0 = (wid / 2) * 32;
        int wn0 = (wid % 2) * 32;
#pragma unroll
        for (int mi = 0; mi < 2; mi++)
#pragma unroll
            for (int ni = 0; ni < 4; ni++) {
                const float* c = acc + (mi * 4 + ni) * 4;
                int col0 = wn0 + ni * 8 + 2 * tq;
                int r0 = wm0 + mi * 16 + g;
                size_t tok0 = (size_t)b * S_LEN + m0 + r0;
                ((uint2*)g_aos4)[tok0 * 512 + (h * 64 + col0) / 2] = limb2(c[0], c[1]);
                ((uint2*)g_aos4)[(tok0 + 8) * 512 + (h * 64 + col0) / 2] = limb2(c[2], c[3]);
            }
    }
}

// ---------------- O projection (proven) ----------------
#define OP_SMEM (2 * (128 + 128) * PADB * 8)
__global__ __launch_bounds__(256, 2) void oproj_kernel(
    const float* __restrict__ bias, float* __restrict__ out)
{
    extern __shared__ char smem[];
    uint32_t su = smem_u32(smem);
    int n0 = blockIdx.x * 128, m0 = blockIdx.y * 128;

    float acc[64];
#pragma unroll
    for (int i = 0; i < 64; i++) acc[i] = 0.f;

    gemm_async_bf16<128, 128, 2, 4, 4, 4>(
        (const uint2*)g_aos4 + (size_t)m0 * 512, 512,
        (const uint2*)g_wo4 + (size_t)n0 * 512, 512, EMB, smem, su, acc);

    epilogue<128, 128, 2, 4, 4, 4>(acc, [&](int row, int col, float val) {
        int token = m0 + row, o = n0 + col;
        out[(size_t)token * EMB + o] = val + bias[o];
    });
}

// ---------------- launch ----------------
extern "C" void kernel_launch(void* const* d_in, const int* in_sizes, int n_in,
                              void* d_out, int out_size)
{
    const float* x = (const float*)d_in[0];
    const int* qw[4];
    const float *sc[4], *zr[4], *bs[4];
    for (int p = 0; p < 4; p++) {
        qw[p] = (const int*)d_in[1 + 4 * p];
        sc[p] = (const float*)d_in[2 + 4 * p];
        zr[p] = (const float*)d_in[3 + 4 * p];
        bs[p] = (const float*)d_in[4 + 4 * p];
    }
    float* out = (float*)d_out;                 // [B,S,E]
    float* attn = out + (size_t)4194304;        // [B,H,S,S]

    cudaFuncSetAttribute(proj_qkv_kernel, cudaFuncAttributeMaxDynamicSharedMemorySize, QKV_SMEM);
    cudaFuncSetAttribute(scores_kernel,   cudaFuncAttributeMaxDynamicSharedMemorySize, SC_SMEM);
    cudaFuncSetAttribute(pv_kernel,       cudaFuncAttributeMaxDynamicSharedMemorySize, PV_SMEM);
    cudaFuncSetAttribute(oproj_kernel,    cudaFuncAttributeMaxDynamicSharedMemorySize, OP_SMEM);

    x_split_kernel<<<8192, 256>>>(x);
    xg_kernel<<<4096, 256>>>(x);
    for (int p = 0; p < 3; p++) {
        pack_qwl_kernel<<<2048, 256>>>(qw[p], p);
        pack_scale_kernel<<<64, 256>>>(sc[p], zr[p], p);
    }
    dequant_o_kernel<<<1024, 256>>>(qw[3], sc[3], zr[3]);

    proj_qkv_kernel<<<dim3(16, 32, 3), 256, QKV_SMEM>>>(bs[0], bs[1], bs[2]);
    scores_kernel<<<dim3(16, 16, 32), 256, SC_SMEM>>>(attn);
    softmax_kernel<<<65536, 256>>>(attn);
    pv_kernel<<<dim3(1, 16, 32), 256, PV_SMEM>>>();
    oproj_kernel<<<dim3(8, 32), 256, OP_SMEM>>>(bs[3], out);
}

// round 12
// speedup vs baseline: 2.7424x; 1.0290x over previous
#include <cuda_runtime.h>
#include <cuda_bf16.h>
#include <cstdint>
#include <cstddef>

#define DEV __device__ __forceinline__

#define S_LEN 2048
#define EMB   1024
#define PAD   20          // float2 per SMEM row (16 data + 4 pad) = 160 B
#define PADB  10          // uint2 per SMEM row (8 data + 2 pad)   = 80 B

// ---------------- scratch (16B-aligned) ----------------
__device__ uint4  g_xbf4[4096 * 1024 / 4];           // x bf16 limb pairs [t][e/2]
__device__ __align__(16) float g_xg[4096 * 16];      // group sums of x [t][g]
__device__ uint4  g_wqkvl4[3][1024 * 1024 / 4];      // qw as (bf16 pair, 0) limb uint2 [o][e/2]
__device__ __align__(16) float g_s[3][1024 * 16];    // scales [o][g]
__device__ __align__(16) float g_sz[3][1024 * 16];   // scale*zero [o][g]
__device__ uint4  g_wo4[1024 * 1024 / 4];            // o weights bf16 limb pairs
__device__ float4 g_qs4[32 * 2048 * 64 / 2];         // q tf32 pairs [bh][s][d]
__device__ float4 g_ks4[32 * 2048 * 64 / 2];
__device__ uint4  g_vts4[32 * 64 * 2048 / 4];        // v^T bf16 limbs [bh][d][s/2]
__device__ uint4  g_pps4[(size_t)32 * 2048 * 2048 / 4];  // P bf16 limbs [bh*s][t/2]
__device__ uint4  g_aos4[4096 * 1024 / 4];           // attn-out bf16 limbs [tok][e/2]

DEV uint32_t f2u(float f) { return __float_as_uint(f); }

DEV uint32_t smem_u32(const void* p) {
    uint32_t a;
    asm("{ .reg .u64 t; cvta.to.shared.u64 t, %1; cvt.u32.u64 %0, t; }" : "=r"(a) : "l"(p));
    return a;
}
DEV void cp16(uint32_t dst, const void* src) {
    asm volatile("cp.async.cg.shared.global [%0], [%1], 16;" :: "r"(dst), "l"(src));
}
DEV void cp_commit() { asm volatile("cp.async.commit_group;" ::: "memory"); }
template<int N> DEV void cp_wait() { asm volatile("cp.async.wait_group %0;" :: "n"(N) : "memory"); }

DEV void mma_tf32(float* c, const uint32_t* a, const uint32_t* b) {
    asm volatile(
        "mma.sync.aligned.m16n8k8.row.col.f32.tf32.tf32.f32 "
        "{%0,%1,%2,%3}, {%4,%5,%6,%7}, {%8,%9}, {%0,%1,%2,%3};"
        : "+f"(c[0]), "+f"(c[1]), "+f"(c[2]), "+f"(c[3])
        : "r"(a[0]), "r"(a[1]), "r"(a[2]), "r"(a[3]), "r"(b[0]), "r"(b[1]));
}
DEV void mma_bf16(float* c, const uint32_t* a, const uint32_t* b) {
    asm volatile(
        "mma.sync.aligned.m16n8k16.row.col.f32.bf16.bf16.f32 "
        "{%0,%1,%2,%3}, {%4,%5,%6,%7}, {%8,%9}, {%0,%1,%2,%3};"
        : "+f"(c[0]), "+f"(c[1]), "+f"(c[2]), "+f"(c[3])
        : "r"(a[0]), "r"(a[1]), "r"(a[2]), "r"(a[3]), "r"(b[0]), "r"(b[1]));
}

DEV void split_store(float2* s, float v) {
    uint32_t hb; asm("cvt.rna.tf32.f32 %0, %1;" : "=r"(hb) : "f"(v));
    float hf = __uint_as_float(hb);
    float lo = v - hf;
    uint32_t lb; asm("cvt.rna.tf32.f32 %0, %1;" : "=r"(lb) : "f"(lo));
    s->x = hf; s->y = __uint_as_float(lb);
}
DEV uint32_t pack_bf16(float a, float b) {
    uint32_t r;
    asm("cvt.rn.bf16x2.f32 %0, %1, %2;" : "=r"(r) : "f"(b), "f"(a));
    return r;
}
DEV void split_bf(float v, float& hi, float& lo) {
    hi = __bfloat162float(__float2bfloat16(v));
    lo = v - hi;
}
DEV uint2 limb2(float a, float b) {
    float ha, la, hb, lb;
    split_bf(a, ha, la); split_bf(b, hb, lb);
    return make_uint2(pack_bf16(ha, hb), pack_bf16(la, lb));
}

// ---------------- async 3xTF32 GEMM (2-stage, 1 sync/chunk) ----------------
template<int BM, int BN, int WM, int WN, int MT, int NT>
DEV void gemm_async_tf32(const float2* __restrict__ A, int lda,
                         const float2* __restrict__ B, int ldb,
                         int K, char* smem, uint32_t su, float* acc)
{
    const int tid = threadIdx.x;
    const int lane = tid & 31, wid = tid >> 5;
    const int g = lane >> 2, tq = lane & 3;
    const int wm0 = (wid / WN) * (BM / WM);
    const int wn0 = (wid % WN) * (BN / WN);

    constexpr int SA = BM * PAD * 8;
    constexpr int STAGE = SA + BN * PAD * 8;

    auto copy_chunk = [&](int c, int s) {
        uint32_t base = su + s * STAGE;
#pragma unroll
        for (int t = 0; t < BM * 8 / 256; t++) {
            int idx = tid + t * 256; int r = idx >> 3, j = idx & 7;
            cp16(base + r * 160 + j * 16, A + (size_t)r * lda + c * 16 + j * 2);
        }
#pragma unroll
        for (int t = 0; t < BN * 8 / 256; t++) {
            int idx = tid + t * 256; int r = idx >> 3, j = idx & 7;
            cp16(base + SA + r * 160 + j * 16, B + (size_t)r * ldb + c * 16 + j * 2);
        }
        cp_commit();
    };
    auto compute = [&](int s) {
        const float2* Ab = (const float2*)(smem + s * STAGE);
        const float2* Bb = (const float2*)(smem + s * STAGE + SA);
#pragma unroll
        for (int ks = 0; ks < 2; ks++) {
            int kb = ks * 8;
            uint32_t bh[NT][2], bl[NT][2];
#pragma unroll
            for (int ni = 0; ni < NT; ni++) {
                int n0 = wn0 + ni * 8 + g;
                float2 w0 = Bb[n0 * PAD + kb + tq];
                float2 w1 = Bb[n0 * PAD + kb + tq + 4];
                bh[ni][0] = f2u(w0.x); bl[ni][0] = f2u(w0.y);
                bh[ni][1] = f2u(w1.x); bl[ni][1] = f2u(w1.y);
            }
#pragma unroll
            for (int mi = 0; mi < MT; mi++) {
                int r0 = wm0 + mi * 16 + g;
                float2 v0 = Ab[r0 * PAD + kb + tq];
                float2 v1 = Ab[(r0 + 8) * PAD + kb + tq];
                float2 v2 = Ab[r0 * PAD + kb + tq + 4];
                float2 v3 = Ab[(r0 + 8) * PAD + kb + tq + 4];
                uint32_t ah[4] = { f2u(v0.x), f2u(v1.x), f2u(v2.x), f2u(v3.x) };
                uint32_t al[4] = { f2u(v0.y), f2u(v1.y), f2u(v2.y), f2u(v3.y) };
#pragma unroll
                for (int ni = 0; ni < NT; ni++) {
                    float* c = acc + (mi * NT + ni) * 4;
                    mma_tf32(c, ah, bh[ni]);
                    mma_tf32(c, ah, bl[ni]);
                    mma_tf32(c, al, bh[ni]);
                }
            }
        }
    };

    int nc = K >> 4;
    copy_chunk(0, 0);
    for (int c = 0; c < nc; c++) {
        cp_wait<0>();
        __syncthreads();
        if (c + 1 < nc) copy_chunk(c + 1, (c + 1) & 1);
        compute(c & 1);
    }
}

// ---------------- async 2-limb bf16 x3 GEMM (proven) ----------------
template<int BM, int BN, int WM, int WN, int MT, int NT>
DEV void gemm_async_bf16(const uint2* __restrict__ A, int lda,
                         const uint2* __restrict__ B, int ldb,
                         int K, char* smem, uint32_t su, float* acc)
{
    const int tid = threadIdx.x;
    const int lane = tid & 31, wid = tid >> 5;
    const int g = lane >> 2, tq = lane & 3;
    const int wm0 = (wid / WN) * (BM / WM);
    const int wn0 = (wid % WN) * (BN / WN);

    constexpr int SA = BM * PADB * 8;
    constexpr int STAGE = SA + BN * PADB * 8;

    auto copy_chunk = [&](int c, int s) {
        uint32_t base = su + s * STAGE;
#pragma unroll
        for (int t = 0; t < BM * 4 / 256; t++) {
            int idx = tid + t * 256; int r = idx >> 2, j = idx & 3;
            cp16(base + r * 80 + j * 16, A + (size_t)r * lda + c * 8 + j * 2);
        }
#pragma unroll
        for (int t = 0; t < (BN * 4 + 255) / 256; t++) {
            int idx = tid + t * 256;
            if (BN * 4 % 256 == 0 || idx < BN * 4) {
                int r = idx >> 2, j = idx & 3;
                cp16(base + SA + r * 80 + j * 16, B + (size_t)r * ldb + c * 8 + j * 2);
            }
        }
        cp_commit();
    };
    auto compute = [&](int s) {
        const uint2* Ab = (const uint2*)(smem + s * STAGE);
        const uint2* Bb = (const uint2*)(smem + s * STAGE + SA);
        uint32_t bh[NT][2], bl[NT][2];
#pragma unroll
        for (int ni = 0; ni < NT; ni++) {
            int n0 = wn0 + ni * 8 + g;
            uint2 w0 = Bb[n0 * PADB + tq];
            uint2 w1 = Bb[n0 * PADB + tq + 4];
            bh[ni][0] = w0.x; bl[ni][0] = w0.y;
            bh[ni][1] = w1.x; bl[ni][1] = w1.y;
        }
#pragma unroll
        for (int mi = 0; mi < MT; mi++) {
            int r0 = wm0 + mi * 16 + g;
            uint2 v0 = Ab[r0 * PADB + tq];
            uint2 v1 = Ab[(r0 + 8) * PADB + tq];
            uint2 v2 = Ab[r0 * PADB + tq + 4];
            uint2 v3 = Ab[(r0 + 8) * PADB + tq + 4];
            uint32_t ah[4] = { v0.x, v1.x, v2.x, v3.x };
            uint32_t al[4] = { v0.y, v1.y, v2.y, v3.y };
#pragma unroll
            for (int ni = 0; ni < NT; ni++) {
                float* c = acc + (mi * NT + ni) * 4;
                mma_bf16(c, ah, bh[ni]);
                mma_bf16(c, ah, bl[ni]);
                mma_bf16(c, al, bh[ni]);
            }
        }
    };

    int nc = K >> 4;
    copy_chunk(0, 0);
    for (int c = 0; c < nc; c++) {
        cp_wait<0>();
        __syncthreads();
        if (c + 1 < nc) copy_chunk(c + 1, (c + 1) & 1);
        compute(c & 1);
    }
}

// epilogue iteration
template<int BM, int BN, int WM, int WN, int MT, int NT, typename F>
DEV void epilogue(const float* acc, F fn)
{
    int lane = threadIdx.x & 31, wid = threadIdx.x >> 5;
    int g = lane >> 2, tq = lane & 3;
    int wm0 = (wid / WN) * (BM / WM);
    int wn0 = (wid % WN) * (BN / WN);
#pragma unroll
    for (int mi = 0; mi < MT; mi++)
#pragma unroll
        for (int ni = 0; ni < NT; ni++)
#pragma unroll
            for (int cj = 0; cj < 4; cj++) {
                int row = wm0 + mi * 16 + g + ((cj >= 2) ? 8 : 0);
                int col = wn0 + ni * 8 + 2 * tq + (cj & 1);
                fn(row, col, acc[(mi * NT + ni) * 4 + cj]);
            }
}

// ---------------- prep kernels ----------------
__global__ __launch_bounds__(256) void x_split_kernel(const float* __restrict__ x)
{
    int idx = blockIdx.x * 256 + threadIdx.x;       // pair index, 2M total
    ((uint2*)g_xbf4)[idx] = limb2(x[2 * idx], x[2 * idx + 1]);
}

__global__ __launch_bounds__(256) void xg_kernel(const float* __restrict__ x)
{
    int t = blockIdx.x;
    int tid = threadIdx.x;
    float4 v = ((const float4*)(x + (size_t)t * EMB))[tid];
    float p = v.x + v.y + v.z + v.w;
#pragma unroll
    for (int o = 8; o > 0; o >>= 1) p += __shfl_down_sync(0xffffffffu, p, o, 16);
    if ((tid & 15) == 0) g_xg[t * 16 + (tid >> 4)] = p;
}

__global__ __launch_bounds__(256) void pack_qwl_kernel(const int* __restrict__ qw, int mode)
{
    int idx = blockIdx.x * 256 + threadIdx.x;       // pair index, 512K total
    ((uint2*)g_wqkvl4[mode])[idx] =
        make_uint2(pack_bf16((float)qw[2 * idx], (float)qw[2 * idx + 1]), 0u);
}
__global__ __launch_bounds__(256) void pack_scale_kernel(
    const float* __restrict__ sc, const float* __restrict__ zr, int mode)
{
    int idx = blockIdx.x * 256 + threadIdx.x;       // 16384
    float s = sc[idx];
    g_s[mode][idx] = s;
    g_sz[mode][idx] = s * zr[idx];
}

__global__ __launch_bounds__(256) void dequant_o_kernel(
    const int* __restrict__ qw, const float* __restrict__ sc,
    const float* __restrict__ zr)
{
    int idx4 = (blockIdx.x * 256 + threadIdx.x) * 4;
    int o = idx4 >> 10, i = idx4 & 1023, grp = i >> 6;
    float s = sc[o * 16 + grp], z = zr[o * 16 + grp];
    uint2* dst = (uint2*)g_wo4 + (idx4 >> 1);
    dst[0] = limb2(((float)qw[idx4 + 0] - z) * s, ((float)qw[idx4 + 1] - z) * s);
    dst[1] = limb2(((float)qw[idx4 + 2] - z) * s, ((float)qw[idx4 + 3] - z) * s);
}

// ---------------- QKV projection: continuous 64-chunk pipeline, 2 products ----------------
// BM=128, BN=64, WM=4, WN=2, MT=2, NT=4 (proven layout). Fold every 4 chunks.
#define QKV_SMEM 33792
__global__ __launch_bounds__(256, 2) void proj_qkv_kernel(
    const float* __restrict__ bq, const float* __restrict__ bk,
    const float* __restrict__ bv)
{
    extern __shared__ char smem[];
    uint32_t su = smem_u32(smem);
    const int tid = threadIdx.x;
    const int lane = tid & 31, wid = tid >> 5;
    const int g = lane >> 2, tq = lane & 3;
    const int wm0 = (wid / 2) * 32;             // WM=4
    const int wn0 = (wid % 2) * 32;             // WN=2

    int mode = blockIdx.z;
    int n0 = blockIdx.x * 64, m0 = blockIdx.y * 128;
    const float* bias = mode == 0 ? bq : (mode == 1 ? bk : bv);

    const uint2* A = (const uint2*)g_xbf4 + (size_t)m0 * 512;
    const uint2* B = (const uint2*)g_wqkvl4[mode] + (size_t)n0 * 512;
    const float* sarr = g_s[mode];
    const float* szarr = g_sz[mode];

    constexpr int SA = 128 * PADB * 8;          // 10240
    constexpr int STAGE = SA + 64 * PADB * 8;   // 15360

    auto copy_chunk = [&](int c, int s) {
        uint32_t base = su + s * STAGE;
#pragma unroll
        for (int t = 0; t < 2; t++) {           // A: 128 rows
            int idx = tid + t * 256; int r = idx >> 2, j = idx & 3;
            cp16(base + r * 80 + j * 16, A + (size_t)r * 512 + c * 8 + j * 2);
        }
        {                                        // B: 64 rows (exactly 256 chunks)
            int r = tid >> 2, j = tid & 3;
            cp16(base + SA + r * 80 + j * 16, B + (size_t)r * 512 + c * 8 + j * 2);
        }
        cp_commit();
    };

    float master[32], tmp[32];
#pragma unroll
    for (int i = 0; i < 32; i++) { master[i] = 0.f; tmp[i] = 0.f; }

    copy_chunk(0, 0);
    for (int c = 0; c < 64; c++) {
        cp_wait<0>();
        __syncthreads();
        if (c + 1 < 64) copy_chunk(c + 1, (c + 1) & 1);
        // compute (2 products: B lo-limb is zero)
        {
            const uint2* Ab = (const uint2*)(smem + (c & 1) * STAGE);
            const uint2* Bb = (const uint2*)(smem + (c & 1) * STAGE + SA);
            uint32_t bh[4][2];
#pragma unroll
            for (int ni = 0; ni < 4; ni++) {
                int n = wn0 + ni * 8 + g;
                uint2 w0 = Bb[n * PADB + tq];
                uint2 w1 = Bb[n * PADB + tq + 4];
                bh[ni][0] = w0.x;
                bh[ni][1] = w1.x;
            }
#pragma unroll
            for (int mi = 0; mi < 2; mi++) {
                int r0 = wm0 + mi * 16 + g;
                uint2 v0 = Ab[r0 * PADB + tq];
                uint2 v1 = Ab[(r0 + 8) * PADB + tq];
                uint2 v2 = Ab[r0 * PADB + tq + 4];
                uint2 v3 = Ab[(r0 + 8) * PADB + tq + 4];
                uint32_t ah[4] = { v0.x, v1.x, v2.x, v3.x };
                uint32_t al[4] = { v0.y, v1.y, v2.y, v3.y };
#pragma unroll
                for (int ni = 0; ni < 4; ni++) {
                    float* cc = tmp + (mi * 4 + ni) * 4;
                    mma_bf16(cc, ah, bh[ni]);
                    mma_bf16(cc, al, bh[ni]);
                }
            }
        }
        // fold every 4 chunks (group boundary)
        if ((c & 3) == 3) {
            int grp = c >> 2;
#pragma unroll
            for (int ni = 0; ni < 4; ni++) {
                int c0 = n0 + wn0 + ni * 8 + 2 * tq;
                float s0 = __ldg(&sarr[c0 * 16 + grp]);
                float s1 = __ldg(&sarr[(c0 + 1) * 16 + grp]);
#pragma unroll
                for (int mi = 0; mi < 2; mi++) {
                    float* mm = master + (mi * 4 + ni) * 4;
                    float* tt = tmp + (mi * 4 + ni) * 4;
                    mm[0] = fmaf(s0, tt[0], mm[0]);
                    mm[1] = fmaf(s1, tt[1], mm[1]);
                    mm[2] = fmaf(s0, tt[2], mm[2]);
                    mm[3] = fmaf(s1, tt[3], mm[3]);
                    tt[0] = 0.f; tt[1] = 0.f; tt[2] = 0.f; tt[3] = 0.f;
                }
            }
        }
    }

    // zero correction: master[row,col] -= sum_g sz[col][g] * xg[row][g]
    for (int grp = 0; grp < 16; grp++) {
        float xr[2][2];
#pragma unroll
        for (int mi = 0; mi < 2; mi++) {
            int r0 = m0 + wm0 + mi * 16 + g;
            xr[mi][0] = __ldg(&g_xg[r0 * 16 + grp]);
            xr[mi][1] = __ldg(&g_xg[(r0 + 8) * 16 + grp]);
        }
#pragma unroll
        for (int ni = 0; ni < 4; ni++) {
            int c0 = n0 + wn0 + ni * 8 + 2 * tq;
            float z0 = __ldg(&szarr[c0 * 16 + grp]);
            float z1 = __ldg(&szarr[(c0 + 1) * 16 + grp]);
#pragma unroll
            for (int mi = 0; mi < 2; mi++) {
                float* mm = master + (mi * 4 + ni) * 4;
                mm[0] = fmaf(-z0, xr[mi][0], mm[0]);
                mm[1] = fmaf(-z1, xr[mi][0], mm[1]);
                mm[2] = fmaf(-z0, xr[mi][1], mm[2]);
                mm[3] = fmaf(-z1, xr[mi][1], mm[3]);
            }
        }
    }

    if (mode < 2) {
        float2* dst = mode == 0 ? (float2*)g_qs4 : (float2*)g_ks4;
        epilogue<128, 64, 4, 2, 2, 4>(master, [&](int row, int col, float val) {
            int token = m0 + row, o = n0 + col;
            int b = token >> 11, si = token & 2047;
            int h = o >> 6, d = o & 63;
            split_store(dst + ((size_t)(b * 16 + h) * S_LEN + si) * 64 + d, val + bias[o]);
        });
    } else {
        __syncthreads();
        float* T = (float*)smem;                // [64 cols][132]
        int b = m0 >> 11, si0 = m0 & 2047;
        epilogue<128, 64, 4, 2, 2, 4>(master, [&](int row, int col, float val) {
            T[col * 132 + row] = val + bias[n0 + col];
        });
        __syncthreads();
        for (int i = threadIdx.x; i < 64 * 64; i += 256) {
            int cl = i >> 6, sp = i & 63;
            int o = n0 + cl; int h = o >> 6, d = o & 63;
            uint2 v = limb2(T[cl * 132 + 2 * sp], T[cl * 132 + 2 * sp + 1]);
            ((uint2*)g_vts4)[((size_t)(b * 16 + h) * 64 + d) * 1024 + ((si0 + 2 * sp) >> 1)] = v;
        }
    }
}

// ---------------- scores (3xTF32, proven) ----------------
#define SC_SMEM (2 * (128 + 128) * PAD * 8)
__global__ __launch_bounds__(256, 2) void scores_kernel(float* __restrict__ attn)
{
    extern __shared__ char smem[];
    uint32_t su = smem_u32(smem);
    int bh = blockIdx.z;
    int n0 = blockIdx.x * 128, m0 = blockIdx.y * 128;
    size_t base = (size_t)bh * S_LEN * 64;

    float acc[64];
#pragma unroll
    for (int i = 0; i < 64; i++) acc[i] = 0.f;

    gemm_async_tf32<128, 128, 2, 4, 4, 4>(
        (const float2*)g_qs4 + base + (size_t)m0 * 64, 64,
        (const float2*)g_ks4 + base + (size_t)n0 * 64, 64, 64, smem, su, acc);

    float* out = attn + (size_t)bh * S_LEN * S_LEN;
    epilogue<128, 128, 2, 4, 4, 4>(acc, [&](int row, int col, float val) {
        out[(size_t)(m0 + row) * S_LEN + n0 + col] = val * 0.125f;
    });
}

// ---------------- softmax (in place) + write bf16 limb P (proven) ----------------
__global__ __launch_bounds__(256) void softmax_kernel(float* __restrict__ S)
{
    size_t row = blockIdx.x;
    float4* p4 = (float4*)(S + row * S_LEN);
    int t = threadIdx.x;
    float4 u0 = p4[2 * t], u1 = p4[2 * t + 1];
    float v[8] = { u0.x, u0.y, u0.z, u0.w, u1.x, u1.y, u1.z, u1.w };
    float m = v[0];
#pragma unroll
    for (int i = 1; i < 8; i++) m = fmaxf(m, v[i]);
#pragma unroll
    for (int o = 16; o > 0; o >>= 1) m = fmaxf(m, __shfl_xor_sync(0xffffffffu, m, o));
    __shared__ float sred[8]; __shared__ float sbc;
    if ((t & 31) == 0) sred[t >> 5] = m;
    __syncthreads();
    if (t == 0) {
        float x = sred[0];
#pragma unroll
        for (int i = 1; i < 8; i++) x = fmaxf(x, sred[i]);
        sbc = x;
    }
    __syncthreads();
    m = sbc;
    float sum = 0.f;
#pragma unroll
    for (int i = 0; i < 8; i++) { v[i] = __expf(v[i] - m); sum += v[i]; }
#pragma unroll
    for (int o = 16; o > 0; o >>= 1) sum += __shfl_xor_sync(0xffffffffu, sum, o);
    __syncthreads();
    if ((t & 31) == 0) sred[t >> 5] = sum;
    __syncthreads();
    if (t == 0) {
        float x = 0.f;
#pragma unroll
        for (int i = 0; i < 8; i++) x += sred[i];
        sbc = 1.0f / x;
    }
    __syncthreads();
    float inv = sbc;
    float w[8];
#pragma unroll
    for (int i = 0; i < 8; i++) w[i] = v[i] * inv;
    p4[2 * t]     = make_float4(w[0], w[1], w[2], w[3]);
    p4[2 * t + 1] = make_float4(w[4], w[5], w[6], w[7]);
    uint2* lp = (uint2*)g_pps4 + row * 1024 + t * 4;
    lp[0] = limb2(w[0], w[1]); lp[1] = limb2(w[2], w[3]);
    lp[2] = limb2(w[4], w[5]); lp[3] = limb2(w[6], w[7]);
}

// ---------------- PV (proven) ----------------
#define PV_SMEM (2 * (128 + 64) * PADB * 8)
__global__ __launch_bounds__(256, 2) void pv_kernel()
{
    extern __shared__ char smem[];
    uint32_t su = smem_u32(smem);
    int bh = blockIdx.z;
    int m0 = blockIdx.y * 128;

    float acc[32];
#pragma unroll
    for (int i = 0; i < 32; i++) acc[i] = 0.f;

    gemm_async_bf16<128, 64, 4, 2, 2, 4>(
        (const uint2*)g_pps4 + ((size_t)bh * S_LEN + m0) * 1024, 1024,
        (const uint2*)g_vts4 + (size_t)bh * 64 * 1024, 1024, S_LEN, smem, su, acc);

    int b = bh >> 4, h = bh & 15;
    {
        int lane = threadIdx.x & 31, wid = threadIdx.x >> 5;
        int g = lane >> 2, tq = lane & 3;
        int wm0 = (wid / 2) * 32;
        int wn0 = (wid % 2) * 32;
#pragma unroll
        for (int mi = 0; mi < 2; mi++)
#pragma unroll
            for (int ni = 0; ni < 4; ni++) {
                const float* c = acc + (mi * 4 + ni) * 4;
                int col0 = wn0 + ni * 8 + 2 * tq;
                int r0 = wm0 + mi * 16 + g;
                size_t tok0 = (size_t)b * S_LEN + m0 + r0;
                ((uint2*)g_aos4)[tok0 * 512 + (h * 64 + col0) / 2] = limb2(c[0], c[1]);
                ((uint2*)g_aos4)[(tok0 + 8) * 512 + (h * 64 + col0) / 2] = limb2(c[2], c[3]);
            }
    }
}

// ---------------- O projection (proven) ----------------
#define OP_SMEM (2 * (128 + 128) * PADB * 8)
__global__ __launch_bounds__(256, 2) void oproj_kernel(
    const float* __restrict__ bias, float* __restrict__ out)
{
    extern __shared__ char smem[];
    uint32_t su = smem_u32(smem);
    int n0 = blockIdx.x * 128, m0 = blockIdx.y * 128;

    float acc[64];
#pragma unroll
    for (int i = 0; i < 64; i++) acc[i] = 0.f;

    gemm_async_bf16<128, 128, 2, 4, 4, 4>(
        (const uint2*)g_aos4 + (size_t)m0 * 512, 512,
        (const uint2*)g_wo4 + (size_t)n0 * 512, 512, EMB, smem, su, acc);

    epilogue<128, 128, 2, 4, 4, 4>(acc, [&](int row, int col, float val) {
        int token = m0 + row, o = n0 + col;
        out[(size_t)token * EMB + o] = val + bias[o];
    });
}

// ---------------- launch ----------------
extern "C" void kernel_launch(void* const* d_in, const int* in_sizes, int n_in,
                              void* d_out, int out_size)
{
    const float* x = (const float*)d_in[0];
    const int* qw[4];
    const float *sc[4], *zr[4], *bs[4];
    for (int p = 0; p < 4; p++) {
        qw[p] = (const int*)d_in[1 + 4 * p];
        sc[p] = (const float*)d_in[2 + 4 * p];
        zr[p] = (const float*)d_in[3 + 4 * p];
        bs[p] = (const float*)d_in[4 + 4 * p];
    }
    float* out = (float*)d_out;                 // [B,S,E]
    float* attn = out + (size_t)4194304;        // [B,H,S,S]

    cudaFuncSetAttribute(proj_qkv_kernel, cudaFuncAttributeMaxDynamicSharedMemorySize, QKV_SMEM);
    cudaFuncSetAttribute(scores_kernel,   cudaFuncAttributeMaxDynamicSharedMemorySize, SC_SMEM);
    cudaFuncSetAttribute(pv_kernel,       cudaFuncAttributeMaxDynamicSharedMemorySize, PV_SMEM);
    cudaFuncSetAttribute(oproj_kernel,    cudaFuncAttributeMaxDynamicSharedMemorySize, OP_SMEM);

    x_split_kernel<<<8192, 256>>>(x);
    xg_kernel<<<4096, 256>>>(x);
    for (int p = 0; p < 3; p++) {
        pack_qwl_kernel<<<2048, 256>>>(qw[p], p);
        pack_scale_kernel<<<64, 256>>>(sc[p], zr[p], p);
    }
    dequant_o_kernel<<<1024, 256>>>(qw[3], sc[3], zr[3]);

    proj_qkv_kernel<<<dim3(16, 32, 3), 256, QKV_SMEM>>>(bs[0], bs[1], bs[2]);
    scores_kernel<<<dim3(16, 16, 32), 256, SC_SMEM>>>(attn);
    softmax_kernel<<<65536, 256>>>(attn);
    pv_kernel<<<dim3(1, 16, 32), 256, PV_SMEM>>>();
    oproj_kernel<<<dim3(8, 32), 256, OP_SMEM>>>(bs[3], out);
}

// round 13
// speedup vs baseline: 3.0509x; 1.1125x over previous
#include <cuda_runtime.h>
#include <cuda_bf16.h>
#include <cuda_fp16.h>
#include <cstdint>
#include <cstddef>

#define DEV __device__ __forceinline__

#define S_LEN 2048
#define EMB   1024
#define PADB  10          // uint2 per SMEM row (8 data + 2 pad)   = 80 B

// ---------------- scratch (16B-aligned) ----------------
__device__ uint4  g_xbf4[4096 * 1024 / 4];           // x bf16 limb pairs [t][e/2]
__device__ __align__(16) float g_xg[4096 * 16];      // group sums of x [t][g]
__device__ uint4  g_wqkvl4[3][1024 * 1024 / 4];      // qw as (bf16 pair, 0) limb uint2 [o][e/2]
__device__ __align__(16) float g_s[3][1024 * 16];    // scales [o][g]
__device__ __align__(16) float g_sz[3][1024 * 16];   // scale*zero [o][g]
__device__ uint4  g_wo4[1024 * 1024 / 4];            // o weights bf16 limb pairs
__device__ uint4  g_qh4[32 * 2048 * 64 / 4];         // q fp16 limb pairs [bh][s][d/2]
__device__ uint4  g_kh4[32 * 2048 * 64 / 4];         // k fp16 limb pairs
__device__ uint4  g_vts4[32 * 64 * 2048 / 4];        // v^T bf16 limbs [bh][d][s/2]
__device__ uint4  g_pps4[(size_t)32 * 2048 * 2048 / 4];  // P bf16 limbs [bh*s][t/2]
__device__ uint4  g_aos4[4096 * 1024 / 4];           // attn-out bf16 limbs [tok][e/2]

DEV uint32_t smem_u32(const void* p) {
    uint32_t a;
    asm("{ .reg .u64 t; cvta.to.shared.u64 t, %1; cvt.u32.u64 %0, t; }" : "=r"(a) : "l"(p));
    return a;
}
DEV void cp16(uint32_t dst, const void* src) {
    asm volatile("cp.async.cg.shared.global [%0], [%1], 16;" :: "r"(dst), "l"(src));
}
DEV void cp_commit() { asm volatile("cp.async.commit_group;" ::: "memory"); }
template<int N> DEV void cp_wait() { asm volatile("cp.async.wait_group %0;" :: "n"(N) : "memory"); }

DEV void mma_bf16(float* c, const uint32_t* a, const uint32_t* b) {
    asm volatile(
        "mma.sync.aligned.m16n8k16.row.col.f32.bf16.bf16.f32 "
        "{%0,%1,%2,%3}, {%4,%5,%6,%7}, {%8,%9}, {%0,%1,%2,%3};"
        : "+f"(c[0]), "+f"(c[1]), "+f"(c[2]), "+f"(c[3])
        : "r"(a[0]), "r"(a[1]), "r"(a[2]), "r"(a[3]), "r"(b[0]), "r"(b[1]));
}
DEV void mma_fp16(float* c, const uint32_t* a, const uint32_t* b) {
    asm volatile(
        "mma.sync.aligned.m16n8k16.row.col.f32.f16.f16.f32 "
        "{%0,%1,%2,%3}, {%4,%5,%6,%7}, {%8,%9}, {%0,%1,%2,%3};"
        : "+f"(c[0]), "+f"(c[1]), "+f"(c[2]), "+f"(c[3])
        : "r"(a[0]), "r"(a[1]), "r"(a[2]), "r"(a[3]), "r"(b[0]), "r"(b[1]));
}

DEV uint32_t pack_bf16(float a, float b) {
    uint32_t r;
    asm("cvt.rn.bf16x2.f32 %0, %1, %2;" : "=r"(r) : "f"(b), "f"(a));
    return r;
}
DEV void split_bf(float v, float& hi, float& lo) {
    hi = __bfloat162float(__float2bfloat16(v));
    lo = v - hi;
}
DEV uint2 limb2(float a, float b) {
    float ha, la, hb, lb;
    split_bf(a, ha, la); split_bf(b, hb, lb);
    return make_uint2(pack_bf16(ha, hb), pack_bf16(la, lb));
}

DEV uint32_t pack_h2(float a, float b) {
    uint32_t r;
    asm("cvt.rn.f16x2.f32 %0, %1, %2;" : "=r"(r) : "f"(b), "f"(a));
    return r;
}
DEV void split_h(float v, float& hi, float& lo) {
    hi = __half2float(__float2half(v));
    lo = v - hi;
}
DEV uint2 limb2h(float a, float b) {
    float ha, la, hb, lb;
    split_h(a, ha, la); split_h(b, hb, lb);
    return make_uint2(pack_h2(ha, hb), pack_h2(la, lb));
}

// ---------------- async 2-limb bf16 x3 GEMM (proven) ----------------
template<int BM, int BN, int WM, int WN, int MT, int NT>
DEV void gemm_async_bf16(const uint2* __restrict__ A, int lda,
                         const uint2* __restrict__ B, int ldb,
                         int K, char* smem, uint32_t su, float* acc)
{
    const int tid = threadIdx.x;
    const int lane = tid & 31, wid = tid >> 5;
    const int g = lane >> 2, tq = lane & 3;
    const int wm0 = (wid / WN) * (BM / WM);
    const int wn0 = (wid % WN) * (BN / WN);

    constexpr int SA = BM * PADB * 8;
    constexpr int STAGE = SA + BN * PADB * 8;

    auto copy_chunk = [&](int c, int s) {
        uint32_t base = su + s * STAGE;
#pragma unroll
        for (int t = 0; t < BM * 4 / 256; t++) {
            int idx = tid + t * 256; int r = idx >> 2, j = idx & 3;
            cp16(base + r * 80 + j * 16, A + (size_t)r * lda + c * 8 + j * 2);
        }
#pragma unroll
        for (int t = 0; t < (BN * 4 + 255) / 256; t++) {
            int idx = tid + t * 256;
            if (BN * 4 % 256 == 0 || idx < BN * 4) {
                int r = idx >> 2, j = idx & 3;
                cp16(base + SA + r * 80 + j * 16, B + (size_t)r * ldb + c * 8 + j * 2);
            }
        }
        cp_commit();
    };
    auto compute = [&](int s) {
        const uint2* Ab = (const uint2*)(smem + s * STAGE);
        const uint2* Bb = (const uint2*)(smem + s * STAGE + SA);
        uint32_t bh[NT][2], bl[NT][2];
#pragma unroll
        for (int ni = 0; ni < NT; ni++) {
            int n0 = wn0 + ni * 8 + g;
            uint2 w0 = Bb[n0 * PADB + tq];
            uint2 w1 = Bb[n0 * PADB + tq + 4];
            bh[ni][0] = w0.x; bl[ni][0] = w0.y;
            bh[ni][1] = w1.x; bl[ni][1] = w1.y;
        }
#pragma unroll
        for (int mi = 0; mi < MT; mi++) {
            int r0 = wm0 + mi * 16 + g;
            uint2 v0 = Ab[r0 * PADB + tq];
            uint2 v1 = Ab[(r0 + 8) * PADB + tq];
            uint2 v2 = Ab[r0 * PADB + tq + 4];
            uint2 v3 = Ab[(r0 + 8) * PADB + tq + 4];
            uint32_t ah[4] = { v0.x, v1.x, v2.x, v3.x };
            uint32_t al[4] = { v0.y, v1.y, v2.y, v3.y };
#pragma unroll
            for (int ni = 0; ni < NT; ni++) {
                float* c = acc + (mi * NT + ni) * 4;
                mma_bf16(c, ah, bh[ni]);
                mma_bf16(c, ah, bl[ni]);
                mma_bf16(c, al, bh[ni]);
            }
        }
    };

    int nc = K >> 4;
    copy_chunk(0, 0);
    for (int c = 0; c < nc; c++) {
        cp_wait<0>();
        __syncthreads();
        if (c + 1 < nc) copy_chunk(c + 1, (c + 1) & 1);
        compute(c & 1);
    }
}

// ---------------- async 2-limb fp16 x3 GEMM (verbatim copy, fp16 mma) ----------------
template<int BM, int BN, int WM, int WN, int MT, int NT>
DEV void gemm_async_fp16(const uint2* __restrict__ A, int lda,
                         const uint2* __restrict__ B, int ldb,
                         int K, char* smem, uint32_t su, float* acc)
{
    const int tid = threadIdx.x;
    const int lane = tid & 31, wid = tid >> 5;
    const int g = lane >> 2, tq = lane & 3;
    const int wm0 = (wid / WN) * (BM / WM);
    const int wn0 = (wid % WN) * (BN / WN);

    constexpr int SA = BM * PADB * 8;
    constexpr int STAGE = SA + BN * PADB * 8;

    auto copy_chunk = [&](int c, int s) {
        uint32_t base = su + s * STAGE;
#pragma unroll
        for (int t = 0; t < BM * 4 / 256; t++) {
            int idx = tid + t * 256; int r = idx >> 2, j = idx & 3;
            cp16(base + r * 80 + j * 16, A + (size_t)r * lda + c * 8 + j * 2);
        }
#pragma unroll
        for (int t = 0; t < (BN * 4 + 255) / 256; t++) {
            int idx = tid + t * 256;
            if (BN * 4 % 256 == 0 || idx < BN * 4) {
                int r = idx >> 2, j = idx & 3;
                cp16(base + SA + r * 80 + j * 16, B + (size_t)r * ldb + c * 8 + j * 2);
            }
        }
        cp_commit();
    };
    auto compute = [&](int s) {
        const uint2* Ab = (const uint2*)(smem + s * STAGE);
        const uint2* Bb = (const uint2*)(smem + s * STAGE + SA);
        uint32_t bh[NT][2], bl[NT][2];
#pragma unroll
        for (int ni = 0; ni < NT; ni++) {
            int n0 = wn0 + ni * 8 + g;
            uint2 w0 = Bb[n0 * PADB + tq];
            uint2 w1 = Bb[n0 * PADB + tq + 4];
            bh[ni][0] = w0.x; bl[ni][0] = w0.y;
            bh[ni][1] = w1.x; bl[ni][1] = w1.y;
        }
#pragma unroll
        for (int mi = 0; mi < MT; mi++) {
            int r0 = wm0 + mi * 16 + g;
            uint2 v0 = Ab[r0 * PADB + tq];
            uint2 v1 = Ab[(r0 + 8) * PADB + tq];
            uint2 v2 = Ab[r0 * PADB + tq + 4];
            uint2 v3 = Ab[(r0 + 8) * PADB + tq + 4];
            uint32_t ah[4] = { v0.x, v1.x, v2.x, v3.x };
            uint32_t al[4] = { v0.y, v1.y, v2.y, v3.y };
#pragma unroll
            for (int ni = 0; ni < NT; ni++) {
                float* c = acc + (mi * NT + ni) * 4;
                mma_fp16(c, ah, bh[ni]);
                mma_fp16(c, ah, bl[ni]);
                mma_fp16(c, al, bh[ni]);
            }
        }
    };

    int nc = K >> 4;
    copy_chunk(0, 0);
    for (int c = 0; c < nc; c++) {
        cp_wait<0>();
        __syncthreads();
        if (c + 1 < nc) copy_chunk(c + 1, (c + 1) & 1);
        compute(c & 1);
    }
}

// epilogue iteration
template<int BM, int BN, int WM, int WN, int MT, int NT, typename F>
DEV void epilogue(const float* acc, F fn)
{
    int lane = threadIdx.x & 31, wid = threadIdx.x >> 5;
    int g = lane >> 2, tq = lane & 3;
    int wm0 = (wid / WN) * (BM / WM);
    int wn0 = (wid % WN) * (BN / WN);
#pragma unroll
    for (int mi = 0; mi < MT; mi++)
#pragma unroll
        for (int ni = 0; ni < NT; ni++)
#pragma unroll
            for (int cj = 0; cj < 4; cj++) {
                int row = wm0 + mi * 16 + g + ((cj >= 2) ? 8 : 0);
                int col = wn0 + ni * 8 + 2 * tq + (cj & 1);
                fn(row, col, acc[(mi * NT + ni) * 4 + cj]);
            }
}

// ---------------- prep kernels ----------------
__global__ __launch_bounds__(256) void x_split_kernel(const float* __restrict__ x)
{
    int idx = blockIdx.x * 256 + threadIdx.x;       // pair index, 2M total
    ((uint2*)g_xbf4)[idx] = limb2(x[2 * idx], x[2 * idx + 1]);
}

__global__ __launch_bounds__(256) void xg_kernel(const float* __restrict__ x)
{
    int t = blockIdx.x;
    int tid = threadIdx.x;
    float4 v = ((const float4*)(x + (size_t)t * EMB))[tid];
    float p = v.x + v.y + v.z + v.w;
#pragma unroll
    for (int o = 8; o > 0; o >>= 1) p += __shfl_down_sync(0xffffffffu, p, o, 16);
    if ((tid & 15) == 0) g_xg[t * 16 + (tid >> 4)] = p;
}

__global__ __launch_bounds__(256) void pack_qwl_kernel(const int* __restrict__ qw, int mode)
{
    int idx = blockIdx.x * 256 + threadIdx.x;       // pair index, 512K total
    ((uint2*)g_wqkvl4[mode])[idx] =
        make_uint2(pack_bf16((float)qw[2 * idx], (float)qw[2 * idx + 1]), 0u);
}
__global__ __launch_bounds__(256) void pack_scale_kernel(
    const float* __restrict__ sc, const float* __restrict__ zr, int mode)
{
    int idx = blockIdx.x * 256 + threadIdx.x;       // 16384
    float s = sc[idx];
    g_s[mode][idx] = s;
    g_sz[mode][idx] = s * zr[idx];
}

__global__ __launch_bounds__(256) void dequant_o_kernel(
    const int* __restrict__ qw, const float* __restrict__ sc,
    const float* __restrict__ zr)
{
    int idx4 = (blockIdx.x * 256 + threadIdx.x) * 4;
    int o = idx4 >> 10, i = idx4 & 1023, grp = i >> 6;
    float s = sc[o * 16 + grp], z = zr[o * 16 + grp];
    uint2* dst = (uint2*)g_wo4 + (idx4 >> 1);
    dst[0] = limb2(((float)qw[idx4 + 0] - z) * s, ((float)qw[idx4 + 1] - z) * s);
    dst[1] = limb2(((float)qw[idx4 + 2] - z) * s, ((float)qw[idx4 + 3] - z) * s);
}

// ---------------- QKV projection: continuous pipeline, 2 products (proven R12) ----------------
#define QKV_SMEM 33792
__global__ __launch_bounds__(256, 2) void proj_qkv_kernel(
    const float* __restrict__ bq, const float* __restrict__ bk,
    const float* __restrict__ bv)
{
    extern __shared__ char smem[];
    uint32_t su = smem_u32(smem);
    const int tid = threadIdx.x;
    const int lane = tid & 31, wid = tid >> 5;
    const int g = lane >> 2, tq = lane & 3;
    const int wm0 = (wid / 2) * 32;             // WM=4
    const int wn0 = (wid % 2) * 32;             // WN=2

    int mode = blockIdx.z;
    int n0 = blockIdx.x * 64, m0 = blockIdx.y * 128;
    const float* bias = mode == 0 ? bq : (mode == 1 ? bk : bv);

    const uint2* A = (const uint2*)g_xbf4 + (size_t)m0 * 512;
    const uint2* B = (const uint2*)g_wqkvl4[mode] + (size_t)n0 * 512;
    const float* sarr = g_s[mode];
    const float* szarr = g_sz[mode];

    constexpr int SA = 128 * PADB * 8;          // 10240
    constexpr int STAGE = SA + 64 * PADB * 8;   // 15360

    auto copy_chunk = [&](int c, int s) {
        uint32_t base = su + s * STAGE;
#pragma unroll
        for (int t = 0; t < 2; t++) {           // A: 128 rows
            int idx = tid + t * 256; int r = idx >> 2, j = idx & 3;
            cp16(base + r * 80 + j * 16, A + (size_t)r * 512 + c * 8 + j * 2);
        }
        {                                        // B: 64 rows
            int r = tid >> 2, j = tid & 3;
            cp16(base + SA + r * 80 + j * 16, B + (size_t)r * 512 + c * 8 + j * 2);
        }
        cp_commit();
    };

    float master[32], tmp[32];
#pragma unroll
    for (int i = 0; i < 32; i++) { master[i] = 0.f; tmp[i] = 0.f; }

    copy_chunk(0, 0);
    for (int c = 0; c < 64; c++) {
        cp_wait<0>();
        __syncthreads();
        if (c + 1 < 64) copy_chunk(c + 1, (c + 1) & 1);
        {
            const uint2* Ab = (const uint2*)(smem + (c & 1) * STAGE);
            const uint2* Bb = (const uint2*)(smem + (c & 1) * STAGE + SA);
            uint32_t bh[4][2];
#pragma unroll
            for (int ni = 0; ni < 4; ni++) {
                int n = wn0 + ni * 8 + g;
                uint2 w0 = Bb[n * PADB + tq];
                uint2 w1 = Bb[n * PADB + tq + 4];
                bh[ni][0] = w0.x;
                bh[ni][1] = w1.x;
            }
#pragma unroll
            for (int mi = 0; mi < 2; mi++) {
                int r0 = wm0 + mi * 16 + g;
                uint2 v0 = Ab[r0 * PADB + tq];
                uint2 v1 = Ab[(r0 + 8) * PADB + tq];
                uint2 v2 = Ab[r0 * PADB + tq + 4];
                uint2 v3 = Ab[(r0 + 8) * PADB + tq + 4];
                uint32_t ah[4] = { v0.x, v1.x, v2.x, v3.x };
                uint32_t al[4] = { v0.y, v1.y, v2.y, v3.y };
#pragma unroll
                for (int ni = 0; ni < 4; ni++) {
                    float* cc = tmp + (mi * 4 + ni) * 4;
                    mma_bf16(cc, ah, bh[ni]);
                    mma_bf16(cc, al, bh[ni]);
                }
            }
        }
        if ((c & 3) == 3) {
            int grp = c >> 2;
#pragma unroll
            for (int ni = 0; ni < 4; ni++) {
                int c0 = n0 + wn0 + ni * 8 + 2 * tq;
                float s0 = __ldg(&sarr[c0 * 16 + grp]);
                float s1 = __ldg(&sarr[(c0 + 1) * 16 + grp]);
#pragma unroll
                for (int mi = 0; mi < 2; mi++) {
                    float* mm = master + (mi * 4 + ni) * 4;
                    float* tt = tmp + (mi * 4 + ni) * 4;
                    mm[0] = fmaf(s0, tt[0], mm[0]);
                    mm[1] = fmaf(s1, tt[1], mm[1]);
                    mm[2] = fmaf(s0, tt[2], mm[2]);
                    mm[3] = fmaf(s1, tt[3], mm[3]);
                    tt[0] = 0.f; tt[1] = 0.f; tt[2] = 0.f; tt[3] = 0.f;
                }
            }
        }
    }

    // zero correction
    for (int grp = 0; grp < 16; grp++) {
        float xr[2][2];
#pragma unroll
        for (int mi = 0; mi < 2; mi++) {
            int r0 = m0 + wm0 + mi * 16 + g;
            xr[mi][0] = __ldg(&g_xg[r0 * 16 + grp]);
            xr[mi][1] = __ldg(&g_xg[(r0 + 8) * 16 + grp]);
        }
#pragma unroll
        for (int ni = 0; ni < 4; ni++) {
            int c0 = n0 + wn0 + ni * 8 + 2 * tq;
            float z0 = __ldg(&szarr[c0 * 16 + grp]);
            float z1 = __ldg(&szarr[(c0 + 1) * 16 + grp]);
#pragma unroll
            for (int mi = 0; mi < 2; mi++) {
                float* mm = master + (mi * 4 + ni) * 4;
                mm[0] = fmaf(-z0, xr[mi][0], mm[0]);
                mm[1] = fmaf(-z1, xr[mi][0], mm[1]);
                mm[2] = fmaf(-z0, xr[mi][1], mm[2]);
                mm[3] = fmaf(-z1, xr[mi][1], mm[3]);
            }
        }
    }

    if (mode < 2) {
        // write q/k as fp16 limb pairs (mirrors proven PV epilogue pattern)
        uint2* dst = mode == 0 ? (uint2*)g_qh4 : (uint2*)g_kh4;
#pragma unroll
        for (int mi = 0; mi < 2; mi++)
#pragma unroll
            for (int ni = 0; ni < 4; ni++) {
                const float* c = master + (mi * 4 + ni) * 4;
                int col0 = wn0 + ni * 8 + 2 * tq;       // even
                int r0 = wm0 + mi * 16 + g;
                int token = m0 + r0;
                int b = token >> 11, si = token & 2047;
                int o0 = n0 + col0;
                int h = o0 >> 6, d0 = o0 & 63;
                float b0 = bias[o0], b1 = bias[o0 + 1];
                size_t base = ((size_t)(b * 16 + h) * S_LEN + si) * 32 + (d0 >> 1);
                dst[base] = limb2h(c[0] + b0, c[1] + b1);
                dst[base + 8 * 32] = limb2h(c[2] + b0, c[3] + b1);
            }
    } else {
        __syncthreads();
        float* T = (float*)smem;                // [64 cols][132]
        int b = m0 >> 11, si0 = m0 & 2047;
        epilogue<128, 64, 4, 2, 2, 4>(master, [&](int row, int col, float val) {
            T[col * 132 + row] = val + bias[n0 + col];
        });
        __syncthreads();
        for (int i = threadIdx.x; i < 64 * 64; i += 256) {
            int cl = i >> 6, sp = i & 63;
            int o = n0 + cl; int h = o >> 6, d = o & 63;
            uint2 v = limb2(T[cl * 132 + 2 * sp], T[cl * 132 + 2 * sp + 1]);
            ((uint2*)g_vts4)[((size_t)(b * 16 + h) * 64 + d) * 1024 + ((si0 + 2 * sp) >> 1)] = v;
        }
    }
}

// ---------------- scores (2-limb fp16 x3) ----------------
#define SC_SMEM (2 * (128 + 128) * PADB * 8)            // 40960
__global__ __launch_bounds__(256, 2) void scores_kernel(float* __restrict__ attn)
{
    extern __shared__ char smem[];
    uint32_t su = smem_u32(smem);
    int bh = blockIdx.z;
    int n0 = blockIdx.x * 128, m0 = blockIdx.y * 128;
    size_t base = (size_t)bh * S_LEN * 32;              // uint2 units (32 per row of 64)

    float acc[64];
#pragma unroll
    for (int i = 0; i < 64; i++) acc[i] = 0.f;

    gemm_async_fp16<128, 128, 2, 4, 4, 4>(
        (const uint2*)g_qh4 + base + (size_t)m0 * 32, 32,
        (const uint2*)g_kh4 + base + (size_t)n0 * 32, 32, 64, smem, su, acc);

    float* out = attn + (size_t)bh * S_LEN * S_LEN;
    epilogue<128, 128, 2, 4, 4, 4>(acc, [&](int row, int col, float val) {
        out[(size_t)(m0 + row) * S_LEN + n0 + col] = val * 0.125f;
    });
}

// ---------------- softmax (in place) + write bf16 limb P (proven) ----------------
__global__ __launch_bounds__(256) void softmax_kernel(float* __restrict__ S)
{
    size_t row = blockIdx.x;
    float4* p4 = (float4*)(S + row * S_LEN);
    int t = threadIdx.x;
    float4 u0 = p4[2 * t], u1 = p4[2 * t + 1];
    float v[8] = { u0.x, u0.y, u0.z, u0.w, u1.x, u1.y, u1.z, u1.w };
    float m = v[0];
#pragma unroll
    for (int i = 1; i < 8; i++) m = fmaxf(m, v[i]);
#pragma unroll
    for (int o = 16; o > 0; o >>= 1) m = fmaxf(m, __shfl_xor_sync(0xffffffffu, m, o));
    __shared__ float sred[8]; __shared__ float sbc;
    if ((t & 31) == 0) sred[t >> 5] = m;
    __syncthreads();
    if (t == 0) {
        float x = sred[0];
#pragma unroll
        for (int i = 1; i < 8; i++) x = fmaxf(x, sred[i]);
        sbc = x;
    }
    __syncthreads();
    m = sbc;
    float sum = 0.f;
#pragma unroll
    for (int i = 0; i < 8; i++) { v[i] = __expf(v[i] - m); sum += v[i]; }
#pragma unroll
    for (int o = 16; o > 0; o >>= 1) sum += __shfl_xor_sync(0xffffffffu, sum, o);
    __syncthreads();
    if ((t & 31) == 0) sred[t >> 5] = sum;
    __syncthreads();
    if (t == 0) {
        float x = 0.f;
#pragma unroll
        for (int i = 0; i < 8; i++) x += sred[i];
        sbc = 1.0f / x;
    }
    __syncthreads();
    float inv = sbc;
    float w[8];
#pragma unroll
    for (int i = 0; i < 8; i++) w[i] = v[i] * inv;
    p4[2 * t]     = make_float4(w[0], w[1], w[2], w[3]);
    p4[2 * t + 1] = make_float4(w[4], w[5], w[6], w[7]);
    uint2* lp = (uint2*)g_pps4 + row * 1024 + t * 4;
    lp[0] = limb2(w[0], w[1]); lp[1] = limb2(w[2], w[3]);
    lp[2] = limb2(w[4], w[5]); lp[3] = limb2(w[6], w[7]);
}

// ---------------- PV (proven) ----------------
#define PV_SMEM (2 * (128 + 64) * PADB * 8)
__global__ __launch_bounds__(256, 2) void pv_kernel()
{
    extern __shared__ char smem[];
    uint32_t su = smem_u32(smem);
    int bh = blockIdx.z;
    int m0 = blockIdx.y * 128;

    float acc[32];
#pragma unroll
    for (int i = 0; i < 32; i++) acc[i] = 0.f;

    gemm_async_bf16<128, 64, 4, 2, 2, 4>(
        (const uint2*)g_pps4 + ((size_t)bh * S_LEN + m0) * 1024, 1024,
        (const uint2*)g_vts4 + (size_t)bh * 64 * 1024, 1024, S_LEN, smem, su, acc);

    int b = bh >> 4, h = bh & 15;
    {
        int lane = threadIdx.x & 31, wid = threadIdx.x >> 5;
        int g = lane >> 2, tq = lane & 3;
        int wm0 = (wid / 2) * 32;
        int wn0 = (wid % 2) * 32;
#pragma unroll
        for (int mi = 0; mi < 2; mi++)
#pragma unroll
            for (int ni = 0; ni < 4; ni++) {
                const float* c = acc + (mi * 4 + ni) * 4;
                int col0 = wn0 + ni * 8 + 2 * tq;
                int r0 = wm0 + mi * 16 + g;
                size_t tok0 = (size_t)b * S_LEN + m0 + r0;
                ((uint2*)g_aos4)[tok0 * 512 + (h * 64 + col0) / 2] = limb2(c[0], c[1]);
                ((uint2*)g_aos4)[(tok0 + 8) * 512 + (h * 64 + col0) / 2] = limb2(c[2], c[3]);
            }
    }
}

// ---------------- O projection (proven) ----------------
#define OP_SMEM (2 * (128 + 128) * PADB * 8)
__global__ __launch_bounds__(256, 2) void oproj_kernel(
    const float* __restrict__ bias, float* __restrict__ out)
{
    extern __shared__ char smem[];
    uint32_t su = smem_u32(smem);
    int n0 = blockIdx.x * 128, m0 = blockIdx.y * 128;

    float acc[64];
#pragma unroll
    for (int i = 0; i < 64; i++) acc[i] = 0.f;

    gemm_async_bf16<128, 128, 2, 4, 4, 4>(
        (const uint2*)g_aos4 + (size_t)m0 * 512, 512,
        (const uint2*)g_wo4 + (size_t)n0 * 512, 512, EMB, smem, su, acc);

    epilogue<128, 128, 2, 4, 4, 4>(acc, [&](int row, int col, float val) {
        int token = m0 + row, o = n0 + col;
        out[(size_t)token * EMB + o] = val + bias[o];
    });
}

// ---------------- launch ----------------
extern "C" void kernel_launch(void* const* d_in, const int* in_sizes, int n_in,
                              void* d_out, int out_size)
{
    const float* x = (const float*)d_in[0];
    const int* qw[4];
    const float *sc[4], *zr[4], *bs[4];
    for (int p = 0; p < 4; p++) {
        qw[p] = (const int*)d_in[1 + 4 * p];
        sc[p] = (const float*)d_in[2 + 4 * p];
        zr[p] = (const float*)d_in[3 + 4 * p];
        bs[p] = (const float*)d_in[4 + 4 * p];
    }
    float* out = (float*)d_out;                 // [B,S,E]
    float* attn = out + (size_t)4194304;        // [B,H,S,S]

    cudaFuncSetAttribute(proj_qkv_kernel, cudaFuncAttributeMaxDynamicSharedMemorySize, QKV_SMEM);
    cudaFuncSetAttribute(scores_kernel,   cudaFuncAttributeMaxDynamicSharedMemorySize, SC_SMEM);
    cudaFuncSetAttribute(pv_kernel,       cudaFuncAttributeMaxDynamicSharedMemorySize, PV_SMEM);
    cudaFuncSetAttribute(oproj_kernel,    cudaFuncAttributeMaxDynamicSharedMemorySize, OP_SMEM);

    x_split_kernel<<<8192, 256>>>(x);
    xg_kernel<<<4096, 256>>>(x);
    for (int p = 0; p < 3; p++) {
        pack_qwl_kernel<<<2048, 256>>>(qw[p], p);
        pack_scale_kernel<<<64, 256>>>(sc[p], zr[p], p);
    }
    dequant_o_kernel<<<1024, 256>>>(qw[3], sc[3], zr[3]);

    proj_qkv_kernel<<<dim3(16, 32, 3), 256, QKV_SMEM>>>(bs[0], bs[1], bs[2]);
    scores_kernel<<<dim3(16, 16, 32), 256, SC_SMEM>>>(attn);
    softmax_kernel<<<65536, 256>>>(attn);
    pv_kernel<<<dim3(1, 16, 32), 256, PV_SMEM>>>();
    oproj_kernel<<<dim3(8, 32), 256, OP_SMEM>>>(bs[3], out);
}

// round 14
// speedup vs baseline: 3.3141x; 1.0863x over previous
#include <cuda_runtime.h>
#include <cuda_bf16.h>
#include <cuda_fp16.h>
#include <cstdint>
#include <cstddef>

#define DEV __device__ __forceinline__

#define S_LEN 2048
#define EMB   1024
#define PADB  10          // uint2 per SMEM row (8 data + 2 pad)   = 80 B

// ---------------- scratch (16B-aligned) ----------------
__device__ uint4  g_xbf4[4096 * 1024 / 4];           // x bf16 limb pairs [t][e/2]
__device__ __align__(16) float g_xg[4096 * 16];      // group sums of x [t][g]
__device__ uint4  g_wqkvl4[3][1024 * 1024 / 4];      // qw as (bf16 pair, 0) limb uint2 [o][e/2]
__device__ __align__(16) float g_s[3][1024 * 16];    // scales [o][g]
__device__ __align__(16) float g_sz[3][1024 * 16];   // scale*zero [o][g]
__device__ uint4  g_wo4[1024 * 1024 / 4];            // o weights bf16 limb pairs
__device__ uint4  g_qh4[32 * 2048 * 64 / 4];         // q fp16 limb pairs [bh][s][d/2]
__device__ uint4  g_kh4[32 * 2048 * 64 / 4];         // k fp16 limb pairs
__device__ uint4  g_vts4[32 * 64 * 2048 / 4];        // v^T bf16 limbs [bh][d][s/2]
__device__ uint4  g_aos4[4096 * 1024 / 4];           // attn-out bf16 limbs [tok][e/2]

DEV uint32_t smem_u32(const void* p) {
    uint32_t a;
    asm("{ .reg .u64 t; cvta.to.shared.u64 t, %1; cvt.u32.u64 %0, t; }" : "=r"(a) : "l"(p));
    return a;
}
DEV void cp16(uint32_t dst, const void* src) {
    asm volatile("cp.async.cg.shared.global [%0], [%1], 16;" :: "r"(dst), "l"(src));
}
DEV void cp_commit() { asm volatile("cp.async.commit_group;" ::: "memory"); }
template<int N> DEV void cp_wait() { asm volatile("cp.async.wait_group %0;" :: "n"(N) : "memory"); }

DEV void mma_bf16(float* c, const uint32_t* a, const uint32_t* b) {
    asm volatile(
        "mma.sync.aligned.m16n8k16.row.col.f32.bf16.bf16.f32 "
        "{%0,%1,%2,%3}, {%4,%5,%6,%7}, {%8,%9}, {%0,%1,%2,%3};"
        : "+f"(c[0]), "+f"(c[1]), "+f"(c[2]), "+f"(c[3])
        : "r"(a[0]), "r"(a[1]), "r"(a[2]), "r"(a[3]), "r"(b[0]), "r"(b[1]));
}
DEV void mma_fp16(float* c, const uint32_t* a, const uint32_t* b) {
    asm volatile(
        "mma.sync.aligned.m16n8k16.row.col.f32.f16.f16.f32 "
        "{%0,%1,%2,%3}, {%4,%5,%6,%7}, {%8,%9}, {%0,%1,%2,%3};"
        : "+f"(c[0]), "+f"(c[1]), "+f"(c[2]), "+f"(c[3])
        : "r"(a[0]), "r"(a[1]), "r"(a[2]), "r"(a[3]), "r"(b[0]), "r"(b[1]));
}

DEV uint32_t pack_bf16(float a, float b) {
    uint32_t r;
    asm("cvt.rn.bf16x2.f32 %0, %1, %2;" : "=r"(r) : "f"(b), "f"(a));
    return r;
}
DEV void split_bf(float v, float& hi, float& lo) {
    hi = __bfloat162float(__float2bfloat16(v));
    lo = v - hi;
}
DEV uint2 limb2(float a, float b) {
    float ha, la, hb, lb;
    split_bf(a, ha, la); split_bf(b, hb, lb);
    return make_uint2(pack_bf16(ha, hb), pack_bf16(la, lb));
}

DEV uint32_t pack_h2(float a, float b) {
    uint32_t r;
    asm("cvt.rn.f16x2.f32 %0, %1, %2;" : "=r"(r) : "f"(b), "f"(a));
    return r;
}
DEV void split_h(float v, float& hi, float& lo) {
    hi = __half2float(__float2half(v));
    lo = v - hi;
}
DEV uint2 limb2h(float a, float b) {
    float ha, la, hb, lb;
    split_h(a, ha, la); split_h(b, hb, lb);
    return make_uint2(pack_h2(ha, hb), pack_h2(la, lb));
}

// ---------------- async 2-limb bf16 x3 GEMM (proven) ----------------
template<int BM, int BN, int WM, int WN, int MT, int NT>
DEV void gemm_async_bf16(const uint2* __restrict__ A, int lda,
                         const uint2* __restrict__ B, int ldb,
                         int K, char* smem, uint32_t su, float* acc)
{
    const int tid = threadIdx.x;
    const int lane = tid & 31, wid = tid >> 5;
    const int g = lane >> 2, tq = lane & 3;
    const int wm0 = (wid / WN) * (BM / WM);
    const int wn0 = (wid % WN) * (BN / WN);

    constexpr int SA = BM * PADB * 8;
    constexpr int STAGE = SA + BN * PADB * 8;

    auto copy_chunk = [&](int c, int s) {
        uint32_t base = su + s * STAGE;
#pragma unroll
        for (int t = 0; t < BM * 4 / 256; t++) {
            int idx = tid + t * 256; int r = idx >> 2, j = idx & 3;
            cp16(base + r * 80 + j * 16, A + (size_t)r * lda + c * 8 + j * 2);
        }
#pragma unroll
        for (int t = 0; t < (BN * 4 + 255) / 256; t++) {
            int idx = tid + t * 256;
            if (BN * 4 % 256 == 0 || idx < BN * 4) {
                int r = idx >> 2, j = idx & 3;
                cp16(base + SA + r * 80 + j * 16, B + (size_t)r * ldb + c * 8 + j * 2);
            }
        }
        cp_commit();
    };
    auto compute = [&](int s) {
        const uint2* Ab = (const uint2*)(smem + s * STAGE);
        const uint2* Bb = (const uint2*)(smem + s * STAGE + SA);
        uint32_t bh[NT][2], bl[NT][2];
#pragma unroll
        for (int ni = 0; ni < NT; ni++) {
            int n0 = wn0 + ni * 8 + g;
            uint2 w0 = Bb[n0 * PADB + tq];
            uint2 w1 = Bb[n0 * PADB + tq + 4];
            bh[ni][0] = w0.x; bl[ni][0] = w0.y;
            bh[ni][1] = w1.x; bl[ni][1] = w1.y;
        }
#pragma unroll
        for (int mi = 0; mi < MT; mi++) {
            int r0 = wm0 + mi * 16 + g;
            uint2 v0 = Ab[r0 * PADB + tq];
            uint2 v1 = Ab[(r0 + 8) * PADB + tq];
            uint2 v2 = Ab[r0 * PADB + tq + 4];
            uint2 v3 = Ab[(r0 + 8) * PADB + tq + 4];
            uint32_t ah[4] = { v0.x, v1.x, v2.x, v3.x };
            uint32_t al[4] = { v0.y, v1.y, v2.y, v3.y };
#pragma unroll
            for (int ni = 0; ni < NT; ni++) {
                float* c = acc + (mi * NT + ni) * 4;
                mma_bf16(c, ah, bh[ni]);
                mma_bf16(c, ah, bl[ni]);
                mma_bf16(c, al, bh[ni]);
            }
        }
    };

    int nc = K >> 4;
    copy_chunk(0, 0);
    for (int c = 0; c < nc; c++) {
        cp_wait<0>();
        __syncthreads();
        if (c + 1 < nc) copy_chunk(c + 1, (c + 1) & 1);
        compute(c & 1);
    }
}

// ---------------- async 2-limb fp16 x3 GEMM (proven R13) ----------------
template<int BM, int BN, int WM, int WN, int MT, int NT>
DEV void gemm_async_fp16(const uint2* __restrict__ A, int lda,
                         const uint2* __restrict__ B, int ldb,
                         int K, char* smem, uint32_t su, float* acc)
{
    const int tid = threadIdx.x;
    const int lane = tid & 31, wid = tid >> 5;
    const int g = lane >> 2, tq = lane & 3;
    const int wm0 = (wid / WN) * (BM / WM);
    const int wn0 = (wid % WN) * (BN / WN);

    constexpr int SA = BM * PADB * 8;
    constexpr int STAGE = SA + BN * PADB * 8;

    auto copy_chunk = [&](int c, int s) {
        uint32_t base = su + s * STAGE;
#pragma unroll
        for (int t = 0; t < BM * 4 / 256; t++) {
            int idx = tid + t * 256; int r = idx >> 2, j = idx & 3;
            cp16(base + r * 80 + j * 16, A + (size_t)r * lda + c * 8 + j * 2);
        }
#pragma unroll
        for (int t = 0; t < (BN * 4 + 255) / 256; t++) {
            int idx = tid + t * 256;
            if (BN * 4 % 256 == 0 || idx < BN * 4) {
                int r = idx >> 2, j = idx & 3;
                cp16(base + SA + r * 80 + j * 16, B + (size_t)r * ldb + c * 8 + j * 2);
            }
        }
        cp_commit();
    };
    auto compute = [&](int s) {
        const uint2* Ab = (const uint2*)(smem + s * STAGE);
        const uint2* Bb = (const uint2*)(smem + s * STAGE + SA);
        uint32_t bh[NT][2], bl[NT][2];
#pragma unroll
        for (int ni = 0; ni < NT; ni++) {
            int n0 = wn0 + ni * 8 + g;
            uint2 w0 = Bb[n0 * PADB + tq];
            uint2 w1 = Bb[n0 * PADB + tq + 4];
            bh[ni][0] = w0.x; bl[ni][0] = w0.y;
            bh[ni][1] = w1.x; bl[ni][1] = w1.y;
        }
#pragma unroll
        for (int mi = 0; mi < MT; mi++) {
            int r0 = wm0 + mi * 16 + g;
            uint2 v0 = Ab[r0 * PADB + tq];
            uint2 v1 = Ab[(r0 + 8) * PADB + tq];
            uint2 v2 = Ab[r0 * PADB + tq + 4];
            uint2 v3 = Ab[(r0 + 8) * PADB + tq + 4];
            uint32_t ah[4] = { v0.x, v1.x, v2.x, v3.x };
            uint32_t al[4] = { v0.y, v1.y, v2.y, v3.y };
#pragma unroll
            for (int ni = 0; ni < NT; ni++) {
                float* c = acc + (mi * NT + ni) * 4;
                mma_fp16(c, ah, bh[ni]);
                mma_fp16(c, ah, bl[ni]);
                mma_fp16(c, al, bh[ni]);
            }
        }
    };

    int nc = K >> 4;
    copy_chunk(0, 0);
    for (int c = 0; c < nc; c++) {
        cp_wait<0>();
        __syncthreads();
        if (c + 1 < nc) copy_chunk(c + 1, (c + 1) & 1);
        compute(c & 1);
    }
}

// epilogue iteration
template<int BM, int BN, int WM, int WN, int MT, int NT, typename F>
DEV void epilogue(const float* acc, F fn)
{
    int lane = threadIdx.x & 31, wid = threadIdx.x >> 5;
    int g = lane >> 2, tq = lane & 3;
    int wm0 = (wid / WN) * (BM / WM);
    int wn0 = (wid % WN) * (BN / WN);
#pragma unroll
    for (int mi = 0; mi < MT; mi++)
#pragma unroll
        for (int ni = 0; ni < NT; ni++)
#pragma unroll
            for (int cj = 0; cj < 4; cj++) {
                int row = wm0 + mi * 16 + g + ((cj >= 2) ? 8 : 0);
                int col = wn0 + ni * 8 + 2 * tq + (cj & 1);
                fn(row, col, acc[(mi * NT + ni) * 4 + cj]);
            }
}

// ---------------- prep kernels ----------------
__global__ __launch_bounds__(256) void x_split_kernel(const float* __restrict__ x)
{
    int idx = blockIdx.x * 256 + threadIdx.x;
    ((uint2*)g_xbf4)[idx] = limb2(x[2 * idx], x[2 * idx + 1]);
}

__global__ __launch_bounds__(256) void xg_kernel(const float* __restrict__ x)
{
    int t = blockIdx.x;
    int tid = threadIdx.x;
    float4 v = ((const float4*)(x + (size_t)t * EMB))[tid];
    float p = v.x + v.y + v.z + v.w;
#pragma unroll
    for (int o = 8; o > 0; o >>= 1) p += __shfl_down_sync(0xffffffffu, p, o, 16);
    if ((tid & 15) == 0) g_xg[t * 16 + (tid >> 4)] = p;
}

__global__ __launch_bounds__(256) void pack_qwl_kernel(const int* __restrict__ qw, int mode)
{
    int idx = blockIdx.x * 256 + threadIdx.x;
    ((uint2*)g_wqkvl4[mode])[idx] =
        make_uint2(pack_bf16((float)qw[2 * idx], (float)qw[2 * idx + 1]), 0u);
}
__global__ __launch_bounds__(256) void pack_scale_kernel(
    const float* __restrict__ sc, const float* __restrict__ zr, int mode)
{
    int idx = blockIdx.x * 256 + threadIdx.x;
    float s = sc[idx];
    g_s[mode][idx] = s;
    g_sz[mode][idx] = s * zr[idx];
}

__global__ __launch_bounds__(256) void dequant_o_kernel(
    const int* __restrict__ qw, const float* __restrict__ sc,
    const float* __restrict__ zr)
{
    int idx4 = (blockIdx.x * 256 + threadIdx.x) * 4;
    int o = idx4 >> 10, i = idx4 & 1023, grp = i >> 6;
    float s = sc[o * 16 + grp], z = zr[o * 16 + grp];
    uint2* dst = (uint2*)g_wo4 + (idx4 >> 1);
    dst[0] = limb2(((float)qw[idx4 + 0] - z) * s, ((float)qw[idx4 + 1] - z) * s);
    dst[1] = limb2(((float)qw[idx4 + 2] - z) * s, ((float)qw[idx4 + 3] - z) * s);
}

// ---------------- QKV projection (proven R12/R13) ----------------
#define QKV_SMEM 33792
__global__ __launch_bounds__(256, 2) void proj_qkv_kernel(
    const float* __restrict__ bq, const float* __restrict__ bk,
    const float* __restrict__ bv)
{
    extern __shared__ char smem[];
    uint32_t su = smem_u32(smem);
    const int tid = threadIdx.x;
    const int lane = tid & 31, wid = tid >> 5;
    const int g = lane >> 2, tq = lane & 3;
    const int wm0 = (wid / 2) * 32;
    const int wn0 = (wid % 2) * 32;

    int mode = blockIdx.z;
    int n0 = blockIdx.x * 64, m0 = blockIdx.y * 128;
    const float* bias = mode == 0 ? bq : (mode == 1 ? bk : bv);

    const uint2* A = (const uint2*)g_xbf4 + (size_t)m0 * 512;
    const uint2* B = (const uint2*)g_wqkvl4[mode] + (size_t)n0 * 512;
    const float* sarr = g_s[mode];
    const float* szarr = g_sz[mode];

    constexpr int SA = 128 * PADB * 8;
    constexpr int STAGE = SA + 64 * PADB * 8;

    auto copy_chunk = [&](int c, int s) {
        uint32_t base = su + s * STAGE;
#pragma unroll
        for (int t = 0; t < 2; t++) {
            int idx = tid + t * 256; int r = idx >> 2, j = idx & 3;
            cp16(base + r * 80 + j * 16, A + (size_t)r * 512 + c * 8 + j * 2);
        }
        {
            int r = tid >> 2, j = tid & 3;
            cp16(base + SA + r * 80 + j * 16, B + (size_t)r * 512 + c * 8 + j * 2);
        }
        cp_commit();
    };

    float master[32], tmp[32];
#pragma unroll
    for (int i = 0; i < 32; i++) { master[i] = 0.f; tmp[i] = 0.f; }

    copy_chunk(0, 0);
    for (int c = 0; c < 64; c++) {
        cp_wait<0>();
        __syncthreads();
        if (c + 1 < 64) copy_chunk(c + 1, (c + 1) & 1);
        {
            const uint2* Ab = (const uint2*)(smem + (c & 1) * STAGE);
            const uint2* Bb = (const uint2*)(smem + (c & 1) * STAGE + SA);
            uint32_t bh[4][2];
#pragma unroll
            for (int ni = 0; ni < 4; ni++) {
                int n = wn0 + ni * 8 + g;
                uint2 w0 = Bb[n * PADB + tq];
                uint2 w1 = Bb[n * PADB + tq + 4];
                bh[ni][0] = w0.x;
                bh[ni][1] = w1.x;
            }
#pragma unroll
            for (int mi = 0; mi < 2; mi++) {
                int r0 = wm0 + mi * 16 + g;
                uint2 v0 = Ab[r0 * PADB + tq];
                uint2 v1 = Ab[(r0 + 8) * PADB + tq];
                uint2 v2 = Ab[r0 * PADB + tq + 4];
                uint2 v3 = Ab[(r0 + 8) * PADB + tq + 4];
                uint32_t ah[4] = { v0.x, v1.x, v2.x, v3.x };
                uint32_t al[4] = { v0.y, v1.y, v2.y, v3.y };
#pragma unroll
                for (int ni = 0; ni < 4; ni++) {
                    float* cc = tmp + (mi * 4 + ni) * 4;
                    mma_bf16(cc, ah, bh[ni]);
                    mma_bf16(cc, al, bh[ni]);
                }
            }
        }
        if ((c & 3) == 3) {
            int grp = c >> 2;
#pragma unroll
            for (int ni = 0; ni < 4; ni++) {
                int c0 = n0 + wn0 + ni * 8 + 2 * tq;
                float s0 = __ldg(&sarr[c0 * 16 + grp]);
                float s1 = __ldg(&sarr[(c0 + 1) * 16 + grp]);
#pragma unroll
                for (int mi = 0; mi < 2; mi++) {
                    float* mm = master + (mi * 4 + ni) * 4;
                    float* tt = tmp + (mi * 4 + ni) * 4;
                    mm[0] = fmaf(s0, tt[0], mm[0]);
                    mm[1] = fmaf(s1, tt[1], mm[1]);
                    mm[2] = fmaf(s0, tt[2], mm[2]);
                    mm[3] = fmaf(s1, tt[3], mm[3]);
                    tt[0] = 0.f; tt[1] = 0.f; tt[2] = 0.f; tt[3] = 0.f;
                }
            }
        }
    }

    for (int grp = 0; grp < 16; grp++) {
        float xr[2][2];
#pragma unroll
        for (int mi = 0; mi < 2; mi++) {
            int r0 = m0 + wm0 + mi * 16 + g;
            xr[mi][0] = __ldg(&g_xg[r0 * 16 + grp]);
            xr[mi][1] = __ldg(&g_xg[(r0 + 8) * 16 + grp]);
        }
#pragma unroll
        for (int ni = 0; ni < 4; ni++) {
            int c0 = n0 + wn0 + ni * 8 + 2 * tq;
            float z0 = __ldg(&szarr[c0 * 16 + grp]);
            float z1 = __ldg(&szarr[(c0 + 1) * 16 + grp]);
#pragma unroll
            for (int mi = 0; mi < 2; mi++) {
                float* mm = master + (mi * 4 + ni) * 4;
                mm[0] = fmaf(-z0, xr[mi][0], mm[0]);
                mm[1] = fmaf(-z1, xr[mi][0], mm[1]);
                mm[2] = fmaf(-z0, xr[mi][1], mm[2]);
                mm[3] = fmaf(-z1, xr[mi][1], mm[3]);
            }
        }
    }

    if (mode < 2) {
        uint2* dst = mode == 0 ? (uint2*)g_qh4 : (uint2*)g_kh4;
#pragma unroll
        for (int mi = 0; mi < 2; mi++)
#pragma unroll
            for (int ni = 0; ni < 4; ni++) {
                const float* c = master + (mi * 4 + ni) * 4;
                int col0 = wn0 + ni * 8 + 2 * tq;
                int r0 = wm0 + mi * 16 + g;
                int token = m0 + r0;
                int b = token >> 11, si = token & 2047;
                int o0 = n0 + col0;
                int h = o0 >> 6, d0 = o0 & 63;
                float b0 = bias[o0], b1 = bias[o0 + 1];
                size_t base = ((size_t)(b * 16 + h) * S_LEN + si) * 32 + (d0 >> 1);
                dst[base] = limb2h(c[0] + b0, c[1] + b1);
                dst[base + 8 * 32] = limb2h(c[2] + b0, c[3] + b1);
            }
    } else {
        __syncthreads();
        float* T = (float*)smem;
        int b = m0 >> 11, si0 = m0 & 2047;
        epilogue<128, 64, 4, 2, 2, 4>(master, [&](int row, int col, float val) {
            T[col * 132 + row] = val + bias[n0 + col];
        });
        __syncthreads();
        for (int i = threadIdx.x; i < 64 * 64; i += 256) {
            int cl = i >> 6, sp = i & 63;
            int o = n0 + cl; int h = o >> 6, d = o & 63;
            uint2 v = limb2(T[cl * 132 + 2 * sp], T[cl * 132 + 2 * sp + 1]);
            ((uint2*)g_vts4)[((size_t)(b * 16 + h) * 64 + d) * 1024 + ((si0 + 2 * sp) >> 1)] = v;
        }
    }
}

// ---------------- scores (2-limb fp16 x3, proven R13) ----------------
#define SC_SMEM (2 * (128 + 128) * PADB * 8)
__global__ __launch_bounds__(256, 2) void scores_kernel(float* __restrict__ attn)
{
    extern __shared__ char smem[];
    uint32_t su = smem_u32(smem);
    int bh = blockIdx.z;
    int n0 = blockIdx.x * 128, m0 = blockIdx.y * 128;
    size_t base = (size_t)bh * S_LEN * 32;

    float acc[64];
#pragma unroll
    for (int i = 0; i < 64; i++) acc[i] = 0.f;

    gemm_async_fp16<128, 128, 2, 4, 4, 4>(
        (const uint2*)g_qh4 + base + (size_t)m0 * 32, 32,
        (const uint2*)g_kh4 + base + (size_t)n0 * 32, 32, 64, smem, su, acc);

    float* out = attn + (size_t)bh * S_LEN * S_LEN;
    epilogue<128, 128, 2, 4, 4, 4>(acc, [&](int row, int col, float val) {
        out[(size_t)(m0 + row) * S_LEN + n0 + col] = val * 0.125f;
    });
}

// ---------------- softmax (in place, fp32 only) ----------------
__global__ __launch_bounds__(256) void softmax_kernel(float* __restrict__ S)
{
    size_t row = blockIdx.x;
    float4* p4 = (float4*)(S + row * S_LEN);
    int t = threadIdx.x;
    float4 u0 = p4[2 * t], u1 = p4[2 * t + 1];
    float v[8] = { u0.x, u0.y, u0.z, u0.w, u1.x, u1.y, u1.z, u1.w };
    float m = v[0];
#pragma unroll
    for (int i = 1; i < 8; i++) m = fmaxf(m, v[i]);
#pragma unroll
    for (int o = 16; o > 0; o >>= 1) m = fmaxf(m, __shfl_xor_sync(0xffffffffu, m, o));
    __shared__ float sred[8]; __shared__ float sbc;
    if ((t & 31) == 0) sred[t >> 5] = m;
    __syncthreads();
    if (t == 0) {
        float x = sred[0];
#pragma unroll
        for (int i = 1; i < 8; i++) x = fmaxf(x, sred[i]);
        sbc = x;
    }
    __syncthreads();
    m = sbc;
    float sum = 0.f;
#pragma unroll
    for (int i = 0; i < 8; i++) { v[i] = __expf(v[i] - m); sum += v[i]; }
#pragma unroll
    for (int o = 16; o > 0; o >>= 1) sum += __shfl_xor_sync(0xffffffffu, sum, o);
    __syncthreads();
    if ((t & 31) == 0) sred[t >> 5] = sum;
    __syncthreads();
    if (t == 0) {
        float x = 0.f;
#pragma unroll
        for (int i = 0; i < 8; i++) x += sred[i];
        sbc = 1.0f / x;
    }
    __syncthreads();
    float inv = sbc;
    p4[2 * t]     = make_float4(v[0] * inv, v[1] * inv, v[2] * inv, v[3] * inv);
    p4[2 * t + 1] = make_float4(v[4] * inv, v[5] * inv, v[6] * inv, v[7] * inv);
}

// ---------------- PV: A = fp32 P (split at fragment load), B = V^T bf16 limbs ----------------
#define PV_SMEM (2 * (128 + 64) * PADB * 8)             // same stage bytes: 16 fp32 = 64 B/row
__global__ __launch_bounds__(256, 2) void pv_kernel(const float* __restrict__ attn)
{
    extern __shared__ char smem[];
    uint32_t su = smem_u32(smem);
    const int tid = threadIdx.x;
    const int lane = tid & 31, wid = tid >> 5;
    const int g = lane >> 2, tq = lane & 3;
    const int wm0 = (wid / 2) * 32;             // WM=4
    const int wn0 = (wid % 2) * 32;             // WN=2
    int bh = blockIdx.z;
    int m0 = blockIdx.y * 128;

    const float* Af = attn + (size_t)bh * S_LEN * S_LEN + (size_t)m0 * S_LEN;
    const uint2* B = (const uint2*)g_vts4 + (size_t)bh * 64 * 1024;

    constexpr int SA = 128 * 80;                // fp32 rows: 16 floats + 4 pad = 80 B
    constexpr int STAGE = SA + 64 * 80;

    auto copy_chunk = [&](int c, int s) {
        uint32_t base = su + s * STAGE;
#pragma unroll
        for (int t = 0; t < 2; t++) {           // A: 128 rows x 64 B fp32
            int idx = tid + t * 256; int r = idx >> 2, j = idx & 3;
            cp16(base + r * 80 + j * 16, Af + (size_t)r * S_LEN + c * 16 + j * 4);
        }
        {                                        // B: 64 rows x 64 B limbs
            int r = tid >> 2, j = tid & 3;
            cp16(base + SA + r * 80 + j * 16, B + (size_t)r * 1024 + c * 8 + j * 2);
        }
        cp_commit();
    };

    float acc[32];
#pragma unroll
    for (int i = 0; i < 32; i++) acc[i] = 0.f;

    copy_chunk(0, 0);
    for (int c = 0; c < 128; c++) {
        cp_wait<0>();
        __syncthreads();
        if (c + 1 < 128) copy_chunk(c + 1, (c + 1) & 1);
        {
            const float* Ab = (const float*)(smem + (c & 1) * STAGE);   // [128][20]
            const uint2* Bb = (const uint2*)(smem + (c & 1) * STAGE + SA);
            uint32_t bh[4][2], bl[4][2];
#pragma unroll
            for (int ni = 0; ni < 4; ni++) {
                int n = wn0 + ni * 8 + g;
                uint2 w0 = Bb[n * PADB + tq];
                uint2 w1 = Bb[n * PADB + tq + 4];
                bh[ni][0] = w0.x; bl[ni][0] = w0.y;
                bh[ni][1] = w1.x; bl[ni][1] = w1.y;
            }
#pragma unroll
            for (int mi = 0; mi < 2; mi++) {
                int r0 = wm0 + mi * 16 + g;
                // fragment k-pairs: words 2tq (k=2tq,2tq+1) and 8+2tq (k=8+2tq,+1)
                float2 a0 = ((const float2*)(Ab + r0 * 20))[tq];
                float2 a1 = ((const float2*)(Ab + (r0 + 8) * 20))[tq];
                float2 a2 = ((const float2*)(Ab + r0 * 20 + 8))[tq];
                float2 a3 = ((const float2*)(Ab + (r0 + 8) * 20 + 8))[tq];
                uint2 u0 = limb2(a0.x, a0.y);
                uint2 u1 = limb2(a1.x, a1.y);
                uint2 u2 = limb2(a2.x, a2.y);
                uint2 u3 = limb2(a3.x, a3.y);
                uint32_t ah[4] = { u0.x, u1.x, u2.x, u3.x };
                uint32_t al[4] = { u0.y, u1.y, u2.y, u3.y };
#pragma unroll
                for (int ni = 0; ni < 4; ni++) {
                    float* cc = acc + (mi * 4 + ni) * 4;
                    mma_bf16(cc, ah, bh[ni]);
                    mma_bf16(cc, ah, bl[ni]);
                    mma_bf16(cc, al, bh[ni]);
                }
            }
        }
    }

    int b = bh >> 4, h = bh & 15;
#pragma unroll
    for (int mi = 0; mi < 2; mi++)
#pragma unroll
        for (int ni = 0; ni < 4; ni++) {
            const float* c = acc + (mi * 4 + ni) * 4;
            int col0 = wn0 + ni * 8 + 2 * tq;
            int r0 = wm0 + mi * 16 + g;
            size_t tok0 = (size_t)b * S_LEN + m0 + r0;
            ((uint2*)g_aos4)[tok0 * 512 + (h * 64 + col0) / 2] = limb2(c[0], c[1]);
            ((uint2*)g_aos4)[(tok0 + 8) * 512 + (h * 64 + col0) / 2] = limb2(c[2], c[3]);
        }
}

// ---------------- O projection (proven) ----------------
#define OP_SMEM (2 * (128 + 128) * PADB * 8)
__global__ __launch_bounds__(256, 2) void oproj_kernel(
    const float* __restrict__ bias, float* __restrict__ out)
{
    extern __shared__ char smem[];
    uint32_t su = smem_u32(smem);
    int n0 = blockIdx.x * 128, m0 = blockIdx.y * 128;

    float acc[64];
#pragma unroll
    for (int i = 0; i < 64; i++) acc[i] = 0.f;

    gemm_async_bf16<128, 128, 2, 4, 4, 4>(
        (const uint2*)g_aos4 + (size_t)m0 * 512, 512,
        (const uint2*)g_wo4 + (size_t)n0 * 512, 512, EMB, smem, su, acc);

    epilogue<128, 128, 2, 4, 4, 4>(acc, [&](int row, int col, float val) {
        int token = m0 + row, o = n0 + col;
        out[(size_t)token * EMB + o] = val + bias[o];
    });
}

// ---------------- launch ----------------
extern "C" void kernel_launch(void* const* d_in, const int* in_sizes, int n_in,
                              void* d_out, int out_size)
{
    const float* x = (const float*)d_in[0];
    const int* qw[4];
    const float *sc[4], *zr[4], *bs[4];
    for (int p = 0; p < 4; p++) {
        qw[p] = (const int*)d_in[1 + 4 * p];
        sc[p] = (const float*)d_in[2 + 4 * p];
        zr[p] = (const float*)d_in[3 + 4 * p];
        bs[p] = (const float*)d_in[4 + 4 * p];
    }
    float* out = (float*)d_out;                 // [B,S,E]
    float* attn = out + (size_t)4194304;        // [B,H,S,S]

    cudaFuncSetAttribute(proj_qkv_kernel, cudaFuncAttributeMaxDynamicSharedMemorySize, QKV_SMEM);
    cudaFuncSetAttribute(scores_kernel,   cudaFuncAttributeMaxDynamicSharedMemorySize, SC_SMEM);
    cudaFuncSetAttribute(pv_kernel,       cudaFuncAttributeMaxDynamicSharedMemorySize, PV_SMEM);
    cudaFuncSetAttribute(oproj_kernel,    cudaFuncAttributeMaxDynamicSharedMemorySize, OP_SMEM);

    x_split_kernel<<<8192, 256>>>(x);
    xg_kernel<<<4096, 256>>>(x);
    for (int p = 0; p < 3; p++) {
        pack_qwl_kernel<<<2048, 256>>>(qw[p], p);
        pack_scale_kernel<<<64, 256>>>(sc[p], zr[p], p);
    }
    dequant_o_kernel<<<1024, 256>>>(qw[3], sc[3], zr[3]);

    proj_qkv_kernel<<<dim3(16, 32, 3), 256, QKV_SMEM>>>(bs[0], bs[1], bs[2]);
    scores_kernel<<<dim3(16, 16, 32), 256, SC_SMEM>>>(attn);
    softmax_kernel<<<65536, 256>>>(attn);
    pv_kernel<<<dim3(1, 16, 32), 256, PV_SMEM>>>(attn);
    oproj_kernel<<<dim3(8, 32), 256, OP_SMEM>>>(bs[3], out);
}

// round 15
// speedup vs baseline: 3.3429x; 1.0087x over previous
#include <cuda_runtime.h>
#include <cuda_bf16.h>
#include <cuda_fp16.h>
#include <cstdint>
#include <cstddef>

#define DEV __device__ __forceinline__

#define S_LEN 2048
#define EMB   1024
#define PADB  10          // uint2 per SMEM row (8 data + 2 pad)   = 80 B

// ---------------- scratch (16B-aligned) ----------------
__device__ uint4  g_xbf4[4096 * 1024 / 4];           // x bf16 limb pairs [t][e/2]
__device__ __align__(16) float g_xg[4096 * 16];      // group sums of x [t][g]
__device__ uint4  g_wqkvl4[3][1024 * 1024 / 4];      // qw as (bf16 pair, 0) limb uint2 [o][e/2]
__device__ __align__(16) float g_s[3][1024 * 16];    // scales [o][g]
__device__ __align__(16) float g_sz[3][1024 * 16];   // scale*zero [o][g]
__device__ uint4  g_wo4[1024 * 1024 / 4];            // o weights bf16 limb pairs
__device__ uint4  g_qh4[32 * 2048 * 64 / 4];         // q fp16 limb pairs [bh][s][d/2]
__device__ uint4  g_kh4[32 * 2048 * 64 / 4];         // k fp16 limb pairs
__device__ uint4  g_vts4[32 * 64 * 2048 / 4];        // v^T fp16 limbs [bh][d][s/2]
__device__ uint4  g_aos4[4096 * 1024 / 4];           // attn-out bf16 limbs [tok][e/2]

DEV uint32_t smem_u32(const void* p) {
    uint32_t a;
    asm("{ .reg .u64 t; cvta.to.shared.u64 t, %1; cvt.u32.u64 %0, t; }" : "=r"(a) : "l"(p));
    return a;
}
DEV void cp16(uint32_t dst, const void* src) {
    asm volatile("cp.async.cg.shared.global [%0], [%1], 16;" :: "r"(dst), "l"(src));
}
DEV void cp_commit() { asm volatile("cp.async.commit_group;" ::: "memory"); }
template<int N> DEV void cp_wait() { asm volatile("cp.async.wait_group %0;" :: "n"(N) : "memory"); }

DEV void mma_bf16(float* c, const uint32_t* a, const uint32_t* b) {
    asm volatile(
        "mma.sync.aligned.m16n8k16.row.col.f32.bf16.bf16.f32 "
        "{%0,%1,%2,%3}, {%4,%5,%6,%7}, {%8,%9}, {%0,%1,%2,%3};"
        : "+f"(c[0]), "+f"(c[1]), "+f"(c[2]), "+f"(c[3])
        : "r"(a[0]), "r"(a[1]), "r"(a[2]), "r"(a[3]), "r"(b[0]), "r"(b[1]));
}
DEV void mma_fp16(float* c, const uint32_t* a, const uint32_t* b) {
    asm volatile(
        "mma.sync.aligned.m16n8k16.row.col.f32.f16.f16.f32 "
        "{%0,%1,%2,%3}, {%4,%5,%6,%7}, {%8,%9}, {%0,%1,%2,%3};"
        : "+f"(c[0]), "+f"(c[1]), "+f"(c[2]), "+f"(c[3])
        : "r"(a[0]), "r"(a[1]), "r"(a[2]), "r"(a[3]), "r"(b[0]), "r"(b[1]));
}

DEV uint32_t pack_bf16(float a, float b) {
    uint32_t r;
    asm("cvt.rn.bf16x2.f32 %0, %1, %2;" : "=r"(r) : "f"(b), "f"(a));
    return r;
}
DEV void split_bf(float v, float& hi, float& lo) {
    hi = __bfloat162float(__float2bfloat16(v));
    lo = v - hi;
}
DEV uint2 limb2(float a, float b) {
    float ha, la, hb, lb;
    split_bf(a, ha, la); split_bf(b, hb, lb);
    return make_uint2(pack_bf16(ha, hb), pack_bf16(la, lb));
}

DEV uint32_t pack_h2(float a, float b) {
    uint32_t r;
    asm("cvt.rn.f16x2.f32 %0, %1, %2;" : "=r"(r) : "f"(b), "f"(a));
    return r;
}
DEV void split_h(float v, float& hi, float& lo) {
    hi = __half2float(__float2half(v));
    lo = v - hi;
}
DEV uint2 limb2h(float a, float b) {
    float ha, la, hb, lb;
    split_h(a, ha, la); split_h(b, hb, lb);
    return make_uint2(pack_h2(ha, hb), pack_h2(la, lb));
}

// ---------------- async 2-limb bf16 x3 GEMM (proven) ----------------
template<int BM, int BN, int WM, int WN, int MT, int NT>
DEV void gemm_async_bf16(const uint2* __restrict__ A, int lda,
                         const uint2* __restrict__ B, int ldb,
                         int K, char* smem, uint32_t su, float* acc)
{
    const int tid = threadIdx.x;
    const int lane = tid & 31, wid = tid >> 5;
    const int g = lane >> 2, tq = lane & 3;
    const int wm0 = (wid / WN) * (BM / WM);
    const int wn0 = (wid % WN) * (BN / WN);

    constexpr int SA = BM * PADB * 8;
    constexpr int STAGE = SA + BN * PADB * 8;

    auto copy_chunk = [&](int c, int s) {
        uint32_t base = su + s * STAGE;
#pragma unroll
        for (int t = 0; t < BM * 4 / 256; t++) {
            int idx = tid + t * 256; int r = idx >> 2, j = idx & 3;
            cp16(base + r * 80 + j * 16, A + (size_t)r * lda + c * 8 + j * 2);
        }
#pragma unroll
        for (int t = 0; t < (BN * 4 + 255) / 256; t++) {
            int idx = tid + t * 256;
            if (BN * 4 % 256 == 0 || idx < BN * 4) {
                int r = idx >> 2, j = idx & 3;
                cp16(base + SA + r * 80 + j * 16, B + (size_t)r * ldb + c * 8 + j * 2);
            }
        }
        cp_commit();
    };
    auto compute = [&](int s) {
        const uint2* Ab = (const uint2*)(smem + s * STAGE);
        const uint2* Bb = (const uint2*)(smem + s * STAGE + SA);
        uint32_t bh[NT][2], bl[NT][2];
#pragma unroll
        for (int ni = 0; ni < NT; ni++) {
            int n0 = wn0 + ni * 8 + g;
            uint2 w0 = Bb[n0 * PADB + tq];
            uint2 w1 = Bb[n0 * PADB + tq + 4];
            bh[ni][0] = w0.x; bl[ni][0] = w0.y;
            bh[ni][1] = w1.x; bl[ni][1] = w1.y;
        }
#pragma unroll
        for (int mi = 0; mi < MT; mi++) {
            int r0 = wm0 + mi * 16 + g;
            uint2 v0 = Ab[r0 * PADB + tq];
            uint2 v1 = Ab[(r0 + 8) * PADB + tq];
            uint2 v2 = Ab[r0 * PADB + tq + 4];
            uint2 v3 = Ab[(r0 + 8) * PADB + tq + 4];
            uint32_t ah[4] = { v0.x, v1.x, v2.x, v3.x };
            uint32_t al[4] = { v0.y, v1.y, v2.y, v3.y };
#pragma unroll
            for (int ni = 0; ni < NT; ni++) {
                float* c = acc + (mi * NT + ni) * 4;
                mma_bf16(c, ah, bh[ni]);
                mma_bf16(c, ah, bl[ni]);
                mma_bf16(c, al, bh[ni]);
            }
        }
    };

    int nc = K >> 4;
    copy_chunk(0, 0);
    for (int c = 0; c < nc; c++) {
        cp_wait<0>();
        __syncthreads();
        if (c + 1 < nc) copy_chunk(c + 1, (c + 1) & 1);
        compute(c & 1);
    }
}

// ---------------- async 2-limb fp16 x3 GEMM (proven R13) ----------------
template<int BM, int BN, int WM, int WN, int MT, int NT>
DEV void gemm_async_fp16(const uint2* __restrict__ A, int lda,
                         const uint2* __restrict__ B, int ldb,
                         int K, char* smem, uint32_t su, float* acc)
{
    const int tid = threadIdx.x;
    const int lane = tid & 31, wid = tid >> 5;
    const int g = lane >> 2, tq = lane & 3;
    const int wm0 = (wid / WN) * (BM / WM);
    const int wn0 = (wid % WN) * (BN / WN);

    constexpr int SA = BM * PADB * 8;
    constexpr int STAGE = SA + BN * PADB * 8;

    auto copy_chunk = [&](int c, int s) {
        uint32_t base = su + s * STAGE;
#pragma unroll
        for (int t = 0; t < BM * 4 / 256; t++) {
            int idx = tid + t * 256; int r = idx >> 2, j = idx & 3;
            cp16(base + r * 80 + j * 16, A + (size_t)r * lda + c * 8 + j * 2);
        }
#pragma unroll
        for (int t = 0; t < (BN * 4 + 255) / 256; t++) {
            int idx = tid + t * 256;
            if (BN * 4 % 256 == 0 || idx < BN * 4) {
                int r = idx >> 2, j = idx & 3;
                cp16(base + SA + r * 80 + j * 16, B + (size_t)r * ldb + c * 8 + j * 2);
            }
        }
        cp_commit();
    };
    auto compute = [&](int s) {
        const uint2* Ab = (const uint2*)(smem + s * STAGE);
        const uint2* Bb = (const uint2*)(smem + s * STAGE + SA);
        uint32_t bh[NT][2], bl[NT][2];
#pragma unroll
        for (int ni = 0; ni < NT; ni++) {
            int n0 = wn0 + ni * 8 + g;
            uint2 w0 = Bb[n0 * PADB + tq];
            uint2 w1 = Bb[n0 * PADB + tq + 4];
            bh[ni][0] = w0.x; bl[ni][0] = w0.y;
            bh[ni][1] = w1.x; bl[ni][1] = w1.y;
        }
#pragma unroll
        for (int mi = 0; mi < MT; mi++) {
            int r0 = wm0 + mi * 16 + g;
            uint2 v0 = Ab[r0 * PADB + tq];
            uint2 v1 = Ab[(r0 + 8) * PADB + tq];
            uint2 v2 = Ab[r0 * PADB + tq + 4];
            uint2 v3 = Ab[(r0 + 8) * PADB + tq + 4];
            uint32_t ah[4] = { v0.x, v1.x, v2.x, v3.x };
            uint32_t al[4] = { v0.y, v1.y, v2.y, v3.y };
#pragma unroll
            for (int ni = 0; ni < NT; ni++) {
                float* c = acc + (mi * NT + ni) * 4;
                mma_fp16(c, ah, bh[ni]);
                mma_fp16(c, ah, bl[ni]);
                mma_fp16(c, al, bh[ni]);
            }
        }
    };

    int nc = K >> 4;
    copy_chunk(0, 0);
    for (int c = 0; c < nc; c++) {
        cp_wait<0>();
        __syncthreads();
        if (c + 1 < nc) copy_chunk(c + 1, (c + 1) & 1);
        compute(c & 1);
    }
}

// epilogue iteration
template<int BM, int BN, int WM, int WN, int MT, int NT, typename F>
DEV void epilogue(const float* acc, F fn)
{
    int lane = threadIdx.x & 31, wid = threadIdx.x >> 5;
    int g = lane >> 2, tq = lane & 3;
    int wm0 = (wid / WN) * (BM / WM);
    int wn0 = (wid % WN) * (BN / WN);
#pragma unroll
    for (int mi = 0; mi < MT; mi++)
#pragma unroll
        for (int ni = 0; ni < NT; ni++)
#pragma unroll
            for (int cj = 0; cj < 4; cj++) {
                int row = wm0 + mi * 16 + g + ((cj >= 2) ? 8 : 0);
                int col = wn0 + ni * 8 + 2 * tq + (cj & 1);
                fn(row, col, acc[(mi * NT + ni) * 4 + cj]);
            }
}

// ---------------- prep kernels ----------------
__global__ __launch_bounds__(256) void x_split_kernel(const float* __restrict__ x)
{
    int idx = blockIdx.x * 256 + threadIdx.x;
    ((uint2*)g_xbf4)[idx] = limb2(x[2 * idx], x[2 * idx + 1]);
}

__global__ __launch_bounds__(256) void xg_kernel(const float* __restrict__ x)
{
    int t = blockIdx.x;
    int tid = threadIdx.x;
    float4 v = ((const float4*)(x + (size_t)t * EMB))[tid];
    float p = v.x + v.y + v.z + v.w;
#pragma unroll
    for (int o = 8; o > 0; o >>= 1) p += __shfl_down_sync(0xffffffffu, p, o, 16);
    if ((tid & 15) == 0) g_xg[t * 16 + (tid >> 4)] = p;
}

__global__ __launch_bounds__(256) void pack_qwl_kernel(const int* __restrict__ qw, int mode)
{
    int idx = blockIdx.x * 256 + threadIdx.x;
    ((uint2*)g_wqkvl4[mode])[idx] =
        make_uint2(pack_bf16((float)qw[2 * idx], (float)qw[2 * idx + 1]), 0u);
}
__global__ __launch_bounds__(256) void pack_scale_kernel(
    const float* __restrict__ sc, const float* __restrict__ zr, int mode)
{
    int idx = blockIdx.x * 256 + threadIdx.x;
    float s = sc[idx];
    g_s[mode][idx] = s;
    g_sz[mode][idx] = s * zr[idx];
}

__global__ __launch_bounds__(256) void dequant_o_kernel(
    const int* __restrict__ qw, const float* __restrict__ sc,
    const float* __restrict__ zr)
{
    int idx4 = (blockIdx.x * 256 + threadIdx.x) * 4;
    int o = idx4 >> 10, i = idx4 & 1023, grp = i >> 6;
    float s = sc[o * 16 + grp], z = zr[o * 16 + grp];
    uint2* dst = (uint2*)g_wo4 + (idx4 >> 1);
    dst[0] = limb2(((float)qw[idx4 + 0] - z) * s, ((float)qw[idx4 + 1] - z) * s);
    dst[1] = limb2(((float)qw[idx4 + 2] - z) * s, ((float)qw[idx4 + 3] - z) * s);
}

// ---------------- QKV projection (proven R12/R13) ----------------
#define QKV_SMEM 33792
__global__ __launch_bounds__(256, 2) void proj_qkv_kernel(
    const float* __restrict__ bq, const float* __restrict__ bk,
    const float* __restrict__ bv)
{
    extern __shared__ char smem[];
    uint32_t su = smem_u32(smem);
    const int tid = threadIdx.x;
    const int lane = tid & 31, wid = tid >> 5;
    const int g = lane >> 2, tq = lane & 3;
    const int wm0 = (wid / 2) * 32;
    const int wn0 = (wid % 2) * 32;

    int mode = blockIdx.z;
    int n0 = blockIdx.x * 64, m0 = blockIdx.y * 128;
    const float* bias = mode == 0 ? bq : (mode == 1 ? bk : bv);

    const uint2* A = (const uint2*)g_xbf4 + (size_t)m0 * 512;
    const uint2* B = (const uint2*)g_wqkvl4[mode] + (size_t)n0 * 512;
    const float* sarr = g_s[mode];
    const float* szarr = g_sz[mode];

    constexpr int SA = 128 * PADB * 8;
    constexpr int STAGE = SA + 64 * PADB * 8;

    auto copy_chunk = [&](int c, int s) {
        uint32_t base = su + s * STAGE;
#pragma unroll
        for (int t = 0; t < 2; t++) {
            int idx = tid + t * 256; int r = idx >> 2, j = idx & 3;
            cp16(base + r * 80 + j * 16, A + (size_t)r * 512 + c * 8 + j * 2);
        }
        {
            int r = tid >> 2, j = tid & 3;
            cp16(base + SA + r * 80 + j * 16, B + (size_t)r * 512 + c * 8 + j * 2);
        }
        cp_commit();
    };

    float master[32], tmp[32];
#pragma unroll
    for (int i = 0; i < 32; i++) { master[i] = 0.f; tmp[i] = 0.f; }

    copy_chunk(0, 0);
    for (int c = 0; c < 64; c++) {
        cp_wait<0>();
        __syncthreads();
        if (c + 1 < 64) copy_chunk(c + 1, (c + 1) & 1);
        {
            const uint2* Ab = (const uint2*)(smem + (c & 1) * STAGE);
            const uint2* Bb = (const uint2*)(smem + (c & 1) * STAGE + SA);
            uint32_t bh[4][2];
#pragma unroll
            for (int ni = 0; ni < 4; ni++) {
                int n = wn0 + ni * 8 + g;
                uint2 w0 = Bb[n * PADB + tq];
                uint2 w1 = Bb[n * PADB + tq + 4];
                bh[ni][0] = w0.x;
                bh[ni][1] = w1.x;
            }
#pragma unroll
            for (int mi = 0; mi < 2; mi++) {
                int r0 = wm0 + mi * 16 + g;
                uint2 v0 = Ab[r0 * PADB + tq];
                uint2 v1 = Ab[(r0 + 8) * PADB + tq];
                uint2 v2 = Ab[r0 * PADB + tq + 4];
                uint2 v3 = Ab[(r0 + 8) * PADB + tq + 4];
                uint32_t ah[4] = { v0.x, v1.x, v2.x, v3.x };
                uint32_t al[4] = { v0.y, v1.y, v2.y, v3.y };
#pragma unroll
                for (int ni = 0; ni < 4; ni++) {
                    float* cc = tmp + (mi * 4 + ni) * 4;
                    mma_bf16(cc, ah, bh[ni]);
                    mma_bf16(cc, al, bh[ni]);
                }
            }
        }
        if ((c & 3) == 3) {
            int grp = c >> 2;
#pragma unroll
            for (int ni = 0; ni < 4; ni++) {
                int c0 = n0 + wn0 + ni * 8 + 2 * tq;
                float s0 = __ldg(&sarr[c0 * 16 + grp]);
                float s1 = __ldg(&sarr[(c0 + 1) * 16 + grp]);
#pragma unroll
                for (int mi = 0; mi < 2; mi++) {
                    float* mm = master + (mi * 4 + ni) * 4;
                    float* tt = tmp + (mi * 4 + ni) * 4;
                    mm[0] = fmaf(s0, tt[0], mm[0]);
                    mm[1] = fmaf(s1, tt[1], mm[1]);
                    mm[2] = fmaf(s0, tt[2], mm[2]);
                    mm[3] = fmaf(s1, tt[3], mm[3]);
                    tt[0] = 0.f; tt[1] = 0.f; tt[2] = 0.f; tt[3] = 0.f;
                }
            }
        }
    }

    for (int grp = 0; grp < 16; grp++) {
        float xr[2][2];
#pragma unroll
        for (int mi = 0; mi < 2; mi++) {
            int r0 = m0 + wm0 + mi * 16 + g;
            xr[mi][0] = __ldg(&g_xg[r0 * 16 + grp]);
            xr[mi][1] = __ldg(&g_xg[(r0 + 8) * 16 + grp]);
        }
#pragma unroll
        for (int ni = 0; ni < 4; ni++) {
            int c0 = n0 + wn0 + ni * 8 + 2 * tq;
            float z0 = __ldg(&szarr[c0 * 16 + grp]);
            float z1 = __ldg(&szarr[(c0 + 1) * 16 + grp]);
#pragma unroll
            for (int mi = 0; mi < 2; mi++) {
                float* mm = master + (mi * 4 + ni) * 4;
                mm[0] = fmaf(-z0, xr[mi][0], mm[0]);
                mm[1] = fmaf(-z1, xr[mi][0], mm[1]);
                mm[2] = fmaf(-z0, xr[mi][1], mm[2]);
                mm[3] = fmaf(-z1, xr[mi][1], mm[3]);
            }
        }
    }

    if (mode < 2) {
        uint2* dst = mode == 0 ? (uint2*)g_qh4 : (uint2*)g_kh4;
#pragma unroll
        for (int mi = 0; mi < 2; mi++)
#pragma unroll
            for (int ni = 0; ni < 4; ni++) {
                const float* c = master + (mi * 4 + ni) * 4;
                int col0 = wn0 + ni * 8 + 2 * tq;
                int r0 = wm0 + mi * 16 + g;
                int token = m0 + r0;
                int b = token >> 11, si = token & 2047;
                int o0 = n0 + col0;
                int h = o0 >> 6, d0 = o0 & 63;
                float b0 = bias[o0], b1 = bias[o0 + 1];
                size_t base = ((size_t)(b * 16 + h) * S_LEN + si) * 32 + (d0 >> 1);
                dst[base] = limb2h(c[0] + b0, c[1] + b1);
                dst[base + 8 * 32] = limb2h(c[2] + b0, c[3] + b1);
            }
    } else {
        __syncthreads();
        float* T = (float*)smem;
        int b = m0 >> 11, si0 = m0 & 2047;
        epilogue<128, 64, 4, 2, 2, 4>(master, [&](int row, int col, float val) {
            T[col * 132 + row] = val + bias[n0 + col];
        });
        __syncthreads();
        for (int i = threadIdx.x; i < 64 * 64; i += 256) {
            int cl = i >> 6, sp = i & 63;
            int o = n0 + cl; int h = o >> 6, d = o & 63;
            uint2 v = limb2h(T[cl * 132 + 2 * sp], T[cl * 132 + 2 * sp + 1]);   // fp16 limbs now
            ((uint2*)g_vts4)[((size_t)(b * 16 + h) * 64 + d) * 1024 + ((si0 + 2 * sp) >> 1)] = v;
        }
    }
}

// ---------------- scores (2-limb fp16 x3, proven R13) ----------------
#define SC_SMEM (2 * (128 + 128) * PADB * 8)
__global__ __launch_bounds__(256, 2) void scores_kernel(float* __restrict__ attn)
{
    extern __shared__ char smem[];
    uint32_t su = smem_u32(smem);
    int bh = blockIdx.z;
    int n0 = blockIdx.x * 128, m0 = blockIdx.y * 128;
    size_t base = (size_t)bh * S_LEN * 32;

    float acc[64];
#pragma unroll
    for (int i = 0; i < 64; i++) acc[i] = 0.f;

    gemm_async_fp16<128, 128, 2, 4, 4, 4>(
        (const uint2*)g_qh4 + base + (size_t)m0 * 32, 32,
        (const uint2*)g_kh4 + base + (size_t)n0 * 32, 32, 64, smem, su, acc);

    float* out = attn + (size_t)bh * S_LEN * S_LEN;
    epilogue<128, 128, 2, 4, 4, 4>(acc, [&](int row, int col, float val) {
        out[(size_t)(m0 + row) * S_LEN + n0 + col] = val * 0.125f;
    });
}

// ---------------- softmax (in place, fp32 only, proven R14) ----------------
__global__ __launch_bounds__(256) void softmax_kernel(float* __restrict__ S)
{
    size_t row = blockIdx.x;
    float4* p4 = (float4*)(S + row * S_LEN);
    int t = threadIdx.x;
    float4 u0 = p4[2 * t], u1 = p4[2 * t + 1];
    float v[8] = { u0.x, u0.y, u0.z, u0.w, u1.x, u1.y, u1.z, u1.w };
    float m = v[0];
#pragma unroll
    for (int i = 1; i < 8; i++) m = fmaxf(m, v[i]);
#pragma unroll
    for (int o = 16; o > 0; o >>= 1) m = fmaxf(m, __shfl_xor_sync(0xffffffffu, m, o));
    __shared__ float sred[8]; __shared__ float sbc;
    if ((t & 31) == 0) sred[t >> 5] = m;
    __syncthreads();
    if (t == 0) {
        float x = sred[0];
#pragma unroll
        for (int i = 1; i < 8; i++) x = fmaxf(x, sred[i]);
        sbc = x;
    }
    __syncthreads();
    m = sbc;
    float sum = 0.f;
#pragma unroll
    for (int i = 0; i < 8; i++) { v[i] = __expf(v[i] - m); sum += v[i]; }
#pragma unroll
    for (int o = 16; o > 0; o >>= 1) sum += __shfl_xor_sync(0xffffffffu, sum, o);
    __syncthreads();
    if ((t & 31) == 0) sred[t >> 5] = sum;
    __syncthreads();
    if (t == 0) {
        float x = 0.f;
#pragma unroll
        for (int i = 0; i < 8; i++) x += sred[i];
        sbc = 1.0f / x;
    }
    __syncthreads();
    float inv = sbc;
    p4[2 * t]     = make_float4(v[0] * inv, v[1] * inv, v[2] * inv, v[3] * inv);
    p4[2 * t + 1] = make_float4(v[4] * inv, v[5] * inv, v[6] * inv, v[7] * inv);
}

// ---------------- PV: A = fp32 P -> fp16 hi (in-register), B = V^T fp16 limbs, 2 products ----------------
#define PV_SMEM (2 * (128 + 64) * PADB * 8)
__global__ __launch_bounds__(256, 2) void pv_kernel(const float* __restrict__ attn)
{
    extern __shared__ char smem[];
    uint32_t su = smem_u32(smem);
    const int tid = threadIdx.x;
    const int lane = tid & 31, wid = tid >> 5;
    const int g = lane >> 2, tq = lane & 3;
    const int wm0 = (wid / 2) * 32;             // WM=4
    const int wn0 = (wid % 2) * 32;             // WN=2
    int bh = blockIdx.z;
    int m0 = blockIdx.y * 128;

    const float* Af = attn + (size_t)bh * S_LEN * S_LEN + (size_t)m0 * S_LEN;
    const uint2* B = (const uint2*)g_vts4 + (size_t)bh * 64 * 1024;

    constexpr int SA = 128 * 80;
    constexpr int STAGE = SA + 64 * 80;

    auto copy_chunk = [&](int c, int s) {
        uint32_t base = su + s * STAGE;
#pragma unroll
        for (int t = 0; t < 2; t++) {
            int idx = tid + t * 256; int r = idx >> 2, j = idx & 3;
            cp16(base + r * 80 + j * 16, Af + (size_t)r * S_LEN + c * 16 + j * 4);
        }
        {
            int r = tid >> 2, j = tid & 3;
            cp16(base + SA + r * 80 + j * 16, B + (size_t)r * 1024 + c * 8 + j * 2);
        }
        cp_commit();
    };

    float acc[32];
#pragma unroll
    for (int i = 0; i < 32; i++) acc[i] = 0.f;

    copy_chunk(0, 0);
    for (int c = 0; c < 128; c++) {
        cp_wait<0>();
        __syncthreads();
        if (c + 1 < 128) copy_chunk(c + 1, (c + 1) & 1);
        {
            const float* Ab = (const float*)(smem + (c & 1) * STAGE);
            const uint2* Bb = (const uint2*)(smem + (c & 1) * STAGE + SA);
            uint32_t bh[4][2], bl[4][2];
#pragma unroll
            for (int ni = 0; ni < 4; ni++) {
                int n = wn0 + ni * 8 + g;
                uint2 w0 = Bb[n * PADB + tq];
                uint2 w1 = Bb[n * PADB + tq + 4];
                bh[ni][0] = w0.x; bl[ni][0] = w0.y;
                bh[ni][1] = w1.x; bl[ni][1] = w1.y;
            }
#pragma unroll
            for (int mi = 0; mi < 2; mi++) {
                int r0 = wm0 + mi * 16 + g;
                float2 a0 = ((const float2*)(Ab + r0 * 20))[tq];
                float2 a1 = ((const float2*)(Ab + (r0 + 8) * 20))[tq];
                float2 a2 = ((const float2*)(Ab + r0 * 20 + 8))[tq];
                float2 a3 = ((const float2*)(Ab + (r0 + 8) * 20 + 8))[tq];
                uint32_t ah[4] = { pack_h2(a0.x, a0.y), pack_h2(a1.x, a1.y),
                                   pack_h2(a2.x, a2.y), pack_h2(a3.x, a3.y) };
#pragma unroll
                for (int ni = 0; ni < 4; ni++) {
                    float* cc = acc + (mi * 4 + ni) * 4;
                    mma_fp16(cc, ah, bh[ni]);
                    mma_fp16(cc, ah, bl[ni]);
                }
            }
        }
    }

    int b = bh >> 4, h = bh & 15;
#pragma unroll
    for (int mi = 0; mi < 2; mi++)
#pragma unroll
        for (int ni = 0; ni < 4; ni++) {
            const float* c = acc + (mi * 4 + ni) * 4;
            int col0 = wn0 + ni * 8 + 2 * tq;
            int r0 = wm0 + mi * 16 + g;
            size_t tok0 = (size_t)b * S_LEN + m0 + r0;
            ((uint2*)g_aos4)[tok0 * 512 + (h * 64 + col0) / 2] = limb2(c[0], c[1]);
            ((uint2*)g_aos4)[(tok0 + 8) * 512 + (h * 64 + col0) / 2] = limb2(c[2], c[3]);
        }
}

// ---------------- O projection (proven) ----------------
#define OP_SMEM (2 * (128 + 128) * PADB * 8)
__global__ __launch_bounds__(256, 2) void oproj_kernel(
    const float* __restrict__ bias, float* __restrict__ out)
{
    extern __shared__ char smem[];
    uint32_t su = smem_u32(smem);
    int n0 = blockIdx.x * 128, m0 = blockIdx.y * 128;

    float acc[64];
#pragma unroll
    for (int i = 0; i < 64; i++) acc[i] = 0.f;

    gemm_async_bf16<128, 128, 2, 4, 4, 4>(
        (const uint2*)g_aos4 + (size_t)m0 * 512, 512,
        (const uint2*)g_wo4 + (size_t)n0 * 512, 512, EMB, smem, su, acc);

    epilogue<128, 128, 2, 4, 4, 4>(acc, [&](int row, int col, float val) {
        int token = m0 + row, o = n0 + col;
        out[(size_t)token * EMB + o] = val + bias[o];
    });
}

// ---------------- launch ----------------
extern "C" void kernel_launch(void* const* d_in, const int* in_sizes, int n_in,
                              void* d_out, int out_size)
{
    const float* x = (const float*)d_in[0];
    const int* qw[4];
    const float *sc[4], *zr[4], *bs[4];
    for (int p = 0; p < 4; p++) {
        qw[p] = (const int*)d_in[1 + 4 * p];
        sc[p] = (const float*)d_in[2 + 4 * p];
        zr[p] = (const float*)d_in[3 + 4 * p];
        bs[p] = (const float*)d_in[4 + 4 * p];
    }
    float* out = (float*)d_out;                 // [B,S,E]
    float* attn = out + (size_t)4194304;        // [B,H,S,S]

    cudaFuncSetAttribute(proj_qkv_kernel, cudaFuncAttributeMaxDynamicSharedMemorySize, QKV_SMEM);
    cudaFuncSetAttribute(scores_kernel,   cudaFuncAttributeMaxDynamicSharedMemorySize, SC_SMEM);
    cudaFuncSetAttribute(pv_kernel,       cudaFuncAttributeMaxDynamicSharedMemorySize, PV_SMEM);
    cudaFuncSetAttribute(oproj_kernel,    cudaFuncAttributeMaxDynamicSharedMemorySize, OP_SMEM);

    x_split_kernel<<<8192, 256>>>(x);
    xg_kernel<<<4096, 256>>>(x);
    for (int p = 0; p < 3; p++) {
        pack_qwl_kernel<<<2048, 256>>>(qw[p], p);
        pack_scale_kernel<<<64, 256>>>(sc[p], zr[p], p);
    }
    dequant_o_kernel<<<1024, 256>>>(qw[3], sc[3], zr[3]);

    proj_qkv_kernel<<<dim3(16, 32, 3), 256, QKV_SMEM>>>(bs[0], bs[1], bs[2]);
    scores_kernel<<<dim3(16, 16, 32), 256, SC_SMEM>>>(attn);
    softmax_kernel<<<65536, 256>>>(attn);
    pv_kernel<<<dim3(1, 16, 32), 256, PV_SMEM>>>(attn);
    oproj_kernel<<<dim3(8, 32), 256, OP_SMEM>>>(bs[3], out);
}

// round 16
// speedup vs baseline: 3.4773x; 1.0402x over previous
#include <cuda_runtime.h>
#include <cuda_bf16.h>
#include <cuda_fp16.h>
#include <cstdint>
#include <cstddef>

#define DEV __device__ __forceinline__

#define S_LEN 2048
#define EMB   1024
#define PADB  10          // uint2 per SMEM row (8 data + 2 pad)   = 80 B

// ---------------- scratch (16B-aligned) ----------------
__device__ uint4  g_xbf4[4096 * 1024 / 4];           // x bf16 limb pairs [t][e/2]
__device__ __align__(16) float g_xg[4096 * 16];      // group sums of x [t][g]
__device__ uint4  g_wqkvl4[3][1024 * 1024 / 4];      // qw as (bf16 pair, 0) limb uint2 [o][e/2]
__device__ __align__(16) float g_s[3][1024 * 16];    // scales [o][g]
__device__ __align__(16) float g_sz[3][1024 * 16];   // scale*zero [o][g]
__device__ uint4  g_wo4[1024 * 1024 / 4];            // o weights bf16 limb pairs
__device__ uint4  g_qh4[32 * 2048 * 64 / 4];         // q fp16 limb pairs [bh][s][d/2]
__device__ uint4  g_kh4[32 * 2048 * 64 / 4];         // k fp16 limb pairs
__device__ uint4  g_vts4[32 * 64 * 2048 / 4];        // v^T fp16 limbs [bh][d][s/2]
__device__ uint4  g_aos4[4096 * 1024 / 4];           // attn-out bf16 limbs [tok][e/2]

DEV uint32_t smem_u32(const void* p) {
    uint32_t a;
    asm("{ .reg .u64 t; cvta.to.shared.u64 t, %1; cvt.u32.u64 %0, t; }" : "=r"(a) : "l"(p));
    return a;
}
DEV void cp16(uint32_t dst, const void* src) {
    asm volatile("cp.async.cg.shared.global [%0], [%1], 16;" :: "r"(dst), "l"(src));
}
DEV void cp_commit() { asm volatile("cp.async.commit_group;" ::: "memory"); }
template<int N> DEV void cp_wait() { asm volatile("cp.async.wait_group %0;" :: "n"(N) : "memory"); }

DEV void mma_bf16(float* c, const uint32_t* a, const uint32_t* b) {
    asm volatile(
        "mma.sync.aligned.m16n8k16.row.col.f32.bf16.bf16.f32 "
        "{%0,%1,%2,%3}, {%4,%5,%6,%7}, {%8,%9}, {%0,%1,%2,%3};"
        : "+f"(c[0]), "+f"(c[1]), "+f"(c[2]), "+f"(c[3])
        : "r"(a[0]), "r"(a[1]), "r"(a[2]), "r"(a[3]), "r"(b[0]), "r"(b[1]));
}
DEV void mma_fp16(float* c, const uint32_t* a, const uint32_t* b) {
    asm volatile(
        "mma.sync.aligned.m16n8k16.row.col.f32.f16.f16.f32 "
        "{%0,%1,%2,%3}, {%4,%5,%6,%7}, {%8,%9}, {%0,%1,%2,%3};"
        : "+f"(c[0]), "+f"(c[1]), "+f"(c[2]), "+f"(c[3])
        : "r"(a[0]), "r"(a[1]), "r"(a[2]), "r"(a[3]), "r"(b[0]), "r"(b[1]));
}

DEV uint32_t pack_bf16(float a, float b) {
    uint32_t r;
    asm("cvt.rn.bf16x2.f32 %0, %1, %2;" : "=r"(r) : "f"(b), "f"(a));
    return r;
}
DEV void split_bf(float v, float& hi, float& lo) {
    hi = __bfloat162float(__float2bfloat16(v));
    lo = v - hi;
}
DEV uint2 limb2(float a, float b) {
    float ha, la, hb, lb;
    split_bf(a, ha, la); split_bf(b, hb, lb);
    return make_uint2(pack_bf16(ha, hb), pack_bf16(la, lb));
}

DEV uint32_t pack_h2(float a, float b) {
    uint32_t r;
    asm("cvt.rn.f16x2.f32 %0, %1, %2;" : "=r"(r) : "f"(b), "f"(a));
    return r;
}
DEV void split_h(float v, float& hi, float& lo) {
    hi = __half2float(__float2half(v));
    lo = v - hi;
}
DEV uint2 limb2h(float a, float b) {
    float ha, la, hb, lb;
    split_h(a, ha, la); split_h(b, hb, lb);
    return make_uint2(pack_h2(ha, hb), pack_h2(la, lb));
}

// ---------------- async 2-limb bf16 x3 GEMM (proven) ----------------
template<int BM, int BN, int WM, int WN, int MT, int NT>
DEV void gemm_async_bf16(const uint2* __restrict__ A, int lda,
                         const uint2* __restrict__ B, int ldb,
                         int K, char* smem, uint32_t su, float* acc)
{
    const int tid = threadIdx.x;
    const int lane = tid & 31, wid = tid >> 5;
    const int g = lane >> 2, tq = lane & 3;
    const int wm0 = (wid / WN) * (BM / WM);
    const int wn0 = (wid % WN) * (BN / WN);

    constexpr int SA = BM * PADB * 8;
    constexpr int STAGE = SA + BN * PADB * 8;

    auto copy_chunk = [&](int c, int s) {
        uint32_t base = su + s * STAGE;
#pragma unroll
        for (int t = 0; t < BM * 4 / 256; t++) {
            int idx = tid + t * 256; int r = idx >> 2, j = idx & 3;
            cp16(base + r * 80 + j * 16, A + (size_t)r * lda + c * 8 + j * 2);
        }
#pragma unroll
        for (int t = 0; t < (BN * 4 + 255) / 256; t++) {
            int idx = tid + t * 256;
            if (BN * 4 % 256 == 0 || idx < BN * 4) {
                int r = idx >> 2, j = idx & 3;
                cp16(base + SA + r * 80 + j * 16, B + (size_t)r * ldb + c * 8 + j * 2);
            }
        }
        cp_commit();
    };
    auto compute = [&](int s) {
        const uint2* Ab = (const uint2*)(smem + s * STAGE);
        const uint2* Bb = (const uint2*)(smem + s * STAGE + SA);
        uint32_t bh[NT][2], bl[NT][2];
#pragma unroll
        for (int ni = 0; ni < NT; ni++) {
            int n0 = wn0 + ni * 8 + g;
            uint2 w0 = Bb[n0 * PADB + tq];
            uint2 w1 = Bb[n0 * PADB + tq + 4];
            bh[ni][0] = w0.x; bl[ni][0] = w0.y;
            bh[ni][1] = w1.x; bl[ni][1] = w1.y;
        }
#pragma unroll
        for (int mi = 0; mi < MT; mi++) {
            int r0 = wm0 + mi * 16 + g;
            uint2 v0 = Ab[r0 * PADB + tq];
            uint2 v1 = Ab[(r0 + 8) * PADB + tq];
            uint2 v2 = Ab[r0 * PADB + tq + 4];
            uint2 v3 = Ab[(r0 + 8) * PADB + tq + 4];
            uint32_t ah[4] = { v0.x, v1.x, v2.x, v3.x };
            uint32_t al[4] = { v0.y, v1.y, v2.y, v3.y };
#pragma unroll
            for (int ni = 0; ni < NT; ni++) {
                float* c = acc + (mi * NT + ni) * 4;
                mma_bf16(c, ah, bh[ni]);
                mma_bf16(c, ah, bl[ni]);
                mma_bf16(c, al, bh[ni]);
            }
        }
    };

    int nc = K >> 4;
    copy_chunk(0, 0);
    for (int c = 0; c < nc; c++) {
        cp_wait<0>();
        __syncthreads();
        if (c + 1 < nc) copy_chunk(c + 1, (c + 1) & 1);
        compute(c & 1);
    }
}

// ---------------- async 2-limb fp16 x3 GEMM (proven R13) ----------------
template<int BM, int BN, int WM, int WN, int MT, int NT>
DEV void gemm_async_fp16(const uint2* __restrict__ A, int lda,
                         const uint2* __restrict__ B, int ldb,
                         int K, char* smem, uint32_t su, float* acc)
{
    const int tid = threadIdx.x;
    const int lane = tid & 31, wid = tid >> 5;
    const int g = lane >> 2, tq = lane & 3;
    const int wm0 = (wid / WN) * (BM / WM);
    const int wn0 = (wid % WN) * (BN / WN);

    constexpr int SA = BM * PADB * 8;
    constexpr int STAGE = SA + BN * PADB * 8;

    auto copy_chunk = [&](int c, int s) {
        uint32_t base = su + s * STAGE;
#pragma unroll
        for (int t = 0; t < BM * 4 / 256; t++) {
            int idx = tid + t * 256; int r = idx >> 2, j = idx & 3;
            cp16(base + r * 80 + j * 16, A + (size_t)r * lda + c * 8 + j * 2);
        }
#pragma unroll
        for (int t = 0; t < (BN * 4 + 255) / 256; t++) {
            int idx = tid + t * 256;
            if (BN * 4 % 256 == 0 || idx < BN * 4) {
                int r = idx >> 2, j = idx & 3;
                cp16(base + SA + r * 80 + j * 16, B + (size_t)r * ldb + c * 8 + j * 2);
            }
        }
        cp_commit();
    };
    auto compute = [&](int s) {
        const uint2* Ab = (const uint2*)(smem + s * STAGE);
        const uint2* Bb = (const uint2*)(smem + s * STAGE + SA);
        uint32_t bh[NT][2], bl[NT][2];
#pragma unroll
        for (int ni = 0; ni < NT; ni++) {
            int n0 = wn0 + ni * 8 + g;
            uint2 w0 = Bb[n0 * PADB + tq];
            uint2 w1 = Bb[n0 * PADB + tq + 4];
            bh[ni][0] = w0.x; bl[ni][0] = w0.y;
            bh[ni][1] = w1.x; bl[ni][1] = w1.y;
        }
#pragma unroll
        for (int mi = 0; mi < MT; mi++) {
            int r0 = wm0 + mi * 16 + g;
            uint2 v0 = Ab[r0 * PADB + tq];
            uint2 v1 = Ab[(r0 + 8) * PADB + tq];
            uint2 v2 = Ab[r0 * PADB + tq + 4];
            uint2 v3 = Ab[(r0 + 8) * PADB + tq + 4];
            uint32_t ah[4] = { v0.x, v1.x, v2.x, v3.x };
            uint32_t al[4] = { v0.y, v1.y, v2.y, v3.y };
#pragma unroll
            for (int ni = 0; ni < NT; ni++) {
                float* c = acc + (mi * NT + ni) * 4;
                mma_fp16(c, ah, bh[ni]);
                mma_fp16(c, ah, bl[ni]);
                mma_fp16(c, al, bh[ni]);
            }
        }
    };

    int nc = K >> 4;
    copy_chunk(0, 0);
    for (int c = 0; c < nc; c++) {
        cp_wait<0>();
        __syncthreads();
        if (c + 1 < nc) copy_chunk(c + 1, (c + 1) & 1);
        compute(c & 1);
    }
}

// epilogue iteration
template<int BM, int BN, int WM, int WN, int MT, int NT, typename F>
DEV void epilogue(const float* acc, F fn)
{
    int lane = threadIdx.x & 31, wid = threadIdx.x >> 5;
    int g = lane >> 2, tq = lane & 3;
    int wm0 = (wid / WN) * (BM / WM);
    int wn0 = (wid % WN) * (BN / WN);
#pragma unroll
    for (int mi = 0; mi < MT; mi++)
#pragma unroll
        for (int ni = 0; ni < NT; ni++)
#pragma unroll
            for (int cj = 0; cj < 4; cj++) {
                int row = wm0 + mi * 16 + g + ((cj >= 2) ? 8 : 0);
                int col = wn0 + ni * 8 + 2 * tq + (cj & 1);
                fn(row, col, acc[(mi * NT + ni) * 4 + cj]);
            }
}

// ---------------- prep kernels ----------------
__global__ __launch_bounds__(256) void x_split_kernel(const float* __restrict__ x)
{
    int idx = blockIdx.x * 256 + threadIdx.x;
    ((uint2*)g_xbf4)[idx] = limb2(x[2 * idx], x[2 * idx + 1]);
}

__global__ __launch_bounds__(256) void xg_kernel(const float* __restrict__ x)
{
    int t = blockIdx.x;
    int tid = threadIdx.x;
    float4 v = ((const float4*)(x + (size_t)t * EMB))[tid];
    float p = v.x + v.y + v.z + v.w;
#pragma unroll
    for (int o = 8; o > 0; o >>= 1) p += __shfl_down_sync(0xffffffffu, p, o, 16);
    if ((tid & 15) == 0) g_xg[t * 16 + (tid >> 4)] = p;
}

__global__ __launch_bounds__(256) void pack_qwl_kernel(const int* __restrict__ qw, int mode)
{
    int idx = blockIdx.x * 256 + threadIdx.x;
    ((uint2*)g_wqkvl4[mode])[idx] =
        make_uint2(pack_bf16((float)qw[2 * idx], (float)qw[2 * idx + 1]), 0u);
}
__global__ __launch_bounds__(256) void pack_scale_kernel(
    const float* __restrict__ sc, const float* __restrict__ zr, int mode)
{
    int idx = blockIdx.x * 256 + threadIdx.x;
    float s = sc[idx];
    g_s[mode][idx] = s;
    g_sz[mode][idx] = s * zr[idx];
}

__global__ __launch_bounds__(256) void dequant_o_kernel(
    const int* __restrict__ qw, const float* __restrict__ sc,
    const float* __restrict__ zr)
{
    int idx4 = (blockIdx.x * 256 + threadIdx.x) * 4;
    int o = idx4 >> 10, i = idx4 & 1023, grp = i >> 6;
    float s = sc[o * 16 + grp], z = zr[o * 16 + grp];
    uint2* dst = (uint2*)g_wo4 + (idx4 >> 1);
    dst[0] = limb2(((float)qw[idx4 + 0] - z) * s, ((float)qw[idx4 + 1] - z) * s);
    dst[1] = limb2(((float)qw[idx4 + 2] - z) * s, ((float)qw[idx4 + 3] - z) * s);
}

// ---------------- QKV projection (proven R12/R13) ----------------
#define QKV_SMEM 33792
__global__ __launch_bounds__(256, 2) void proj_qkv_kernel(
    const float* __restrict__ bq, const float* __restrict__ bk,
    const float* __restrict__ bv)
{
    extern __shared__ char smem[];
    uint32_t su = smem_u32(smem);
    const int tid = threadIdx.x;
    const int lane = tid & 31, wid = tid >> 5;
    const int g = lane >> 2, tq = lane & 3;
    const int wm0 = (wid / 2) * 32;
    const int wn0 = (wid % 2) * 32;

    int mode = blockIdx.z;
    int n0 = blockIdx.x * 64, m0 = blockIdx.y * 128;
    const float* bias = mode == 0 ? bq : (mode == 1 ? bk : bv);

    const uint2* A = (const uint2*)g_xbf4 + (size_t)m0 * 512;
    const uint2* B = (const uint2*)g_wqkvl4[mode] + (size_t)n0 * 512;
    const float* sarr = g_s[mode];
    const float* szarr = g_sz[mode];

    constexpr int SA = 128 * PADB * 8;
    constexpr int STAGE = SA + 64 * PADB * 8;

    auto copy_chunk = [&](int c, int s) {
        uint32_t base = su + s * STAGE;
#pragma unroll
        for (int t = 0; t < 2; t++) {
            int idx = tid + t * 256; int r = idx >> 2, j = idx & 3;
            cp16(base + r * 80 + j * 16, A + (size_t)r * 512 + c * 8 + j * 2);
        }
        {
            int r = tid >> 2, j = tid & 3;
            cp16(base + SA + r * 80 + j * 16, B + (size_t)r * 512 + c * 8 + j * 2);
        }
        cp_commit();
    };

    float master[32], tmp[32];
#pragma unroll
    for (int i = 0; i < 32; i++) { master[i] = 0.f; tmp[i] = 0.f; }

    copy_chunk(0, 0);
    for (int c = 0; c < 64; c++) {
        cp_wait<0>();
        __syncthreads();
        if (c + 1 < 64) copy_chunk(c + 1, (c + 1) & 1);
        {
            const uint2* Ab = (const uint2*)(smem + (c & 1) * STAGE);
            const uint2* Bb = (const uint2*)(smem + (c & 1) * STAGE + SA);
            uint32_t bh[4][2];
#pragma unroll
            for (int ni = 0; ni < 4; ni++) {
                int n = wn0 + ni * 8 + g;
                uint2 w0 = Bb[n * PADB + tq];
                uint2 w1 = Bb[n * PADB + tq + 4];
                bh[ni][0] = w0.x;
                bh[ni][1] = w1.x;
            }
#pragma unroll
            for (int mi = 0; mi < 2; mi++) {
                int r0 = wm0 + mi * 16 + g;
                uint2 v0 = Ab[r0 * PADB + tq];
                uint2 v1 = Ab[(r0 + 8) * PADB + tq];
                uint2 v2 = Ab[r0 * PADB + tq + 4];
                uint2 v3 = Ab[(r0 + 8) * PADB + tq + 4];
                uint32_t ah[4] = { v0.x, v1.x, v2.x, v3.x };
                uint32_t al[4] = { v0.y, v1.y, v2.y, v3.y };
#pragma unroll
                for (int ni = 0; ni < 4; ni++) {
                    float* cc = tmp + (mi * 4 + ni) * 4;
                    mma_bf16(cc, ah, bh[ni]);
                    mma_bf16(cc, al, bh[ni]);
                }
            }
        }
        if ((c & 3) == 3) {
            int grp = c >> 2;
#pragma unroll
            for (int ni = 0; ni < 4; ni++) {
                int c0 = n0 + wn0 + ni * 8 + 2 * tq;
                float s0 = __ldg(&sarr[c0 * 16 + grp]);
                float s1 = __ldg(&sarr[(c0 + 1) * 16 + grp]);
#pragma unroll
                for (int mi = 0; mi < 2; mi++) {
                    float* mm = master + (mi * 4 + ni) * 4;
                    float* tt = tmp + (mi * 4 + ni) * 4;
                    mm[0] = fmaf(s0, tt[0], mm[0]);
                    mm[1] = fmaf(s1, tt[1], mm[1]);
                    mm[2] = fmaf(s0, tt[2], mm[2]);
                    mm[3] = fmaf(s1, tt[3], mm[3]);
                    tt[0] = 0.f; tt[1] = 0.f; tt[2] = 0.f; tt[3] = 0.f;
                }
            }
        }
    }

    for (int grp = 0; grp < 16; grp++) {
        float xr[2][2];
#pragma unroll
        for (int mi = 0; mi < 2; mi++) {
            int r0 = m0 + wm0 + mi * 16 + g;
            xr[mi][0] = __ldg(&g_xg[r0 * 16 + grp]);
            xr[mi][1] = __ldg(&g_xg[(r0 + 8) * 16 + grp]);
        }
#pragma unroll
        for (int ni = 0; ni < 4; ni++) {
            int c0 = n0 + wn0 + ni * 8 + 2 * tq;
            float z0 = __ldg(&szarr[c0 * 16 + grp]);
            float z1 = __ldg(&szarr[(c0 + 1) * 16 + grp]);
#pragma unroll
            for (int mi = 0; mi < 2; mi++) {
                float* mm = master + (mi * 4 + ni) * 4;
                mm[0] = fmaf(-z0, xr[mi][0], mm[0]);
                mm[1] = fmaf(-z1, xr[mi][0], mm[1]);
                mm[2] = fmaf(-z0, xr[mi][1], mm[2]);
                mm[3] = fmaf(-z1, xr[mi][1], mm[3]);
            }
        }
    }

    if (mode < 2) {
        uint2* dst = mode == 0 ? (uint2*)g_qh4 : (uint2*)g_kh4;
#pragma unroll
        for (int mi = 0; mi < 2; mi++)
#pragma unroll
            for (int ni = 0; ni < 4; ni++) {
                const float* c = master + (mi * 4 + ni) * 4;
                int col0 = wn0 + ni * 8 + 2 * tq;
                int r0 = wm0 + mi * 16 + g;
                int token = m0 + r0;
                int b = token >> 11, si = token & 2047;
                int o0 = n0 + col0;
                int h = o0 >> 6, d0 = o0 & 63;
                float b0 = bias[o0], b1 = bias[o0 + 1];
                size_t base = ((size_t)(b * 16 + h) * S_LEN + si) * 32 + (d0 >> 1);
                dst[base] = limb2h(c[0] + b0, c[1] + b1);
                dst[base + 8 * 32] = limb2h(c[2] + b0, c[3] + b1);
            }
    } else {
        __syncthreads();
        float* T = (float*)smem;
        int b = m0 >> 11, si0 = m0 & 2047;
        epilogue<128, 64, 4, 2, 2, 4>(master, [&](int row, int col, float val) {
            T[col * 132 + row] = val + bias[n0 + col];
        });
        __syncthreads();
        for (int i = threadIdx.x; i < 64 * 64; i += 256) {
            int cl = i >> 6, sp = i & 63;
            int o = n0 + cl; int h = o >> 6, d = o & 63;
            uint2 v = limb2h(T[cl * 132 + 2 * sp], T[cl * 132 + 2 * sp + 1]);
            ((uint2*)g_vts4)[((size_t)(b * 16 + h) * 64 + d) * 1024 + ((si0 + 2 * sp) >> 1)] = v;
        }
    }
}

// ---------------- scores (2-limb fp16 x3, proven R13) ----------------
#define SC_SMEM (2 * (128 + 128) * PADB * 8)
__global__ __launch_bounds__(256, 2) void scores_kernel(float* __restrict__ attn)
{
    extern __shared__ char smem[];
    uint32_t su = smem_u32(smem);
    int bh = blockIdx.z;
    int n0 = blockIdx.x * 128, m0 = blockIdx.y * 128;
    size_t base = (size_t)bh * S_LEN * 32;

    float acc[64];
#pragma unroll
    for (int i = 0; i < 64; i++) acc[i] = 0.f;

    gemm_async_fp16<128, 128, 2, 4, 4, 4>(
        (const uint2*)g_qh4 + base + (size_t)m0 * 32, 32,
        (const uint2*)g_kh4 + base + (size_t)n0 * 32, 32, 64, smem, su, acc);

    float* out = attn + (size_t)bh * S_LEN * S_LEN;
    epilogue<128, 128, 2, 4, 4, 4>(acc, [&](int row, int col, float val) {
        out[(size_t)(m0 + row) * S_LEN + n0 + col] = val * 0.125f;
    });
}

// ---------------- softmax (in place, fp32 only, proven R14) ----------------
__global__ __launch_bounds__(256) void softmax_kernel(float* __restrict__ S)
{
    size_t row = blockIdx.x;
    float4* p4 = (float4*)(S + row * S_LEN);
    int t = threadIdx.x;
    float4 u0 = p4[2 * t], u1 = p4[2 * t + 1];
    float v[8] = { u0.x, u0.y, u0.z, u0.w, u1.x, u1.y, u1.z, u1.w };
    float m = v[0];
#pragma unroll
    for (int i = 1; i < 8; i++) m = fmaxf(m, v[i]);
#pragma unroll
    for (int o = 16; o > 0; o >>= 1) m = fmaxf(m, __shfl_xor_sync(0xffffffffu, m, o));
    __shared__ float sred[8]; __shared__ float sbc;
    if ((t & 31) == 0) sred[t >> 5] = m;
    __syncthreads();
    if (t == 0) {
        float x = sred[0];
#pragma unroll
        for (int i = 1; i < 8; i++) x = fmaxf(x, sred[i]);
        sbc = x;
    }
    __syncthreads();
    m = sbc;
    float sum = 0.f;
#pragma unroll
    for (int i = 0; i < 8; i++) { v[i] = __expf(v[i] - m); sum += v[i]; }
#pragma unroll
    for (int o = 16; o > 0; o >>= 1) sum += __shfl_xor_sync(0xffffffffu, sum, o);
    __syncthreads();
    if ((t & 31) == 0) sred[t >> 5] = sum;
    __syncthreads();
    if (t == 0) {
        float x = 0.f;
#pragma unroll
        for (int i = 0; i < 8; i++) x += sred[i];
        sbc = 1.0f / x;
    }
    __syncthreads();
    float inv = sbc;
    p4[2 * t]     = make_float4(v[0] * inv, v[1] * inv, v[2] * inv, v[3] * inv);
    p4[2 * t + 1] = make_float4(v[4] * inv, v[5] * inv, v[6] * inv, v[7] * inv);
}

// ---------------- PV: k32 chunks (64 iters), A = fp32 P -> fp16 hi, B = V^T fp16 limbs ----------------
// A row: 32 fp32 + 4 pad = 144 B.  B row: 16 uint2 + 2 pad = 144 B.
#define PV_SMEM (2 * (128 * 144 + 64 * 144))
__global__ __launch_bounds__(256, 2) void pv_kernel(const float* __restrict__ attn)
{
    extern __shared__ char smem[];
    uint32_t su = smem_u32(smem);
    const int tid = threadIdx.x;
    const int lane = tid & 31, wid = tid >> 5;
    const int g = lane >> 2, tq = lane & 3;
    const int wm0 = (wid / 2) * 32;             // WM=4
    const int wn0 = (wid % 2) * 32;             // WN=2
    int bh = blockIdx.z;
    int m0 = blockIdx.y * 128;

    const float* Af = attn + (size_t)bh * S_LEN * S_LEN + (size_t)m0 * S_LEN;
    const uint2* B = (const uint2*)g_vts4 + (size_t)bh * 64 * 1024;

    constexpr int SA = 128 * 144;               // 18432
    constexpr int STAGE = SA + 64 * 144;        // 27648

    auto copy_chunk = [&](int c, int s) {
        uint32_t base = su + s * STAGE;
#pragma unroll
        for (int t = 0; t < 4; t++) {           // A: 128 rows x 128 B = 1024 cp16
            int idx = tid + t * 256; int r = idx >> 3, j = idx & 7;
            cp16(base + r * 144 + j * 16, Af + (size_t)r * S_LEN + c * 32 + j * 4);
        }
#pragma unroll
        for (int t = 0; t < 2; t++) {           // B: 64 rows x 128 B = 512 cp16
            int idx = tid + t * 256; int r = idx >> 3, j = idx & 7;
            cp16(base + SA + r * 144 + j * 16, B + (size_t)r * 1024 + c * 16 + j * 2);
        }
        cp_commit();
    };

    float acc[32];
#pragma unroll
    for (int i = 0; i < 32; i++) acc[i] = 0.f;

    copy_chunk(0, 0);
    for (int c = 0; c < 64; c++) {
        cp_wait<0>();
        __syncthreads();
        if (c + 1 < 64) copy_chunk(c + 1, (c + 1) & 1);
        const float* Ab = (const float*)(smem + (c & 1) * STAGE);   // rows of 36 floats
        const uint2* Bb = (const uint2*)(smem + (c & 1) * STAGE + SA); // rows of 18 uint2
#pragma unroll
        for (int sub = 0; sub < 2; sub++) {
            uint32_t bh2[4][2], bl2[4][2];
#pragma unroll
            for (int ni = 0; ni < 4; ni++) {
                int n = wn0 + ni * 8 + g;
                uint2 w0 = Bb[n * 18 + sub * 8 + tq];
                uint2 w1 = Bb[n * 18 + sub * 8 + 4 + tq];
                bh2[ni][0] = w0.x; bl2[ni][0] = w0.y;
                bh2[ni][1] = w1.x; bl2[ni][1] = w1.y;
            }
#pragma unroll
            for (int mi = 0; mi < 2; mi++) {
                int r0 = wm0 + mi * 16 + g;
                float2 a0 = ((const float2*)(Ab + r0 * 36 + sub * 16))[tq];
                float2 a1 = ((const float2*)(Ab + (r0 + 8) * 36 + sub * 16))[tq];
                float2 a2 = ((const float2*)(Ab + r0 * 36 + sub * 16 + 8))[tq];
                float2 a3 = ((const float2*)(Ab + (r0 + 8) * 36 + sub * 16 + 8))[tq];
                uint32_t ah[4] = { pack_h2(a0.x, a0.y), pack_h2(a1.x, a1.y),
                                   pack_h2(a2.x, a2.y), pack_h2(a3.x, a3.y) };
#pragma unroll
                for (int ni = 0; ni < 4; ni++) {
                    float* cc = acc + (mi * 4 + ni) * 4;
                    mma_fp16(cc, ah, bh2[ni]);
                    mma_fp16(cc, ah, bl2[ni]);
                }
            }
        }
    }

    int b = bh >> 4, h = bh & 15;
#pragma unroll
    for (int mi = 0; mi < 2; mi++)
#pragma unroll
        for (int ni = 0; ni < 4; ni++) {
            const float* c = acc + (mi * 4 + ni) * 4;
            int col0 = wn0 + ni * 8 + 2 * tq;
            int r0 = wm0 + mi * 16 + g;
            size_t tok0 = (size_t)b * S_LEN + m0 + r0;
            ((uint2*)g_aos4)[tok0 * 512 + (h * 64 + col0) / 2] = limb2(c[0], c[1]);
            ((uint2*)g_aos4)[(tok0 + 8) * 512 + (h * 64 + col0) / 2] = limb2(c[2], c[3]);
        }
}

// ---------------- O projection (proven) ----------------
#define OP_SMEM (2 * (128 + 128) * PADB * 8)
__global__ __launch_bounds__(256, 2) void oproj_kernel(
    const float* __restrict__ bias, float* __restrict__ out)
{
    extern __shared__ char smem[];
    uint32_t su = smem_u32(smem);
    int n0 = blockIdx.x * 128, m0 = blockIdx.y * 128;

    float acc[64];
#pragma unroll
    for (int i = 0; i < 64; i++) acc[i] = 0.f;

    gemm_async_bf16<128, 128, 2, 4, 4, 4>(
        (const uint2*)g_aos4 + (size_t)m0 * 512, 512,
        (const uint2*)g_wo4 + (size_t)n0 * 512, 512, EMB, smem, su, acc);

    epilogue<128, 128, 2, 4, 4, 4>(acc, [&](int row, int col, float val) {
        int token = m0 + row, o = n0 + col;
        out[(size_t)token * EMB + o] = val + bias[o];
    });
}

// ---------------- launch ----------------
extern "C" void kernel_launch(void* const* d_in, const int* in_sizes, int n_in,
                              void* d_out, int out_size)
{
    const float* x = (const float*)d_in[0];
    const int* qw[4];
    const float *sc[4], *zr[4], *bs[4];
    for (int p = 0; p < 4; p++) {
        qw[p] = (const int*)d_in[1 + 4 * p];
        sc[p] = (const float*)d_in[2 + 4 * p];
        zr[p] = (const float*)d_in[3 + 4 * p];
        bs[p] = (const float*)d_in[4 + 4 * p];
    }
    float* out = (float*)d_out;                 // [B,S,E]
    float* attn = out + (size_t)4194304;        // [B,H,S,S]

    cudaFuncSetAttribute(proj_qkv_kernel, cudaFuncAttributeMaxDynamicSharedMemorySize, QKV_SMEM);
    cudaFuncSetAttribute(scores_kernel,   cudaFuncAttributeMaxDynamicSharedMemorySize, SC_SMEM);
    cudaFuncSetAttribute(pv_kernel,       cudaFuncAttributeMaxDynamicSharedMemorySize, PV_SMEM);
    cudaFuncSetAttribute(oproj_kernel,    cudaFuncAttributeMaxDynamicSharedMemorySize, OP_SMEM);

    x_split_kernel<<<8192, 256>>>(x);
    xg_kernel<<<4096, 256>>>(x);
    for (int p = 0; p < 3; p++) {
        pack_qwl_kernel<<<2048, 256>>>(qw[p], p);
        pack_scale_kernel<<<64, 256>>>(sc[p], zr[p], p);
    }
    dequant_o_kernel<<<1024, 256>>>(qw[3], sc[3], zr[3]);

    proj_qkv_kernel<<<dim3(16, 32, 3), 256, QKV_SMEM>>>(bs[0], bs[1], bs[2]);
    scores_kernel<<<dim3(16, 16, 32), 256, SC_SMEM>>>(attn);
    softmax_kernel<<<65536, 256>>>(attn);
    pv_kernel<<<dim3(1, 16, 32), 256, PV_SMEM>>>(attn);
    oproj_kernel<<<dim3(8, 32), 256, OP_SMEM>>>(bs[3], out);
}

// round 17
// speedup vs baseline: 3.6485x; 1.0492x over previous
#include <cuda_runtime.h>
#include <cuda_bf16.h>
#include <cuda_fp16.h>
#include <cstdint>
#include <cstddef>

#define DEV __device__ __forceinline__

#define S_LEN 2048
#define EMB   1024
#define PADB  10          // uint2 per SMEM row (8 data + 2 pad)   = 80 B

// ---------------- scratch (16B-aligned) ----------------
__device__ uint4  g_xbf4[4096 * 1024 / 4];           // x bf16 limb pairs [t][e/2]
__device__ __align__(16) float g_xg[4096 * 16];      // group sums of x [t][g]
__device__ uint4  g_wqkvl4[3][1024 * 1024 / 4];      // qw as (bf16 pair, 0) limb uint2 [o][e/2]
__device__ __align__(16) float g_s[3][1024 * 16];    // scales [o][g]
__device__ __align__(16) float g_sz[3][1024 * 16];   // scale*zero [o][g]
__device__ uint4  g_wo4[1024 * 1024 / 4];            // o weights bf16 limb pairs
__device__ uint4  g_qh4[32 * 2048 * 64 / 4];         // q fp16 limb pairs [bh][s][d/2]
__device__ uint4  g_kh4[32 * 2048 * 64 / 4];         // k fp16 limb pairs
__device__ uint4  g_vts4[32 * 64 * 2048 / 4];        // v^T fp16 limbs [bh][d][s/2]
__device__ uint4  g_aos4[4096 * 1024 / 4];           // attn-out bf16 limbs [tok][e/2]

DEV uint32_t smem_u32(const void* p) {
    uint32_t a;
    asm("{ .reg .u64 t; cvta.to.shared.u64 t, %1; cvt.u32.u64 %0, t; }" : "=r"(a) : "l"(p));
    return a;
}
DEV void cp16(uint32_t dst, const void* src) {
    asm volatile("cp.async.cg.shared.global [%0], [%1], 16;" :: "r"(dst), "l"(src));
}
DEV void cp_commit() { asm volatile("cp.async.commit_group;" ::: "memory"); }
template<int N> DEV void cp_wait() { asm volatile("cp.async.wait_group %0;" :: "n"(N) : "memory"); }

DEV void mma_bf16(float* c, const uint32_t* a, const uint32_t* b) {
    asm volatile(
        "mma.sync.aligned.m16n8k16.row.col.f32.bf16.bf16.f32 "
        "{%0,%1,%2,%3}, {%4,%5,%6,%7}, {%8,%9}, {%0,%1,%2,%3};"
        : "+f"(c[0]), "+f"(c[1]), "+f"(c[2]), "+f"(c[3])
        : "r"(a[0]), "r"(a[1]), "r"(a[2]), "r"(a[3]), "r"(b[0]), "r"(b[1]));
}
DEV void mma_fp16(float* c, const uint32_t* a, const uint32_t* b) {
    asm volatile(
        "mma.sync.aligned.m16n8k16.row.col.f32.f16.f16.f32 "
        "{%0,%1,%2,%3}, {%4,%5,%6,%7}, {%8,%9}, {%0,%1,%2,%3};"
        : "+f"(c[0]), "+f"(c[1]), "+f"(c[2]), "+f"(c[3])
        : "r"(a[0]), "r"(a[1]), "r"(a[2]), "r"(a[3]), "r"(b[0]), "r"(b[1]));
}

DEV uint32_t pack_bf16(float a, float b) {
    uint32_t r;
    asm("cvt.rn.bf16x2.f32 %0, %1, %2;" : "=r"(r) : "f"(b), "f"(a));
    return r;
}
DEV void split_bf(float v, float& hi, float& lo) {
    hi = __bfloat162float(__float2bfloat16(v));
    lo = v - hi;
}
DEV uint2 limb2(float a, float b) {
    float ha, la, hb, lb;
    split_bf(a, ha, la); split_bf(b, hb, lb);
    return make_uint2(pack_bf16(ha, hb), pack_bf16(la, lb));
}

DEV uint32_t pack_h2(float a, float b) {
    uint32_t r;
    asm("cvt.rn.f16x2.f32 %0, %1, %2;" : "=r"(r) : "f"(b), "f"(a));
    return r;
}
DEV void split_h(float v, float& hi, float& lo) {
    hi = __half2float(__float2half(v));
    lo = v - hi;
}
DEV uint2 limb2h(float a, float b) {
    float ha, la, hb, lb;
    split_h(a, ha, la); split_h(b, hb, lb);
    return make_uint2(pack_h2(ha, hb), pack_h2(la, lb));
}

// ---------------- async 2-limb fp16 x3 GEMM (proven R13) ----------------
template<int BM, int BN, int WM, int WN, int MT, int NT>
DEV void gemm_async_fp16(const uint2* __restrict__ A, int lda,
                         const uint2* __restrict__ B, int ldb,
                         int K, char* smem, uint32_t su, float* acc)
{
    const int tid = threadIdx.x;
    const int lane = tid & 31, wid = tid >> 5;
    const int g = lane >> 2, tq = lane & 3;
    const int wm0 = (wid / WN) * (BM / WM);
    const int wn0 = (wid % WN) * (BN / WN);

    constexpr int SA = BM * PADB * 8;
    constexpr int STAGE = SA + BN * PADB * 8;

    auto copy_chunk = [&](int c, int s) {
        uint32_t base = su + s * STAGE;
#pragma unroll
        for (int t = 0; t < BM * 4 / 256; t++) {
            int idx = tid + t * 256; int r = idx >> 2, j = idx & 3;
            cp16(base + r * 80 + j * 16, A + (size_t)r * lda + c * 8 + j * 2);
        }
#pragma unroll
        for (int t = 0; t < (BN * 4 + 255) / 256; t++) {
            int idx = tid + t * 256;
            if (BN * 4 % 256 == 0 || idx < BN * 4) {
                int r = idx >> 2, j = idx & 3;
                cp16(base + SA + r * 80 + j * 16, B + (size_t)r * ldb + c * 8 + j * 2);
            }
        }
        cp_commit();
    };
    auto compute = [&](int s) {
        const uint2* Ab = (const uint2*)(smem + s * STAGE);
        const uint2* Bb = (const uint2*)(smem + s * STAGE + SA);
        uint32_t bh[NT][2], bl[NT][2];
#pragma unroll
        for (int ni = 0; ni < NT; ni++) {
            int n0 = wn0 + ni * 8 + g;
            uint2 w0 = Bb[n0 * PADB + tq];
            uint2 w1 = Bb[n0 * PADB + tq + 4];
            bh[ni][0] = w0.x; bl[ni][0] = w0.y;
            bh[ni][1] = w1.x; bl[ni][1] = w1.y;
        }
#pragma unroll
        for (int mi = 0; mi < MT; mi++) {
            int r0 = wm0 + mi * 16 + g;
            uint2 v0 = Ab[r0 * PADB + tq];
            uint2 v1 = Ab[(r0 + 8) * PADB + tq];
            uint2 v2 = Ab[r0 * PADB + tq + 4];
            uint2 v3 = Ab[(r0 + 8) * PADB + tq + 4];
            uint32_t ah[4] = { v0.x, v1.x, v2.x, v3.x };
            uint32_t al[4] = { v0.y, v1.y, v2.y, v3.y };
#pragma unroll
            for (int ni = 0; ni < NT; ni++) {
                float* c = acc + (mi * NT + ni) * 4;
                mma_fp16(c, ah, bh[ni]);
                mma_fp16(c, ah, bl[ni]);
                mma_fp16(c, al, bh[ni]);
            }
        }
    };

    int nc = K >> 4;
    copy_chunk(0, 0);
    for (int c = 0; c < nc; c++) {
        cp_wait<0>();
        __syncthreads();
        if (c + 1 < nc) copy_chunk(c + 1, (c + 1) & 1);
        compute(c & 1);
    }
}

// ---------------- async 2-limb bf16 x3 GEMM, k32 chunks (PV-validated layout) ----------------
// A,B rows: 16 uint2 data + 2 pad = 144 B.
template<int BM, int BN, int WM, int WN, int MT, int NT>
DEV void gemm_async_bf16_k32(const uint2* __restrict__ A, int lda,
                             const uint2* __restrict__ B, int ldb,
                             int K, char* smem, uint32_t su, float* acc)
{
    const int tid = threadIdx.x;
    const int lane = tid & 31, wid = tid >> 5;
    const int g = lane >> 2, tq = lane & 3;
    const int wm0 = (wid / WN) * (BM / WM);
    const int wn0 = (wid % WN) * (BN / WN);

    constexpr int SA = BM * 144;
    constexpr int STAGE = SA + BN * 144;

    auto copy_chunk = [&](int c, int s) {
        uint32_t base = su + s * STAGE;
#pragma unroll
        for (int t = 0; t < BM * 8 / 256; t++) {
            int idx = tid + t * 256; int r = idx >> 3, j = idx & 7;
            cp16(base + r * 144 + j * 16, A + (size_t)r * lda + c * 16 + j * 2);
        }
#pragma unroll
        for (int t = 0; t < BN * 8 / 256; t++) {
            int idx = tid + t * 256; int r = idx >> 3, j = idx & 7;
            cp16(base + SA + r * 144 + j * 16, B + (size_t)r * ldb + c * 16 + j * 2);
        }
        cp_commit();
    };
    auto compute = [&](int s) {
        const uint2* Ab = (const uint2*)(smem + s * STAGE);   // rows of 18 uint2
        const uint2* Bb = (const uint2*)(smem + s * STAGE + SA);
#pragma unroll
        for (int sub = 0; sub < 2; sub++) {
            uint32_t bh[NT][2], bl[NT][2];
#pragma unroll
            for (int ni = 0; ni < NT; ni++) {
                int n0 = wn0 + ni * 8 + g;
                uint2 w0 = Bb[n0 * 18 + sub * 8 + tq];
                uint2 w1 = Bb[n0 * 18 + sub * 8 + 4 + tq];
                bh[ni][0] = w0.x; bl[ni][0] = w0.y;
                bh[ni][1] = w1.x; bl[ni][1] = w1.y;
            }
#pragma unroll
            for (int mi = 0; mi < MT; mi++) {
                int r0 = wm0 + mi * 16 + g;
                uint2 v0 = Ab[r0 * 18 + sub * 8 + tq];
                uint2 v1 = Ab[(r0 + 8) * 18 + sub * 8 + tq];
                uint2 v2 = Ab[r0 * 18 + sub * 8 + 4 + tq];
                uint2 v3 = Ab[(r0 + 8) * 18 + sub * 8 + 4 + tq];
                uint32_t ah[4] = { v0.x, v1.x, v2.x, v3.x };
                uint32_t al[4] = { v0.y, v1.y, v2.y, v3.y };
#pragma unroll
                for (int ni = 0; ni < NT; ni++) {
                    float* c = acc + (mi * NT + ni) * 4;
                    mma_bf16(c, ah, bh[ni]);
                    mma_bf16(c, ah, bl[ni]);
                    mma_bf16(c, al, bh[ni]);
                }
            }
        }
    };

    int nc = K >> 5;
    copy_chunk(0, 0);
    for (int c = 0; c < nc; c++) {
        cp_wait<0>();
        __syncthreads();
        if (c + 1 < nc) copy_chunk(c + 1, (c + 1) & 1);
        compute(c & 1);
    }
}

// epilogue iteration
template<int BM, int BN, int WM, int WN, int MT, int NT, typename F>
DEV void epilogue(const float* acc, F fn)
{
    int lane = threadIdx.x & 31, wid = threadIdx.x >> 5;
    int g = lane >> 2, tq = lane & 3;
    int wm0 = (wid / WN) * (BM / WM);
    int wn0 = (wid % WN) * (BN / WN);
#pragma unroll
    for (int mi = 0; mi < MT; mi++)
#pragma unroll
        for (int ni = 0; ni < NT; ni++)
#pragma unroll
            for (int cj = 0; cj < 4; cj++) {
                int row = wm0 + mi * 16 + g + ((cj >= 2) ? 8 : 0);
                int col = wn0 + ni * 8 + 2 * tq + (cj & 1);
                fn(row, col, acc[(mi * NT + ni) * 4 + cj]);
            }
}

// ---------------- prep kernels ----------------
__global__ __launch_bounds__(256) void x_split_kernel(const float* __restrict__ x)
{
    int idx = blockIdx.x * 256 + threadIdx.x;
    ((uint2*)g_xbf4)[idx] = limb2(x[2 * idx], x[2 * idx + 1]);
}

__global__ __launch_bounds__(256) void xg_kernel(const float* __restrict__ x)
{
    int t = blockIdx.x;
    int tid = threadIdx.x;
    float4 v = ((const float4*)(x + (size_t)t * EMB))[tid];
    float p = v.x + v.y + v.z + v.w;
#pragma unroll
    for (int o = 8; o > 0; o >>= 1) p += __shfl_down_sync(0xffffffffu, p, o, 16);
    if ((tid & 15) == 0) g_xg[t * 16 + (tid >> 4)] = p;
}

__global__ __launch_bounds__(256) void pack_qwl_kernel(const int* __restrict__ qw, int mode)
{
    int idx = blockIdx.x * 256 + threadIdx.x;
    ((uint2*)g_wqkvl4[mode])[idx] =
        make_uint2(pack_bf16((float)qw[2 * idx], (float)qw[2 * idx + 1]), 0u);
}
__global__ __launch_bounds__(256) void pack_scale_kernel(
    const float* __restrict__ sc, const float* __restrict__ zr, int mode)
{
    int idx = blockIdx.x * 256 + threadIdx.x;
    float s = sc[idx];
    g_s[mode][idx] = s;
    g_sz[mode][idx] = s * zr[idx];
}

__global__ __launch_bounds__(256) void dequant_o_kernel(
    const int* __restrict__ qw, const float* __restrict__ sc,
    const float* __restrict__ zr)
{
    int idx4 = (blockIdx.x * 256 + threadIdx.x) * 4;
    int o = idx4 >> 10, i = idx4 & 1023, grp = i >> 6;
    float s = sc[o * 16 + grp], z = zr[o * 16 + grp];
    uint2* dst = (uint2*)g_wo4 + (idx4 >> 1);
    dst[0] = limb2(((float)qw[idx4 + 0] - z) * s, ((float)qw[idx4 + 1] - z) * s);
    dst[1] = limb2(((float)qw[idx4 + 2] - z) * s, ((float)qw[idx4 + 3] - z) * s);
}

// ---------------- QKV projection (proven R12/R13) ----------------
#define QKV_SMEM 33792
__global__ __launch_bounds__(256, 2) void proj_qkv_kernel(
    const float* __restrict__ bq, const float* __restrict__ bk,
    const float* __restrict__ bv)
{
    extern __shared__ char smem[];
    uint32_t su = smem_u32(smem);
    const int tid = threadIdx.x;
    const int lane = tid & 31, wid = tid >> 5;
    const int g = lane >> 2, tq = lane & 3;
    const int wm0 = (wid / 2) * 32;
    const int wn0 = (wid % 2) * 32;

    int mode = blockIdx.z;
    int n0 = blockIdx.x * 64, m0 = blockIdx.y * 128;
    const float* bias = mode == 0 ? bq : (mode == 1 ? bk : bv);

    const uint2* A = (const uint2*)g_xbf4 + (size_t)m0 * 512;
    const uint2* B = (const uint2*)g_wqkvl4[mode] + (size_t)n0 * 512;
    const float* sarr = g_s[mode];
    const float* szarr = g_sz[mode];

    constexpr int SA = 128 * PADB * 8;
    constexpr int STAGE = SA + 64 * PADB * 8;

    auto copy_chunk = [&](int c, int s) {
        uint32_t base = su + s * STAGE;
#pragma unroll
        for (int t = 0; t < 2; t++) {
            int idx = tid + t * 256; int r = idx >> 2, j = idx & 3;
            cp16(base + r * 80 + j * 16, A + (size_t)r * 512 + c * 8 + j * 2);
        }
        {
            int r = tid >> 2, j = tid & 3;
            cp16(base + SA + r * 80 + j * 16, B + (size_t)r * 512 + c * 8 + j * 2);
        }
        cp_commit();
    };

    float master[32], tmp[32];
#pragma unroll
    for (int i = 0; i < 32; i++) { master[i] = 0.f; tmp[i] = 0.f; }

    copy_chunk(0, 0);
    for (int c = 0; c < 64; c++) {
        cp_wait<0>();
        __syncthreads();
        if (c + 1 < 64) copy_chunk(c + 1, (c + 1) & 1);
        {
            const uint2* Ab = (const uint2*)(smem + (c & 1) * STAGE);
            const uint2* Bb = (const uint2*)(smem + (c & 1) * STAGE + SA);
            uint32_t bh[4][2];
#pragma unroll
            for (int ni = 0; ni < 4; ni++) {
                int n = wn0 + ni * 8 + g;
                uint2 w0 = Bb[n * PADB + tq];
                uint2 w1 = Bb[n * PADB + tq + 4];
                bh[ni][0] = w0.x;
                bh[ni][1] = w1.x;
            }
#pragma unroll
            for (int mi = 0; mi < 2; mi++) {
                int r0 = wm0 + mi * 16 + g;
                uint2 v0 = Ab[r0 * PADB + tq];
                uint2 v1 = Ab[(r0 + 8) * PADB + tq];
                uint2 v2 = Ab[r0 * PADB + tq + 4];
                uint2 v3 = Ab[(r0 + 8) * PADB + tq + 4];
                uint32_t ah[4] = { v0.x, v1.x, v2.x, v3.x };
                uint32_t al[4] = { v0.y, v1.y, v2.y, v3.y };
#pragma unroll
                for (int ni = 0; ni < 4; ni++) {
                    float* cc = tmp + (mi * 4 + ni) * 4;
                    mma_bf16(cc, ah, bh[ni]);
                    mma_bf16(cc, al, bh[ni]);
                }
            }
        }
        if ((c & 3) == 3) {
            int grp = c >> 2;
#pragma unroll
            for (int ni = 0; ni < 4; ni++) {
                int c0 = n0 + wn0 + ni * 8 + 2 * tq;
                float s0 = __ldg(&sarr[c0 * 16 + grp]);
                float s1 = __ldg(&sarr[(c0 + 1) * 16 + grp]);
#pragma unroll
                for (int mi = 0; mi < 2; mi++) {
                    float* mm = master + (mi * 4 + ni) * 4;
                    float* tt = tmp + (mi * 4 + ni) * 4;
                    mm[0] = fmaf(s0, tt[0], mm[0]);
                    mm[1] = fmaf(s1, tt[1], mm[1]);
                    mm[2] = fmaf(s0, tt[2], mm[2]);
                    mm[3] = fmaf(s1, tt[3], mm[3]);
                    tt[0] = 0.f; tt[1] = 0.f; tt[2] = 0.f; tt[3] = 0.f;
                }
            }
        }
    }

    for (int grp = 0; grp < 16; grp++) {
        float xr[2][2];
#pragma unroll
        for (int mi = 0; mi < 2; mi++) {
            int r0 = m0 + wm0 + mi * 16 + g;
            xr[mi][0] = __ldg(&g_xg[r0 * 16 + grp]);
            xr[mi][1] = __ldg(&g_xg[(r0 + 8) * 16 + grp]);
        }
#pragma unroll
        for (int ni = 0; ni < 4; ni++) {
            int c0 = n0 + wn0 + ni * 8 + 2 * tq;
            float z0 = __ldg(&szarr[c0 * 16 + grp]);
            float z1 = __ldg(&szarr[(c0 + 1) * 16 + grp]);
#pragma unroll
            for (int mi = 0; mi < 2; mi++) {
                float* mm = master + (mi * 4 + ni) * 4;
                mm[0] = fmaf(-z0, xr[mi][0], mm[0]);
                mm[1] = fmaf(-z1, xr[mi][0], mm[1]);
                mm[2] = fmaf(-z0, xr[mi][1], mm[2]);
                mm[3] = fmaf(-z1, xr[mi][1], mm[3]);
            }
        }
    }

    if (mode < 2) {
        uint2* dst = mode == 0 ? (uint2*)g_qh4 : (uint2*)g_kh4;
#pragma unroll
        for (int mi = 0; mi < 2; mi++)
#pragma unroll
            for (int ni = 0; ni < 4; ni++) {
                const float* c = master + (mi * 4 + ni) * 4;
                int col0 = wn0 + ni * 8 + 2 * tq;
                int r0 = wm0 + mi * 16 + g;
                int token = m0 + r0;
                int b = token >> 11, si = token & 2047;
                int o0 = n0 + col0;
                int h = o0 >> 6, d0 = o0 & 63;
                float b0 = bias[o0], b1 = bias[o0 + 1];
                size_t base = ((size_t)(b * 16 + h) * S_LEN + si) * 32 + (d0 >> 1);
                dst[base] = limb2h(c[0] + b0, c[1] + b1);
                dst[base + 8 * 32] = limb2h(c[2] + b0, c[3] + b1);
            }
    } else {
        __syncthreads();
        float* T = (float*)smem;
        int b = m0 >> 11, si0 = m0 & 2047;
        epilogue<128, 64, 4, 2, 2, 4>(master, [&](int row, int col, float val) {
            T[col * 132 + row] = val + bias[n0 + col];
        });
        __syncthreads();
        for (int i = threadIdx.x; i < 64 * 64; i += 256) {
            int cl = i >> 6, sp = i & 63;
            int o = n0 + cl; int h = o >> 6, d = o & 63;
            uint2 v = limb2h(T[cl * 132 + 2 * sp], T[cl * 132 + 2 * sp + 1]);
            ((uint2*)g_vts4)[((size_t)(b * 16 + h) * 64 + d) * 1024 + ((si0 + 2 * sp) >> 1)] = v;
        }
    }
}

// ---------------- scores (2-limb fp16 x3, float2 stores) ----------------
#define SC_SMEM (2 * (128 + 128) * PADB * 8)
__global__ __launch_bounds__(256, 2) void scores_kernel(float* __restrict__ attn)
{
    extern __shared__ char smem[];
    uint32_t su = smem_u32(smem);
    int bh = blockIdx.z;
    int n0 = blockIdx.x * 128, m0 = blockIdx.y * 128;
    size_t base = (size_t)bh * S_LEN * 32;

    float acc[64];
#pragma unroll
    for (int i = 0; i < 64; i++) acc[i] = 0.f;

    gemm_async_fp16<128, 128, 2, 4, 4, 4>(
        (const uint2*)g_qh4 + base + (size_t)m0 * 32, 32,
        (const uint2*)g_kh4 + base + (size_t)n0 * 32, 32, 64, smem, su, acc);

    float* out = attn + (size_t)bh * S_LEN * S_LEN;
    {
        int lane = threadIdx.x & 31, wid = threadIdx.x >> 5;
        int g = lane >> 2, tq = lane & 3;
        int wm0 = (wid / 4) * 64;       // WM=2
        int wn0 = (wid % 4) * 32;       // WN=4
#pragma unroll
        for (int mi = 0; mi < 4; mi++)
#pragma unroll
            for (int ni = 0; ni < 4; ni++) {
                const float* c = acc + (mi * 4 + ni) * 4;
                int row = wm0 + mi * 16 + g;
                int col = wn0 + ni * 8 + 2 * tq;
                *(float2*)&out[(size_t)(m0 + row) * S_LEN + n0 + col] =
                    make_float2(c[0] * 0.125f, c[1] * 0.125f);
                *(float2*)&out[(size_t)(m0 + row + 8) * S_LEN + n0 + col] =
                    make_float2(c[2] * 0.125f, c[3] * 0.125f);
            }
    }
}

// ---------------- softmax (in place, fp32 only, proven R14) ----------------
__global__ __launch_bounds__(256) void softmax_kernel(float* __restrict__ S)
{
    size_t row = blockIdx.x;
    float4* p4 = (float4*)(S + row * S_LEN);
    int t = threadIdx.x;
    float4 u0 = p4[2 * t], u1 = p4[2 * t + 1];
    float v[8] = { u0.x, u0.y, u0.z, u0.w, u1.x, u1.y, u1.z, u1.w };
    float m = v[0];
#pragma unroll
    for (int i = 1; i < 8; i++) m = fmaxf(m, v[i]);
#pragma unroll
    for (int o = 16; o > 0; o >>= 1) m = fmaxf(m, __shfl_xor_sync(0xffffffffu, m, o));
    __shared__ float sred[8]; __shared__ float sbc;
    if ((t & 31) == 0) sred[t >> 5] = m;
    __syncthreads();
    if (t == 0) {
        float x = sred[0];
#pragma unroll
        for (int i = 1; i < 8; i++) x = fmaxf(x, sred[i]);
        sbc = x;
    }
    __syncthreads();
    m = sbc;
    float sum = 0.f;
#pragma unroll
    for (int i = 0; i < 8; i++) { v[i] = __expf(v[i] - m); sum += v[i]; }
#pragma unroll
    for (int o = 16; o > 0; o >>= 1) sum += __shfl_xor_sync(0xffffffffu, sum, o);
    __syncthreads();
    if ((t & 31) == 0) sred[t >> 5] = sum;
    __syncthreads();
    if (t == 0) {
        float x = 0.f;
#pragma unroll
        for (int i = 0; i < 8; i++) x += sred[i];
        sbc = 1.0f / x;
    }
    __syncthreads();
    float inv = sbc;
    p4[2 * t]     = make_float4(v[0] * inv, v[1] * inv, v[2] * inv, v[3] * inv);
    p4[2 * t + 1] = make_float4(v[4] * inv, v[5] * inv, v[6] * inv, v[7] * inv);
}

// ---------------- PV: k32 chunks, A = fp32 P -> fp16 hi, B = V^T fp16 limbs (proven R16) ----------------
#define PV_SMEM (2 * (128 * 144 + 64 * 144))
__global__ __launch_bounds__(256, 2) void pv_kernel(const float* __restrict__ attn)
{
    extern __shared__ char smem[];
    uint32_t su = smem_u32(smem);
    const int tid = threadIdx.x;
    const int lane = tid & 31, wid = tid >> 5;
    const int g = lane >> 2, tq = lane & 3;
    const int wm0 = (wid / 2) * 32;
    const int wn0 = (wid % 2) * 32;
    int bh = blockIdx.z;
    int m0 = blockIdx.y * 128;

    const float* Af = attn + (size_t)bh * S_LEN * S_LEN + (size_t)m0 * S_LEN;
    const uint2* B = (const uint2*)g_vts4 + (size_t)bh * 64 * 1024;

    constexpr int SA = 128 * 144;
    constexpr int STAGE = SA + 64 * 144;

    auto copy_chunk = [&](int c, int s) {
        uint32_t base = su + s * STAGE;
#pragma unroll
        for (int t = 0; t < 4; t++) {
            int idx = tid + t * 256; int r = idx >> 3, j = idx & 7;
            cp16(base + r * 144 + j * 16, Af + (size_t)r * S_LEN + c * 32 + j * 4);
        }
#pragma unroll
        for (int t = 0; t < 2; t++) {
            int idx = tid + t * 256; int r = idx >> 3, j = idx & 7;
            cp16(base + SA + r * 144 + j * 16, B + (size_t)r * 1024 + c * 16 + j * 2);
        }
        cp_commit();
    };

    float acc[32];
#pragma unroll
    for (int i = 0; i < 32; i++) acc[i] = 0.f;

    copy_chunk(0, 0);
    for (int c = 0; c < 64; c++) {
        cp_wait<0>();
        __syncthreads();
        if (c + 1 < 64) copy_chunk(c + 1, (c + 1) & 1);
        const float* Ab = (const float*)(smem + (c & 1) * STAGE);
        const uint2* Bb = (const uint2*)(smem + (c & 1) * STAGE + SA);
#pragma unroll
        for (int sub = 0; sub < 2; sub++) {
            uint32_t bh2[4][2], bl2[4][2];
#pragma unroll
            for (int ni = 0; ni < 4; ni++) {
                int n = wn0 + ni * 8 + g;
                uint2 w0 = Bb[n * 18 + sub * 8 + tq];
                uint2 w1 = Bb[n * 18 + sub * 8 + 4 + tq];
                bh2[ni][0] = w0.x; bl2[ni][0] = w0.y;
                bh2[ni][1] = w1.x; bl2[ni][1] = w1.y;
            }
#pragma unroll
            for (int mi = 0; mi < 2; mi++) {
                int r0 = wm0 + mi * 16 + g;
                float2 a0 = ((const float2*)(Ab + r0 * 36 + sub * 16))[tq];
                float2 a1 = ((const float2*)(Ab + (r0 + 8) * 36 + sub * 16))[tq];
                float2 a2 = ((const float2*)(Ab + r0 * 36 + sub * 16 + 8))[tq];
                float2 a3 = ((const float2*)(Ab + (r0 + 8) * 36 + sub * 16 + 8))[tq];
                uint32_t ah[4] = { pack_h2(a0.x, a0.y), pack_h2(a1.x, a1.y),
                                   pack_h2(a2.x, a2.y), pack_h2(a3.x, a3.y) };
#pragma unroll
                for (int ni = 0; ni < 4; ni++) {
                    float* cc = acc + (mi * 4 + ni) * 4;
                    mma_fp16(cc, ah, bh2[ni]);
                    mma_fp16(cc, ah, bl2[ni]);
                }
            }
        }
    }

    int b = bh >> 4, h = bh & 15;
#pragma unroll
    for (int mi = 0; mi < 2; mi++)
#pragma unroll
        for (int ni = 0; ni < 4; ni++) {
            const float* c = acc + (mi * 4 + ni) * 4;
            int col0 = wn0 + ni * 8 + 2 * tq;
            int r0 = wm0 + mi * 16 + g;
            size_t tok0 = (size_t)b * S_LEN + m0 + r0;
            ((uint2*)g_aos4)[tok0 * 512 + (h * 64 + col0) / 2] = limb2(c[0], c[1]);
            ((uint2*)g_aos4)[(tok0 + 8) * 512 + (h * 64 + col0) / 2] = limb2(c[2], c[3]);
        }
}

// ---------------- O projection (k32 chunks) ----------------
#define OP_SMEM (2 * (128 * 144 + 128 * 144))
__global__ __launch_bounds__(256, 2) void oproj_kernel(
    const float* __restrict__ bias, float* __restrict__ out)
{
    extern __shared__ char smem[];
    uint32_t su = smem_u32(smem);
    int n0 = blockIdx.x * 128, m0 = blockIdx.y * 128;

    float acc[64];
#pragma unroll
    for (int i = 0; i < 64; i++) acc[i] = 0.f;

    gemm_async_bf16_k32<128, 128, 2, 4, 4, 4>(
        (const uint2*)g_aos4 + (size_t)m0 * 512, 512,
        (const uint2*)g_wo4 + (size_t)n0 * 512, 512, EMB, smem, su, acc);

    {
        int lane = threadIdx.x & 31, wid = threadIdx.x >> 5;
        int g = lane >> 2, tq = lane & 3;
        int wm0 = (wid / 4) * 64;       // WM=2
        int wn0 = (wid % 4) * 32;       // WN=4
#pragma unroll
        for (int mi = 0; mi < 4; mi++)
#pragma unroll
            for (int ni = 0; ni < 4; ni++) {
                const float* c = acc + (mi * 4 + ni) * 4;
                int row = wm0 + mi * 16 + g;
                int col = wn0 + ni * 8 + 2 * tq;
                int token = m0 + row, o = n0 + col;
                *(float2*)&out[(size_t)token * EMB + o] =
                    make_float2(c[0] + bias[o], c[1] + bias[o + 1]);
                *(float2*)&out[(size_t)(token + 8) * EMB + o] =
                    make_float2(c[2] + bias[o], c[3] + bias[o + 1]);
            }
    }
}

// ---------------- launch ----------------
extern "C" void kernel_launch(void* const* d_in, const int* in_sizes, int n_in,
                              void* d_out, int out_size)
{
    const float* x = (const float*)d_in[0];
    const int* qw[4];
    const float *sc[4], *zr[4], *bs[4];
    for (int p = 0; p < 4; p++) {
        qw[p] = (const int*)d_in[1 + 4 * p];
        sc[p] = (const float*)d_in[2 + 4 * p];
        zr[p] = (const float*)d_in[3 + 4 * p];
        bs[p] = (const float*)d_in[4 + 4 * p];
    }
    float* out = (float*)d_out;                 // [B,S,E]
    float* attn = out + (size_t)4194304;        // [B,H,S,S]

    cudaFuncSetAttribute(proj_qkv_kernel, cudaFuncAttributeMaxDynamicSharedMemorySize, QKV_SMEM);
    cudaFuncSetAttribute(scores_kernel,   cudaFuncAttributeMaxDynamicSharedMemorySize, SC_SMEM);
    cudaFuncSetAttribute(pv_kernel,       cudaFuncAttributeMaxDynamicSharedMemorySize, PV_SMEM);
    cudaFuncSetAttribute(oproj_kernel,    cudaFuncAttributeMaxDynamicSharedMemorySize, OP_SMEM);

    x_split_kernel<<<8192, 256>>>(x);
    xg_kernel<<<4096, 256>>>(x);
    for (int p = 0; p < 3; p++) {
        pack_qwl_kernel<<<2048, 256>>>(qw[p], p);
        pack_scale_kernel<<<64, 256>>>(sc[p], zr[p], p);
    }
    dequant_o_kernel<<<1024, 256>>>(qw[3], sc[3], zr[3]);

    proj_qkv_kernel<<<dim3(16, 32, 3), 256, QKV_SMEM>>>(bs[0], bs[1], bs[2]);
    scores_kernel<<<dim3(16, 16, 32), 256, SC_SMEM>>>(attn);
    softmax_kernel<<<65536, 256>>>(attn);
    pv_kernel<<<dim3(1, 16, 32), 256, PV_SMEM>>>(attn);
    oproj_kernel<<<dim3(8, 32), 256, OP_SMEM>>>(bs[3], out);
}